// round 6
// baseline (speedup 1.0000x reference)
#include <cuda_runtime.h>
#include <cuda_bf16.h>
#include <cstdint>
#include <math.h>

// Problem constants
#define Bdim 2
#define Tdim 2048
#define Cdim 1024
#define Hdim 16
#define Ddim 64
#define Mrows (Bdim * Tdim)   // 4096

// Device-global scratch, all bf16 hi/lo pairs (allocation-free)
__device__ __align__(16) __nv_bfloat16 g_xh[(size_t)Mrows * Cdim];
__device__ __align__(16) __nv_bfloat16 g_xl[(size_t)Mrows * Cdim];
__device__ __align__(16) __nv_bfloat16 g_wah[(size_t)3 * Cdim * Cdim];
__device__ __align__(16) __nv_bfloat16 g_wal[(size_t)3 * Cdim * Cdim];
__device__ __align__(16) __nv_bfloat16 g_wph[(size_t)Cdim * Cdim];
__device__ __align__(16) __nv_bfloat16 g_wpl[(size_t)Cdim * Cdim];
__device__ __align__(16) __nv_bfloat16 g_qh[(size_t)Bdim * Hdim * Tdim * Ddim];
__device__ __align__(16) __nv_bfloat16 g_ql[(size_t)Bdim * Hdim * Tdim * Ddim];
__device__ __align__(16) __nv_bfloat16 g_kh[(size_t)Bdim * Hdim * Tdim * Ddim];
__device__ __align__(16) __nv_bfloat16 g_kl[(size_t)Bdim * Hdim * Tdim * Ddim];
__device__ __align__(16) __nv_bfloat16 g_vh[(size_t)Bdim * Hdim * Tdim * Ddim];
__device__ __align__(16) __nv_bfloat16 g_vl[(size_t)Bdim * Hdim * Tdim * Ddim];
__device__ __align__(16) __nv_bfloat16 g_yh[(size_t)Bdim * Tdim * Cdim];
__device__ __align__(16) __nv_bfloat16 g_yl[(size_t)Bdim * Tdim * Cdim];

// ---------------------------------------------------------------------------
// Helpers
// ---------------------------------------------------------------------------
__device__ __forceinline__ uint32_t smem_u32(const void* p) {
    uint32_t a;
    asm("{ .reg .u64 t; cvta.to.shared.u64 t, %1; cvt.u32.u64 %0, t; }" : "=r"(a) : "l"(p));
    return a;
}

__device__ __forceinline__ void ldsm_x4(uint32_t& r0, uint32_t& r1, uint32_t& r2, uint32_t& r3,
                                        uint32_t addr) {
    asm volatile("ldmatrix.sync.aligned.m8n8.x4.shared.b16 {%0,%1,%2,%3}, [%4];"
                 : "=r"(r0), "=r"(r1), "=r"(r2), "=r"(r3) : "r"(addr));
}
__device__ __forceinline__ void ldsm_x4_t(uint32_t& r0, uint32_t& r1, uint32_t& r2, uint32_t& r3,
                                          uint32_t addr) {
    asm volatile("ldmatrix.sync.aligned.m8n8.x4.trans.shared.b16 {%0,%1,%2,%3}, [%4];"
                 : "=r"(r0), "=r"(r1), "=r"(r2), "=r"(r3) : "r"(addr));
}

__device__ __forceinline__ void mma16816(float* c, const uint32_t* a, const uint32_t* b) {
    asm volatile(
        "mma.sync.aligned.m16n8k16.row.col.f32.bf16.bf16.f32 "
        "{%0,%1,%2,%3}, {%4,%5,%6,%7}, {%8,%9}, {%0,%1,%2,%3};"
        : "+f"(c[0]), "+f"(c[1]), "+f"(c[2]), "+f"(c[3])
        : "r"(a[0]), "r"(a[1]), "r"(a[2]), "r"(a[3]), "r"(b[0]), "r"(b[1]));
}

__device__ __forceinline__ uint32_t pack2bf16(float x, float y) {
    __nv_bfloat162 t;
    t.x = __float2bfloat16_rn(x);
    t.y = __float2bfloat16_rn(y);
    return *reinterpret_cast<uint32_t*>(&t);
}
__device__ __forceinline__ uint32_t pack2bf16_lo(float x, float y) {
    float hx = __bfloat162float(__float2bfloat16_rn(x));
    float hy = __bfloat162float(__float2bfloat16_rn(y));
    __nv_bfloat162 t;
    t.x = __float2bfloat16_rn(x - hx);
    t.y = __float2bfloat16_rn(y - hy);
    return *reinterpret_cast<uint32_t*>(&t);
}

#define SROW 40    // GEMM smem row stride in bf16 (32-col chunks; conflict-free ldmatrix)
#define SROWA 72   // Attention smem row stride in bf16 (64-col tiles; conflict-free)

// ---------------------------------------------------------------------------
// Pre-pass: split fp32 array into bf16 hi/lo arrays. n4 = n/4.
// ---------------------------------------------------------------------------
__global__ void split2_kernel(const float* __restrict__ src, __nv_bfloat16* __restrict__ hi,
                              __nv_bfloat16* __restrict__ lo, int n4) {
    int i = blockIdx.x * blockDim.x + threadIdx.x;
    if (i < n4) {
        float4 v = ((const float4*)src)[i];
        ((uint2*)hi)[i] = make_uint2(pack2bf16(v.x, v.y), pack2bf16(v.z, v.w));
        ((uint2*)lo)[i] = make_uint2(pack2bf16_lo(v.x, v.y), pack2bf16_lo(v.z, v.w));
    }
}

// ---------------------------------------------------------------------------
// Tensor-core GEMM (NT), operands pre-split bf16 hi/lo in global.
// C[M,N] = A[M,K] @ B[N,K]^T (3-term). 128x128 CTA tile, 256 thr, 8 warps.
// MODE 0: fp32 store to Cout.
// MODE 1: scatter bf16 hi/lo into g_q*/g_k*/g_v* [B,H,T,D]; q scaled 0.125.
// ---------------------------------------------------------------------------
template <int MODE>
__global__ void __launch_bounds__(256, 2) gemm_bf(const __nv_bfloat16* __restrict__ Ah,
                                                  const __nv_bfloat16* __restrict__ Al,
                                                  const __nv_bfloat16* __restrict__ Bh,
                                                  const __nv_bfloat16* __restrict__ Bl,
                                                  float* __restrict__ Cout,
                                                  int M, int N, int K) {
    __shared__ __align__(16) __nv_bfloat16 sAhi[128 * SROW];
    __shared__ __align__(16) __nv_bfloat16 sAlo[128 * SROW];
    __shared__ __align__(16) __nv_bfloat16 sBhi[128 * SROW];
    __shared__ __align__(16) __nv_bfloat16 sBlo[128 * SROW];

    const int tid = threadIdx.x;
    const int lane = tid & 31;
    const int wid = tid >> 5;
    const int wm = wid >> 2;
    const int wn = wid & 3;
    const int bm = blockIdx.y * 128;
    const int bn = blockIdx.x * 128;

    // load mapping: u = tid + 256p -> row = u>>2 (0..127), c8 = (u&3)*8
    const int lrow0 = tid >> 2;
    const int lc8 = (tid & 3) * 8;

    const __nv_bfloat16* Agh = Ah + (size_t)bm * K;
    const __nv_bfloat16* Agl = Al + (size_t)bm * K;
    const __nv_bfloat16* Bgh = Bh + (size_t)bn * K;
    const __nv_bfloat16* Bgl = Bl + (size_t)bn * K;

    uint4 rAh[2], rAl[2], rBh[2], rBl[2];
    const int nch = K / 32;

#pragma unroll
    for (int p = 0; p < 2; p++) {
        int row = lrow0 + 64 * p;
        rAh[p] = *(const uint4*)&Agh[(size_t)row * K + lc8];
        rAl[p] = *(const uint4*)&Agl[(size_t)row * K + lc8];
        rBh[p] = *(const uint4*)&Bgh[(size_t)row * K + lc8];
        rBl[p] = *(const uint4*)&Bgl[(size_t)row * K + lc8];
    }

    float acc[4][4][4];
#pragma unroll
    for (int i = 0; i < 4; i++)
#pragma unroll
        for (int j = 0; j < 4; j++)
#pragma unroll
            for (int r = 0; r < 4; r++) acc[i][j][r] = 0.f;

    const uint32_t aHiB = smem_u32(sAhi), aLoB = smem_u32(sAlo);
    const uint32_t bHiB = smem_u32(sBhi), bLoB = smem_u32(sBlo);
    const uint32_t aOff = (uint32_t)((wm * 64 + (lane & 15)) * SROW + (lane >> 4) * 8) * 2;
    const uint32_t bOff = (uint32_t)((wn * 32 + (lane >> 4) * 8 + (lane & 7)) * SROW +
                                     ((lane >> 3) & 1) * 8) * 2;

    for (int ch = 0; ch < nch; ch++) {
#pragma unroll
        for (int p = 0; p < 2; p++) {
            int so = (lrow0 + 64 * p) * SROW + lc8;
            *(uint4*)&sAhi[so] = rAh[p];
            *(uint4*)&sAlo[so] = rAl[p];
            *(uint4*)&sBhi[so] = rBh[p];
            *(uint4*)&sBlo[so] = rBl[p];
        }
        __syncthreads();

        if (ch + 1 < nch) {
            const int koff = (ch + 1) * 32 + lc8;
#pragma unroll
            for (int p = 0; p < 2; p++) {
                int row = lrow0 + 64 * p;
                rAh[p] = *(const uint4*)&Agh[(size_t)row * K + koff];
                rAl[p] = *(const uint4*)&Agl[(size_t)row * K + koff];
                rBh[p] = *(const uint4*)&Bgh[(size_t)row * K + koff];
                rBl[p] = *(const uint4*)&Bgl[(size_t)row * K + koff];
            }
        }

#pragma unroll
        for (int kk = 0; kk < 2; kk++) {
            const uint32_t kByte = (uint32_t)(kk * 16 * 2);
            uint32_t af[4][4];
            uint32_t bh[4][2], bl[4][2];
#pragma unroll
            for (int i = 0; i < 4; i++)
                ldsm_x4(af[i][0], af[i][1], af[i][2], af[i][3],
                        aHiB + aOff + kByte + (uint32_t)(i * 16 * SROW * 2));
#pragma unroll
            for (int jp = 0; jp < 2; jp++) {
                uint32_t r0_, r1_, r2_, r3_;
                ldsm_x4(r0_, r1_, r2_, r3_, bHiB + bOff + kByte + (uint32_t)(jp * 16 * SROW * 2));
                bh[jp * 2][0] = r0_; bh[jp * 2][1] = r1_;
                bh[jp * 2 + 1][0] = r2_; bh[jp * 2 + 1][1] = r3_;
                ldsm_x4(r0_, r1_, r2_, r3_, bLoB + bOff + kByte + (uint32_t)(jp * 16 * SROW * 2));
                bl[jp * 2][0] = r0_; bl[jp * 2][1] = r1_;
                bl[jp * 2 + 1][0] = r2_; bl[jp * 2 + 1][1] = r3_;
            }
#pragma unroll
            for (int i = 0; i < 4; i++)
#pragma unroll
                for (int j = 0; j < 4; j++) {
                    mma16816(acc[i][j], af[i], bh[j]);
                    mma16816(acc[i][j], af[i], bl[j]);
                }
#pragma unroll
            for (int i = 0; i < 4; i++)
                ldsm_x4(af[i][0], af[i][1], af[i][2], af[i][3],
                        aLoB + aOff + kByte + (uint32_t)(i * 16 * SROW * 2));
#pragma unroll
            for (int i = 0; i < 4; i++)
#pragma unroll
                for (int j = 0; j < 4; j++)
                    mma16816(acc[i][j], af[i], bh[j]);
        }
        __syncthreads();
    }

    const int lr = lane >> 2;
    const int lc = (lane & 3) * 2;

    if (MODE == 0) {
#pragma unroll
        for (int i = 0; i < 4; i++) {
            int rowA = bm + wm * 64 + i * 16 + lr;
#pragma unroll
            for (int j = 0; j < 4; j++) {
                int col = bn + wn * 32 + j * 8 + lc;
                *(float2*)&Cout[(size_t)rowA * N + col] = make_float2(acc[i][j][0], acc[i][j][1]);
                *(float2*)&Cout[(size_t)(rowA + 8) * N + col] = make_float2(acc[i][j][2], acc[i][j][3]);
            }
        }
    } else {
        int col0 = bn + wn * 32;
        int sdx = col0 >> 10;
        int rr = col0 & (Cdim - 1);
        int h = rr >> 6;
        int d0 = (rr & (Ddim - 1)) + lc;
        __nv_bfloat16* dh = (sdx == 0) ? g_qh : (sdx == 1) ? g_kh : g_vh;
        __nv_bfloat16* dl = (sdx == 0) ? g_ql : (sdx == 1) ? g_kl : g_vl;
        float sc = (sdx == 0) ? 0.125f : 1.0f;
#pragma unroll
        for (int i = 0; i < 4; i++) {
            int rowA = bm + wm * 64 + i * 16 + lr;
#pragma unroll
            for (int hh = 0; hh < 2; hh++) {
                int row = rowA + hh * 8;
                int b = row >> 11;
                int t = row & (Tdim - 1);
                size_t off = ((size_t)(b * Hdim + h) * Tdim + t) * Ddim;
#pragma unroll
                for (int j = 0; j < 4; j++) {
                    float f0 = acc[i][j][hh * 2] * sc;
                    float f1 = acc[i][j][hh * 2 + 1] * sc;
                    *(uint32_t*)&dh[off + d0 + j * 8] = pack2bf16(f0, f1);
                    *(uint32_t*)&dl[off + d0 + j * 8] = pack2bf16_lo(f0, f1);
                }
            }
        }
    }
}

// ---------------------------------------------------------------------------
// Tensor-core causal flash attention (mma.sync bf16, 3-term splits).
// Q/K/V pre-split bf16 hi/lo in global -> smem staging is pure copies.
// Grid: (T/128, B*H), 256 threads. Warp w owns q-rows [16w,16w+16).
// ---------------------------------------------------------------------------
__global__ void __launch_bounds__(256, 1) attn_mma() {
    // K/V tiles: 64*72*2 = 9216 B each; Q staging overlay: 2 x 128*72*2
    __shared__ __align__(16) char sbuf[36864];
    const uint32_t sb = smem_u32(sbuf);
    const int tid = threadIdx.x;
    const int lane = tid & 31;
    const int w = tid >> 5;
    const int bh = blockIdx.y;
    const int q0 = (int)(gridDim.x - 1 - blockIdx.x) * 128;   // heavy tiles first

    const size_t headoff = (size_t)bh * Tdim * Ddim;

    // smem offsets (bytes)
    const uint32_t oKhi = 0, oKlo = 9216, oVhi = 18432, oVlo = 27648;
    const uint32_t oQhi = 0, oQlo = 18432;   // staging overlay

    // ---- stage Q (128x64) hi/lo (copies), load A-fragments ----
    {
        const uint4* qgh = (const uint4*)(g_qh + headoff + (size_t)q0 * Ddim);
        const uint4* qgl = (const uint4*)(g_ql + headoff + (size_t)q0 * Ddim);
#pragma unroll
        for (int p = 0; p < 4; p++) {
            int u = p * 256 + tid;          // 0..1023
            int row = u >> 3;
            int c8 = (u & 7) * 8;
            uint32_t so = (uint32_t)(row * SROWA + c8) * 2;
            *(uint4*)(sbuf + oQhi + so) = qgh[u];
            *(uint4*)(sbuf + oQlo + so) = qgl[u];
        }
    }
    __syncthreads();

    uint32_t qh[4][4], ql[4][4];
#pragma unroll
    for (int kk = 0; kk < 4; kk++) {
        uint32_t off = (uint32_t)((16 * w + (lane & 15)) * SROWA + 16 * kk + 8 * (lane >> 4)) * 2;
        ldsm_x4(qh[kk][0], qh[kk][1], qh[kk][2], qh[kk][3], sb + oQhi + off);
        ldsm_x4(ql[kk][0], ql[kk][1], ql[kk][2], ql[kk][3], sb + oQlo + off);
    }
    __syncthreads();

    // state
    float oacc[8][4];
#pragma unroll
    for (int j = 0; j < 8; j++)
#pragma unroll
        for (int r = 0; r < 4; r++) oacc[j][r] = 0.f;
    float m1 = -1e30f, m2 = -1e30f, l1 = 0.f, l2 = 0.f;

    const int r1 = q0 + 16 * w + (lane >> 2);
    const int r2 = r1 + 8;
    const int ktmax = (q0 + 127) >> 6;

    // prefetch mapping: u = tid + 256p (p=0..1), row = u>>3 (0..63), c8=(u&7)*8
    const int arow = (tid + 0) >> 3;       // p=0 row
    const int ac8 = (tid & 7) * 8;

    uint4 kh_r[2], kl_r[2], vh_r[2], vl_r[2];
    {
        const __nv_bfloat16* Kh = g_kh + headoff;
        const __nv_bfloat16* Kl = g_kl + headoff;
        const __nv_bfloat16* Vh = g_vh + headoff;
        const __nv_bfloat16* Vl = g_vl + headoff;
#pragma unroll
        for (int p = 0; p < 2; p++) {
            int row = arow + 32 * p;
            kh_r[p] = *(const uint4*)&Kh[(size_t)row * Ddim + ac8];
            kl_r[p] = *(const uint4*)&Kl[(size_t)row * Ddim + ac8];
            vh_r[p] = *(const uint4*)&Vh[(size_t)row * Ddim + ac8];
            vl_r[p] = *(const uint4*)&Vl[(size_t)row * Ddim + ac8];
        }
    }

    for (int kt = 0; kt <= ktmax; kt++) {
        const int kbase = kt * 64;

        // store staged K/V tile hi/lo (pure copies)
#pragma unroll
        for (int p = 0; p < 2; p++) {
            int row = arow + 32 * p;
            uint32_t so = (uint32_t)(row * SROWA + ac8) * 2;
            *(uint4*)(sbuf + oKhi + so) = kh_r[p];
            *(uint4*)(sbuf + oKlo + so) = kl_r[p];
            *(uint4*)(sbuf + oVhi + so) = vh_r[p];
            *(uint4*)(sbuf + oVlo + so) = vl_r[p];
        }
        __syncthreads();

        // prefetch next tile
        if (kt < ktmax) {
            const __nv_bfloat16* Kh = g_kh + headoff + (size_t)(kbase + 64) * Ddim;
            const __nv_bfloat16* Kl = g_kl + headoff + (size_t)(kbase + 64) * Ddim;
            const __nv_bfloat16* Vh = g_vh + headoff + (size_t)(kbase + 64) * Ddim;
            const __nv_bfloat16* Vl = g_vl + headoff + (size_t)(kbase + 64) * Ddim;
#pragma unroll
            for (int p = 0; p < 2; p++) {
                int row = arow + 32 * p;
                kh_r[p] = *(const uint4*)&Kh[(size_t)row * Ddim + ac8];
                kl_r[p] = *(const uint4*)&Kl[(size_t)row * Ddim + ac8];
                vh_r[p] = *(const uint4*)&Vh[(size_t)row * Ddim + ac8];
                vl_r[p] = *(const uint4*)&Vl[(size_t)row * Ddim + ac8];
            }
        }

        // ---- S = Q.K^T (3-term) ----
        float sacc[8][4];
#pragma unroll
        for (int j = 0; j < 8; j++)
#pragma unroll
            for (int r = 0; r < 4; r++) sacc[j][r] = 0.f;

#pragma unroll
        for (int kk = 0; kk < 4; kk++) {
            uint32_t bhp[8][2], blp[8][2];
#pragma unroll
            for (int np = 0; np < 4; np++) {
                uint32_t off = (uint32_t)((np * 16 + (lane >> 4) * 8 + (lane & 7)) * SROWA +
                                          ((lane >> 3) & 1) * 8 + 16 * kk) * 2;
                uint32_t t0, t1, t2, t3;
                ldsm_x4(t0, t1, t2, t3, sb + oKhi + off);
                bhp[2 * np][0] = t0; bhp[2 * np][1] = t1;
                bhp[2 * np + 1][0] = t2; bhp[2 * np + 1][1] = t3;
                ldsm_x4(t0, t1, t2, t3, sb + oKlo + off);
                blp[2 * np][0] = t0; blp[2 * np][1] = t1;
                blp[2 * np + 1][0] = t2; blp[2 * np + 1][1] = t3;
            }
#pragma unroll
            for (int j = 0; j < 8; j++) {
                mma16816(sacc[j], qh[kk], bhp[j]);
                mma16816(sacc[j], qh[kk], blp[j]);
                mma16816(sacc[j], ql[kk], bhp[j]);
            }
        }

        // ---- causal mask (diagonal tiles only; warp-uniform branch) ----
        if (kbase + 63 > q0 + 16 * w) {
            const int c0 = kbase + 2 * (lane & 3);
#pragma unroll
            for (int j = 0; j < 8; j++) {
                int cj = c0 + 8 * j;
                if (cj > r1)     sacc[j][0] = -1e30f;
                if (cj + 1 > r1) sacc[j][1] = -1e30f;
                if (cj > r2)     sacc[j][2] = -1e30f;
                if (cj + 1 > r2) sacc[j][3] = -1e30f;
            }
        }

        // ---- online softmax ----
        float t1m = -1e30f, t2m = -1e30f;
#pragma unroll
        for (int j = 0; j < 8; j++) {
            t1m = fmaxf(t1m, fmaxf(sacc[j][0], sacc[j][1]));
            t2m = fmaxf(t2m, fmaxf(sacc[j][2], sacc[j][3]));
        }
        t1m = fmaxf(t1m, __shfl_xor_sync(0xffffffffu, t1m, 1));
        t1m = fmaxf(t1m, __shfl_xor_sync(0xffffffffu, t1m, 2));
        t2m = fmaxf(t2m, __shfl_xor_sync(0xffffffffu, t2m, 1));
        t2m = fmaxf(t2m, __shfl_xor_sync(0xffffffffu, t2m, 2));

        float nm1 = fmaxf(m1, t1m), nm2 = fmaxf(m2, t2m);
        float corr1 = __expf(m1 - nm1), corr2 = __expf(m2 - nm2);
        m1 = nm1; m2 = nm2;

        float s1 = 0.f, s2 = 0.f;
#pragma unroll
        for (int j = 0; j < 8; j++) {
            sacc[j][0] = __expf(sacc[j][0] - m1);
            sacc[j][1] = __expf(sacc[j][1] - m1);
            sacc[j][2] = __expf(sacc[j][2] - m2);
            sacc[j][3] = __expf(sacc[j][3] - m2);
            s1 += sacc[j][0] + sacc[j][1];
            s2 += sacc[j][2] + sacc[j][3];
        }
        s1 += __shfl_xor_sync(0xffffffffu, s1, 1);
        s1 += __shfl_xor_sync(0xffffffffu, s1, 2);
        s2 += __shfl_xor_sync(0xffffffffu, s2, 1);
        s2 += __shfl_xor_sync(0xffffffffu, s2, 2);
        l1 = l1 * corr1 + s1;
        l2 = l2 * corr2 + s2;

        // pack P into A-fragments (hi/lo)
        uint32_t ph[4][4], pl[4][4];
#pragma unroll
        for (int kk = 0; kk < 4; kk++) {
            int j0 = 2 * kk, j1 = 2 * kk + 1;
            ph[kk][0] = pack2bf16(sacc[j0][0], sacc[j0][1]);
            ph[kk][1] = pack2bf16(sacc[j0][2], sacc[j0][3]);
            ph[kk][2] = pack2bf16(sacc[j1][0], sacc[j1][1]);
            ph[kk][3] = pack2bf16(sacc[j1][2], sacc[j1][3]);
            pl[kk][0] = pack2bf16_lo(sacc[j0][0], sacc[j0][1]);
            pl[kk][1] = pack2bf16_lo(sacc[j0][2], sacc[j0][3]);
            pl[kk][2] = pack2bf16_lo(sacc[j1][0], sacc[j1][1]);
            pl[kk][3] = pack2bf16_lo(sacc[j1][2], sacc[j1][3]);
        }

        // rescale O
#pragma unroll
        for (int j = 0; j < 8; j++) {
            oacc[j][0] *= corr1; oacc[j][1] *= corr1;
            oacc[j][2] *= corr2; oacc[j][3] *= corr2;
        }

        // ---- O += P.V (3-term; V via ldmatrix.trans) ----
#pragma unroll
        for (int kk = 0; kk < 4; kk++) {
            uint32_t vbh[8][2], vbl[8][2];
#pragma unroll
            for (int np = 0; np < 4; np++) {
                uint32_t off = (uint32_t)((16 * kk + (lane & 15)) * SROWA +
                                          16 * np + 8 * (lane >> 4)) * 2;
                uint32_t t0, t1, t2, t3;
                ldsm_x4_t(t0, t1, t2, t3, sb + oVhi + off);
                vbh[2 * np][0] = t0; vbh[2 * np][1] = t1;
                vbh[2 * np + 1][0] = t2; vbh[2 * np + 1][1] = t3;
                ldsm_x4_t(t0, t1, t2, t3, sb + oVlo + off);
                vbl[2 * np][0] = t0; vbl[2 * np][1] = t1;
                vbl[2 * np + 1][0] = t2; vbl[2 * np + 1][1] = t3;
            }
#pragma unroll
            for (int j = 0; j < 8; j++) {
                mma16816(oacc[j], ph[kk], vbh[j]);
                mma16816(oacc[j], ph[kk], vbl[j]);
                mma16816(oacc[j], pl[kk], vbh[j]);
            }
        }
        __syncthreads();
    }

    // ---- epilogue: y[B,T,H,D] as bf16 hi/lo ----
    float inv1 = 1.0f / l1, inv2 = 1.0f / l2;
    int b = bh >> 4, h = bh & 15;
    size_t off1 = ((size_t)(b * Tdim + r1) * Hdim + h) * Ddim;
    size_t off2 = ((size_t)(b * Tdim + r2) * Hdim + h) * Ddim;
    int d0 = 2 * (lane & 3);
#pragma unroll
    for (int j = 0; j < 8; j++) {
        float a0 = oacc[j][0] * inv1, a1 = oacc[j][1] * inv1;
        float b0 = oacc[j][2] * inv2, b1 = oacc[j][3] * inv2;
        *(uint32_t*)&g_yh[off1 + 8 * j + d0] = pack2bf16(a0, a1);
        *(uint32_t*)&g_yl[off1 + 8 * j + d0] = pack2bf16_lo(a0, a1);
        *(uint32_t*)&g_yh[off2 + 8 * j + d0] = pack2bf16(b0, b1);
        *(uint32_t*)&g_yl[off2 + 8 * j + d0] = pack2bf16_lo(b0, b1);
    }
}

// ---------------------------------------------------------------------------
extern "C" void kernel_launch(void* const* d_in, const int* in_sizes, int n_in,
                              void* d_out, int out_size) {
    const float* x = (const float*)d_in[0];        // [B,T,C]
    const float* w_attn = (const float*)d_in[1];   // [3C,C]
    const float* w_proj = (const float*)d_in[2];   // [C,C]
    float* out = (float*)d_out;                    // [B,T,C]

    // Resolve device-global addresses host-side
    __nv_bfloat16 *xh, *xl, *wah, *wal, *wph, *wpl, *yh, *yl;
    cudaGetSymbolAddress((void**)&xh, g_xh);
    cudaGetSymbolAddress((void**)&xl, g_xl);
    cudaGetSymbolAddress((void**)&wah, g_wah);
    cudaGetSymbolAddress((void**)&wal, g_wal);
    cudaGetSymbolAddress((void**)&wph, g_wph);
    cudaGetSymbolAddress((void**)&wpl, g_wpl);
    cudaGetSymbolAddress((void**)&yh, g_yh);
    cudaGetSymbolAddress((void**)&yl, g_yl);

    // Pre-pass: one-time fp32 -> bf16 hi/lo splits
    const int nx4 = Mrows * Cdim / 4;          // 1M
    const int nwa4 = 3 * Cdim * Cdim / 4;      // 768K
    const int nwp4 = Cdim * Cdim / 4;          // 256K
    split2_kernel<<<(nx4 + 255) / 256, 256>>>(x, xh, xl, nx4);
    split2_kernel<<<(nwa4 + 255) / 256, 256>>>(w_attn, wah, wal, nwa4);
    split2_kernel<<<(nwp4 + 255) / 256, 256>>>(w_proj, wph, wpl, nwp4);

    // GEMM1: qkv = x @ w_attn^T -> scattered bf16 hi/lo q/k/v (q pre-scaled)
    dim3 g1(3 * Cdim / 128, Mrows / 128);   // (24, 32)
    gemm_bf<1><<<g1, 256>>>(xh, xl, wah, wal, nullptr, Mrows, 3 * Cdim, Cdim);

    // Attention (tensor cores)
    dim3 ga(Tdim / 128, Bdim * Hdim);       // (16, 32)
    attn_mma<<<ga, 256>>>();

    // GEMM2: out = y @ w_proj^T
    dim3 g2(Cdim / 128, Mrows / 128);       // (8, 32)
    gemm_bf<0><<<g2, 256>>>(yh, yl, wph, wpl, out, Mrows, Cdim, Cdim);
}

// round 7
// speedup vs baseline: 1.0154x; 1.0154x over previous
#include <cuda_runtime.h>
#include <cuda_bf16.h>
#include <cstdint>
#include <math.h>

// Problem constants
#define Bdim 2
#define Tdim 2048
#define Cdim 1024
#define Hdim 16
#define Ddim 64
#define Mrows (Bdim * Tdim)   // 4096

// Device-global scratch, all bf16 hi/lo pairs (allocation-free)
__device__ __align__(16) __nv_bfloat16 g_xh[(size_t)Mrows * Cdim];
__device__ __align__(16) __nv_bfloat16 g_xl[(size_t)Mrows * Cdim];
__device__ __align__(16) __nv_bfloat16 g_wah[(size_t)3 * Cdim * Cdim];
__device__ __align__(16) __nv_bfloat16 g_wal[(size_t)3 * Cdim * Cdim];
__device__ __align__(16) __nv_bfloat16 g_wph[(size_t)Cdim * Cdim];
__device__ __align__(16) __nv_bfloat16 g_wpl[(size_t)Cdim * Cdim];
__device__ __align__(16) __nv_bfloat16 g_qh[(size_t)Bdim * Hdim * Tdim * Ddim];
__device__ __align__(16) __nv_bfloat16 g_ql[(size_t)Bdim * Hdim * Tdim * Ddim];
__device__ __align__(16) __nv_bfloat16 g_kh[(size_t)Bdim * Hdim * Tdim * Ddim];
__device__ __align__(16) __nv_bfloat16 g_kl[(size_t)Bdim * Hdim * Tdim * Ddim];
__device__ __align__(16) __nv_bfloat16 g_vh[(size_t)Bdim * Hdim * Tdim * Ddim];
__device__ __align__(16) __nv_bfloat16 g_vl[(size_t)Bdim * Hdim * Tdim * Ddim];
__device__ __align__(16) __nv_bfloat16 g_yh[(size_t)Bdim * Tdim * Cdim];
__device__ __align__(16) __nv_bfloat16 g_yl[(size_t)Bdim * Tdim * Cdim];

// ---------------------------------------------------------------------------
// Helpers
// ---------------------------------------------------------------------------
__device__ __forceinline__ uint32_t smem_u32(const void* p) {
    uint32_t a;
    asm("{ .reg .u64 t; cvta.to.shared.u64 t, %1; cvt.u32.u64 %0, t; }" : "=r"(a) : "l"(p));
    return a;
}

__device__ __forceinline__ void ldsm_x4(uint32_t& r0, uint32_t& r1, uint32_t& r2, uint32_t& r3,
                                        uint32_t addr) {
    asm volatile("ldmatrix.sync.aligned.m8n8.x4.shared.b16 {%0,%1,%2,%3}, [%4];"
                 : "=r"(r0), "=r"(r1), "=r"(r2), "=r"(r3) : "r"(addr));
}
__device__ __forceinline__ void ldsm_x4_t(uint32_t& r0, uint32_t& r1, uint32_t& r2, uint32_t& r3,
                                          uint32_t addr) {
    asm volatile("ldmatrix.sync.aligned.m8n8.x4.trans.shared.b16 {%0,%1,%2,%3}, [%4];"
                 : "=r"(r0), "=r"(r1), "=r"(r2), "=r"(r3) : "r"(addr));
}

__device__ __forceinline__ void mma16816(float* c, const uint32_t* a, const uint32_t* b) {
    asm volatile(
        "mma.sync.aligned.m16n8k16.row.col.f32.bf16.bf16.f32 "
        "{%0,%1,%2,%3}, {%4,%5,%6,%7}, {%8,%9}, {%0,%1,%2,%3};"
        : "+f"(c[0]), "+f"(c[1]), "+f"(c[2]), "+f"(c[3])
        : "r"(a[0]), "r"(a[1]), "r"(a[2]), "r"(a[3]), "r"(b[0]), "r"(b[1]));
}

__device__ __forceinline__ uint32_t pack2bf16(float x, float y) {
    __nv_bfloat162 t;
    t.x = __float2bfloat16_rn(x);
    t.y = __float2bfloat16_rn(y);
    return *reinterpret_cast<uint32_t*>(&t);
}
__device__ __forceinline__ uint32_t pack2bf16_lo(float x, float y) {
    float hx = __bfloat162float(__float2bfloat16_rn(x));
    float hy = __bfloat162float(__float2bfloat16_rn(y));
    __nv_bfloat162 t;
    t.x = __float2bfloat16_rn(x - hx);
    t.y = __float2bfloat16_rn(y - hy);
    return *reinterpret_cast<uint32_t*>(&t);
}

#define SROW 40    // GEMM smem row stride in bf16 (32-col chunks; conflict-free ldmatrix)
#define SROWA 72   // Attention smem row stride in bf16 (64-col tiles; conflict-free)

// GEMM smem layout (bytes): 2 stages, each 4 tiles of 128*SROW bf16
#define GTILE 10240            // 128*40*2
#define GSTAGE 40960           // 4*GTILE
#define GSMEM (2 * GSTAGE)     // 81920

// Attention smem layout: 2 stages, each Khi/Klo/Vhi/Vlo of 64*SROWA bf16
#define ATILE 9216             // 64*72*2
#define ASTAGE 36864           // 4*ATILE
#define ASMEM (2 * ASTAGE)     // 73728

// ---------------------------------------------------------------------------
// Pre-pass: split fp32 array into bf16 hi/lo arrays. n4 = n/4.
// ---------------------------------------------------------------------------
__global__ void split2_kernel(const float* __restrict__ src, __nv_bfloat16* __restrict__ hi,
                              __nv_bfloat16* __restrict__ lo, int n4) {
    int i = blockIdx.x * blockDim.x + threadIdx.x;
    if (i < n4) {
        float4 v = ((const float4*)src)[i];
        ((uint2*)hi)[i] = make_uint2(pack2bf16(v.x, v.y), pack2bf16(v.z, v.w));
        ((uint2*)lo)[i] = make_uint2(pack2bf16_lo(v.x, v.y), pack2bf16_lo(v.z, v.w));
    }
}

// ---------------------------------------------------------------------------
// Tensor-core GEMM (NT), operands pre-split bf16 hi/lo, double-buffered smem.
// C[M,N] = A[M,K] @ B[N,K]^T (3-term). 128x128 CTA tile, 256 thr, 8 warps.
// One __syncthreads per K-chunk; STS(ch+1) + LDG(ch+2) overlap MMA(ch).
// ---------------------------------------------------------------------------
template <int MODE>
__global__ void __launch_bounds__(256, 2) gemm_bf(const __nv_bfloat16* __restrict__ Ah,
                                                  const __nv_bfloat16* __restrict__ Al,
                                                  const __nv_bfloat16* __restrict__ Bh,
                                                  const __nv_bfloat16* __restrict__ Bl,
                                                  float* __restrict__ Cout,
                                                  int M, int N, int K) {
    extern __shared__ __align__(16) char smem[];
    const uint32_t sb = smem_u32(smem);

    const int tid = threadIdx.x;
    const int lane = tid & 31;
    const int wid = tid >> 5;
    const int wm = wid >> 2;
    const int wn = wid & 3;
    const int bm = blockIdx.y * 128;
    const int bn = blockIdx.x * 128;

    // load mapping: row = tid>>2 (+64), c8 = (tid&3)*8  (64B segments)
    const int lrow0 = tid >> 2;
    const int lc8 = (tid & 3) * 8;

    const __nv_bfloat16* Agh = Ah + (size_t)bm * K;
    const __nv_bfloat16* Agl = Al + (size_t)bm * K;
    const __nv_bfloat16* Bgh = Bh + (size_t)bn * K;
    const __nv_bfloat16* Bgl = Bl + (size_t)bn * K;

    uint4 rAh[2], rAl[2], rBh[2], rBl[2];
    const int nch = K / 32;

    auto ldchunk = [&](int ch) {
        const int koff = ch * 32 + lc8;
#pragma unroll
        for (int p = 0; p < 2; p++) {
            int row = lrow0 + 64 * p;
            rAh[p] = *(const uint4*)&Agh[(size_t)row * K + koff];
            rAl[p] = *(const uint4*)&Agl[(size_t)row * K + koff];
            rBh[p] = *(const uint4*)&Bgh[(size_t)row * K + koff];
            rBl[p] = *(const uint4*)&Bgl[(size_t)row * K + koff];
        }
    };
    auto stchunk = [&](uint32_t stOff) {
#pragma unroll
        for (int p = 0; p < 2; p++) {
            uint32_t so = (uint32_t)((lrow0 + 64 * p) * SROW + lc8) * 2;
            *(uint4*)(smem + stOff + 0 * GTILE + so) = rAh[p];
            *(uint4*)(smem + stOff + 1 * GTILE + so) = rAl[p];
            *(uint4*)(smem + stOff + 2 * GTILE + so) = rBh[p];
            *(uint4*)(smem + stOff + 3 * GTILE + so) = rBl[p];
        }
    };

    float acc[4][4][4];
#pragma unroll
    for (int i = 0; i < 4; i++)
#pragma unroll
        for (int j = 0; j < 4; j++)
#pragma unroll
            for (int r = 0; r < 4; r++) acc[i][j][r] = 0.f;

    const uint32_t aOff = (uint32_t)((wm * 64 + (lane & 15)) * SROW + (lane >> 4) * 8) * 2;
    const uint32_t bOff = (uint32_t)((wn * 32 + (lane >> 4) * 8 + (lane & 7)) * SROW +
                                     ((lane >> 3) & 1) * 8) * 2;

    // prologue: chunk0 -> stage0; chunk1 -> regs
    ldchunk(0);
    stchunk(0);
    ldchunk(1);
    __syncthreads();

    for (int ch = 0; ch < nch; ch++) {
        const int s = ch & 1;
        const uint32_t cur = (uint32_t)s * GSTAGE;
        const uint32_t nxt = (uint32_t)(s ^ 1) * GSTAGE;

        if (ch + 1 < nch) stchunk(nxt);      // regs hold chunk ch+1
        if (ch + 2 < nch) ldchunk(ch + 2);   // refill regs

        const uint32_t aHiB = sb + cur + 0 * GTILE;
        const uint32_t aLoB = sb + cur + 1 * GTILE;
        const uint32_t bHiB = sb + cur + 2 * GTILE;
        const uint32_t bLoB = sb + cur + 3 * GTILE;

#pragma unroll
        for (int kk = 0; kk < 2; kk++) {
            const uint32_t kByte = (uint32_t)(kk * 16 * 2);
            uint32_t af[4][4];
            uint32_t bh[4][2], bl[4][2];
#pragma unroll
            for (int i = 0; i < 4; i++)
                ldsm_x4(af[i][0], af[i][1], af[i][2], af[i][3],
                        aHiB + aOff + kByte + (uint32_t)(i * 16 * SROW * 2));
#pragma unroll
            for (int jp = 0; jp < 2; jp++) {
                uint32_t r0_, r1_, r2_, r3_;
                ldsm_x4(r0_, r1_, r2_, r3_, bHiB + bOff + kByte + (uint32_t)(jp * 16 * SROW * 2));
                bh[jp * 2][0] = r0_; bh[jp * 2][1] = r1_;
                bh[jp * 2 + 1][0] = r2_; bh[jp * 2 + 1][1] = r3_;
                ldsm_x4(r0_, r1_, r2_, r3_, bLoB + bOff + kByte + (uint32_t)(jp * 16 * SROW * 2));
                bl[jp * 2][0] = r0_; bl[jp * 2][1] = r1_;
                bl[jp * 2 + 1][0] = r2_; bl[jp * 2 + 1][1] = r3_;
            }
#pragma unroll
            for (int i = 0; i < 4; i++)
#pragma unroll
                for (int j = 0; j < 4; j++) {
                    mma16816(acc[i][j], af[i], bh[j]);
                    mma16816(acc[i][j], af[i], bl[j]);
                }
#pragma unroll
            for (int i = 0; i < 4; i++)
                ldsm_x4(af[i][0], af[i][1], af[i][2], af[i][3],
                        aLoB + aOff + kByte + (uint32_t)(i * 16 * SROW * 2));
#pragma unroll
            for (int i = 0; i < 4; i++)
#pragma unroll
                for (int j = 0; j < 4; j++)
                    mma16816(acc[i][j], af[i], bh[j]);
        }
        __syncthreads();
    }

    const int lr = lane >> 2;
    const int lc = (lane & 3) * 2;

    if (MODE == 0) {
#pragma unroll
        for (int i = 0; i < 4; i++) {
            int rowA = bm + wm * 64 + i * 16 + lr;
#pragma unroll
            for (int j = 0; j < 4; j++) {
                int col = bn + wn * 32 + j * 8 + lc;
                *(float2*)&Cout[(size_t)rowA * N + col] = make_float2(acc[i][j][0], acc[i][j][1]);
                *(float2*)&Cout[(size_t)(rowA + 8) * N + col] = make_float2(acc[i][j][2], acc[i][j][3]);
            }
        }
    } else {
        int col0 = bn + wn * 32;
        int sdx = col0 >> 10;
        int rr = col0 & (Cdim - 1);
        int h = rr >> 6;
        int d0 = (rr & (Ddim - 1)) + lc;
        __nv_bfloat16* dh = (sdx == 0) ? g_qh : (sdx == 1) ? g_kh : g_vh;
        __nv_bfloat16* dl = (sdx == 0) ? g_ql : (sdx == 1) ? g_kl : g_vl;
        float sc = (sdx == 0) ? 0.125f : 1.0f;
#pragma unroll
        for (int i = 0; i < 4; i++) {
            int rowA = bm + wm * 64 + i * 16 + lr;
#pragma unroll
            for (int hh = 0; hh < 2; hh++) {
                int row = rowA + hh * 8;
                int b = row >> 11;
                int t = row & (Tdim - 1);
                size_t off = ((size_t)(b * Hdim + h) * Tdim + t) * Ddim;
#pragma unroll
                for (int j = 0; j < 4; j++) {
                    float f0 = acc[i][j][hh * 2] * sc;
                    float f1 = acc[i][j][hh * 2 + 1] * sc;
                    *(uint32_t*)&dh[off + d0 + j * 8] = pack2bf16(f0, f1);
                    *(uint32_t*)&dl[off + d0 + j * 8] = pack2bf16_lo(f0, f1);
                }
            }
        }
    }
}

// ---------------------------------------------------------------------------
// Tensor-core causal flash attention (mma.sync bf16, 3-term splits),
// double-buffered K/V staging: one __syncthreads per tile.
// Grid: (T/128, B*H), 256 threads. Warp w owns q-rows [16w,16w+16).
// ---------------------------------------------------------------------------
__global__ void __launch_bounds__(256) attn_mma() {
    extern __shared__ __align__(16) char sbuf[];
    const uint32_t sb = smem_u32(sbuf);
    const int tid = threadIdx.x;
    const int lane = tid & 31;
    const int w = tid >> 5;
    const int bh = blockIdx.y;
    const int q0 = (int)(gridDim.x - 1 - blockIdx.x) * 128;   // heavy tiles first

    const size_t headoff = (size_t)bh * Tdim * Ddim;
    const int ktmax = (q0 + 127) >> 6;

    // KV staging regs + mapping: row = tid>>3 (+32), c8 = (tid&7)*8
    const int arow = tid >> 3;
    const int ac8 = (tid & 7) * 8;
    uint4 kh_r[2], kl_r[2], vh_r[2], vl_r[2];

    auto ldkv = [&](int kt) {
        const size_t base = headoff + (size_t)(kt * 64) * Ddim;
#pragma unroll
        for (int p = 0; p < 2; p++) {
            size_t o = base + (size_t)(arow + 32 * p) * Ddim + ac8;
            kh_r[p] = *(const uint4*)&g_kh[o];
            kl_r[p] = *(const uint4*)&g_kl[o];
            vh_r[p] = *(const uint4*)&g_vh[o];
            vl_r[p] = *(const uint4*)&g_vl[o];
        }
    };
    auto stkv = [&](uint32_t stOff) {
#pragma unroll
        for (int p = 0; p < 2; p++) {
            uint32_t so = (uint32_t)((arow + 32 * p) * SROWA + ac8) * 2;
            *(uint4*)(sbuf + stOff + 0 * ATILE + so) = kh_r[p];
            *(uint4*)(sbuf + stOff + 1 * ATILE + so) = kl_r[p];
            *(uint4*)(sbuf + stOff + 2 * ATILE + so) = vh_r[p];
            *(uint4*)(sbuf + stOff + 3 * ATILE + so) = vl_r[p];
        }
    };

    // ---- stage Q (128x64) hi/lo into smem overlay, load A-fragments ----
    ldkv(0);   // issue kv0 LDGs early; they retire while we stage Q
    {
        const uint4* qgh = (const uint4*)(g_qh + headoff + (size_t)q0 * Ddim);
        const uint4* qgl = (const uint4*)(g_ql + headoff + (size_t)q0 * Ddim);
#pragma unroll
        for (int p = 0; p < 4; p++) {
            int u = p * 256 + tid;          // 0..1023
            int row = u >> 3;
            int c8 = (u & 7) * 8;
            uint32_t so = (uint32_t)(row * SROWA + c8) * 2;
            *(uint4*)(sbuf + so) = qgh[u];               // Q hi @ 0
            *(uint4*)(sbuf + 18432 + so) = qgl[u];       // Q lo @ 18432
        }
    }
    __syncthreads();

    uint32_t qh[4][4], ql[4][4];
#pragma unroll
    for (int kk = 0; kk < 4; kk++) {
        uint32_t off = (uint32_t)((16 * w + (lane & 15)) * SROWA + 16 * kk + 8 * (lane >> 4)) * 2;
        ldsm_x4(qh[kk][0], qh[kk][1], qh[kk][2], qh[kk][3], sb + off);
        ldsm_x4(ql[kk][0], ql[kk][1], ql[kk][2], ql[kk][3], sb + 18432 + off);
    }
    __syncthreads();

    // prologue: kv0 -> stage0, kv1 -> regs
    stkv(0);
    ldkv(1);
    __syncthreads();

    // state
    float oacc[8][4];
#pragma unroll
    for (int j = 0; j < 8; j++)
#pragma unroll
        for (int r = 0; r < 4; r++) oacc[j][r] = 0.f;
    float m1 = -1e30f, m2 = -1e30f, l1 = 0.f, l2 = 0.f;

    const int r1 = q0 + 16 * w + (lane >> 2);
    const int r2 = r1 + 8;

    for (int kt = 0; kt <= ktmax; kt++) {
        const int kbase = kt * 64;
        const int s = kt & 1;
        const uint32_t cur = (uint32_t)s * ASTAGE;
        const uint32_t nxt = (uint32_t)(s ^ 1) * ASTAGE;

        if (kt + 1 <= ktmax) stkv(nxt);       // regs hold tile kt+1
        if (kt + 2 <= ktmax) ldkv(kt + 2);    // refill regs

        const uint32_t oKhi = cur + 0 * ATILE, oKlo = cur + 1 * ATILE;
        const uint32_t oVhi = cur + 2 * ATILE, oVlo = cur + 3 * ATILE;

        // ---- S = Q.K^T (3-term) ----
        float sacc[8][4];
#pragma unroll
        for (int j = 0; j < 8; j++)
#pragma unroll
            for (int r = 0; r < 4; r++) sacc[j][r] = 0.f;

#pragma unroll
        for (int kk = 0; kk < 4; kk++) {
            uint32_t bhp[8][2], blp[8][2];
#pragma unroll
            for (int np = 0; np < 4; np++) {
                uint32_t off = (uint32_t)((np * 16 + (lane >> 4) * 8 + (lane & 7)) * SROWA +
                                          ((lane >> 3) & 1) * 8 + 16 * kk) * 2;
                uint32_t t0, t1, t2, t3;
                ldsm_x4(t0, t1, t2, t3, sb + oKhi + off);
                bhp[2 * np][0] = t0; bhp[2 * np][1] = t1;
                bhp[2 * np + 1][0] = t2; bhp[2 * np + 1][1] = t3;
                ldsm_x4(t0, t1, t2, t3, sb + oKlo + off);
                blp[2 * np][0] = t0; blp[2 * np][1] = t1;
                blp[2 * np + 1][0] = t2; blp[2 * np + 1][1] = t3;
            }
#pragma unroll
            for (int j = 0; j < 8; j++) {
                mma16816(sacc[j], qh[kk], bhp[j]);
                mma16816(sacc[j], qh[kk], blp[j]);
                mma16816(sacc[j], ql[kk], bhp[j]);
            }
        }

        // ---- causal mask (diagonal tiles only; warp-uniform branch) ----
        if (kbase + 63 > q0 + 16 * w) {
            const int c0 = kbase + 2 * (lane & 3);
#pragma unroll
            for (int j = 0; j < 8; j++) {
                int cj = c0 + 8 * j;
                if (cj > r1)     sacc[j][0] = -1e30f;
                if (cj + 1 > r1) sacc[j][1] = -1e30f;
                if (cj > r2)     sacc[j][2] = -1e30f;
                if (cj + 1 > r2) sacc[j][3] = -1e30f;
            }
        }

        // ---- online softmax ----
        float t1m = -1e30f, t2m = -1e30f;
#pragma unroll
        for (int j = 0; j < 8; j++) {
            t1m = fmaxf(t1m, fmaxf(sacc[j][0], sacc[j][1]));
            t2m = fmaxf(t2m, fmaxf(sacc[j][2], sacc[j][3]));
        }
        t1m = fmaxf(t1m, __shfl_xor_sync(0xffffffffu, t1m, 1));
        t1m = fmaxf(t1m, __shfl_xor_sync(0xffffffffu, t1m, 2));
        t2m = fmaxf(t2m, __shfl_xor_sync(0xffffffffu, t2m, 1));
        t2m = fmaxf(t2m, __shfl_xor_sync(0xffffffffu, t2m, 2));

        float nm1 = fmaxf(m1, t1m), nm2 = fmaxf(m2, t2m);
        float corr1 = __expf(m1 - nm1), corr2 = __expf(m2 - nm2);
        m1 = nm1; m2 = nm2;

        float s1 = 0.f, s2 = 0.f;
#pragma unroll
        for (int j = 0; j < 8; j++) {
            sacc[j][0] = __expf(sacc[j][0] - m1);
            sacc[j][1] = __expf(sacc[j][1] - m1);
            sacc[j][2] = __expf(sacc[j][2] - m2);
            sacc[j][3] = __expf(sacc[j][3] - m2);
            s1 += sacc[j][0] + sacc[j][1];
            s2 += sacc[j][2] + sacc[j][3];
        }
        s1 += __shfl_xor_sync(0xffffffffu, s1, 1);
        s1 += __shfl_xor_sync(0xffffffffu, s1, 2);
        s2 += __shfl_xor_sync(0xffffffffu, s2, 1);
        s2 += __shfl_xor_sync(0xffffffffu, s2, 2);
        l1 = l1 * corr1 + s1;
        l2 = l2 * corr2 + s2;

        // pack P into A-fragments (hi/lo)
        uint32_t ph[4][4], pl[4][4];
#pragma unroll
        for (int kk = 0; kk < 4; kk++) {
            int j0 = 2 * kk, j1 = 2 * kk + 1;
            ph[kk][0] = pack2bf16(sacc[j0][0], sacc[j0][1]);
            ph[kk][1] = pack2bf16(sacc[j0][2], sacc[j0][3]);
            ph[kk][2] = pack2bf16(sacc[j1][0], sacc[j1][1]);
            ph[kk][3] = pack2bf16(sacc[j1][2], sacc[j1][3]);
            pl[kk][0] = pack2bf16_lo(sacc[j0][0], sacc[j0][1]);
            pl[kk][1] = pack2bf16_lo(sacc[j0][2], sacc[j0][3]);
            pl[kk][2] = pack2bf16_lo(sacc[j1][0], sacc[j1][1]);
            pl[kk][3] = pack2bf16_lo(sacc[j1][2], sacc[j1][3]);
        }

        // rescale O
#pragma unroll
        for (int j = 0; j < 8; j++) {
            oacc[j][0] *= corr1; oacc[j][1] *= corr1;
            oacc[j][2] *= corr2; oacc[j][3] *= corr2;
        }

        // ---- O += P.V (3-term; V via ldmatrix.trans) ----
#pragma unroll
        for (int kk = 0; kk < 4; kk++) {
            uint32_t vbh[8][2], vbl[8][2];
#pragma unroll
            for (int np = 0; np < 4; np++) {
                uint32_t off = (uint32_t)((16 * kk + (lane & 15)) * SROWA +
                                          16 * np + 8 * (lane >> 4)) * 2;
                uint32_t t0, t1, t2, t3;
                ldsm_x4_t(t0, t1, t2, t3, sb + oVhi + off);
                vbh[2 * np][0] = t0; vbh[2 * np][1] = t1;
                vbh[2 * np + 1][0] = t2; vbh[2 * np + 1][1] = t3;
                ldsm_x4_t(t0, t1, t2, t3, sb + oVlo + off);
                vbl[2 * np][0] = t0; vbl[2 * np][1] = t1;
                vbl[2 * np + 1][0] = t2; vbl[2 * np + 1][1] = t3;
            }
#pragma unroll
            for (int j = 0; j < 8; j++) {
                mma16816(oacc[j], ph[kk], vbh[j]);
                mma16816(oacc[j], ph[kk], vbl[j]);
                mma16816(oacc[j], pl[kk], vbh[j]);
            }
        }
        __syncthreads();
    }

    // ---- epilogue: y[B,T,H,D] as bf16 hi/lo ----
    float inv1 = 1.0f / l1, inv2 = 1.0f / l2;
    int b = bh >> 4, h = bh & 15;
    size_t off1 = ((size_t)(b * Tdim + r1) * Hdim + h) * Ddim;
    size_t off2 = ((size_t)(b * Tdim + r2) * Hdim + h) * Ddim;
    int d0 = 2 * (lane & 3);
#pragma unroll
    for (int j = 0; j < 8; j++) {
        float a0 = oacc[j][0] * inv1, a1 = oacc[j][1] * inv1;
        float b0 = oacc[j][2] * inv2, b1 = oacc[j][3] * inv2;
        *(uint32_t*)&g_yh[off1 + 8 * j + d0] = pack2bf16(a0, a1);
        *(uint32_t*)&g_yl[off1 + 8 * j + d0] = pack2bf16_lo(a0, a1);
        *(uint32_t*)&g_yh[off2 + 8 * j + d0] = pack2bf16(b0, b1);
        *(uint32_t*)&g_yl[off2 + 8 * j + d0] = pack2bf16_lo(b0, b1);
    }
}

// ---------------------------------------------------------------------------
extern "C" void kernel_launch(void* const* d_in, const int* in_sizes, int n_in,
                              void* d_out, int out_size) {
    const float* x = (const float*)d_in[0];        // [B,T,C]
    const float* w_attn = (const float*)d_in[1];   // [3C,C]
    const float* w_proj = (const float*)d_in[2];   // [C,C]
    float* out = (float*)d_out;                    // [B,T,C]

    // Resolve device-global addresses host-side
    __nv_bfloat16 *xh, *xl, *wah, *wal, *wph, *wpl, *yh, *yl;
    cudaGetSymbolAddress((void**)&xh, g_xh);
    cudaGetSymbolAddress((void**)&xl, g_xl);
    cudaGetSymbolAddress((void**)&wah, g_wah);
    cudaGetSymbolAddress((void**)&wal, g_wal);
    cudaGetSymbolAddress((void**)&wph, g_wph);
    cudaGetSymbolAddress((void**)&wpl, g_wpl);
    cudaGetSymbolAddress((void**)&yh, g_yh);
    cudaGetSymbolAddress((void**)&yl, g_yl);

    cudaFuncSetAttribute(gemm_bf<0>, cudaFuncAttributeMaxDynamicSharedMemorySize, GSMEM);
    cudaFuncSetAttribute(gemm_bf<1>, cudaFuncAttributeMaxDynamicSharedMemorySize, GSMEM);
    cudaFuncSetAttribute(attn_mma, cudaFuncAttributeMaxDynamicSharedMemorySize, ASMEM);

    // Pre-pass: one-time fp32 -> bf16 hi/lo splits
    const int nx4 = Mrows * Cdim / 4;          // 1M
    const int nwa4 = 3 * Cdim * Cdim / 4;      // 768K
    const int nwp4 = Cdim * Cdim / 4;          // 256K
    split2_kernel<<<(nx4 + 255) / 256, 256>>>(x, xh, xl, nx4);
    split2_kernel<<<(nwa4 + 255) / 256, 256>>>(w_attn, wah, wal, nwa4);
    split2_kernel<<<(nwp4 + 255) / 256, 256>>>(w_proj, wph, wpl, nwp4);

    // GEMM1: qkv = x @ w_attn^T -> scattered bf16 hi/lo q/k/v (q pre-scaled)
    dim3 g1(3 * Cdim / 128, Mrows / 128);   // (24, 32)
    gemm_bf<1><<<g1, 256, GSMEM>>>(xh, xl, wah, wal, nullptr, Mrows, 3 * Cdim, Cdim);

    // Attention (tensor cores, double-buffered)
    dim3 ga(Tdim / 128, Bdim * Hdim);       // (16, 32)
    attn_mma<<<ga, 256, ASMEM>>>();

    // GEMM2: out = y @ w_proj^T
    dim3 g2(Cdim / 128, Mrows / 128);       // (8, 32)
    gemm_bf<0><<<g2, 256, GSMEM>>>(yh, yl, wph, wpl, out, Mrows, Cdim, Cdim);
}

// round 8
// speedup vs baseline: 1.0178x; 1.0024x over previous
#include <cuda_runtime.h>
#include <cuda_bf16.h>
#include <cstdint>
#include <math.h>

// Problem constants
#define Bdim 2
#define Tdim 2048
#define Cdim 1024
#define Hdim 16
#define Ddim 64
#define Mrows (Bdim * Tdim)   // 4096

// Device-global scratch, all bf16 hi/lo pairs (allocation-free)
__device__ __align__(16) __nv_bfloat16 g_xh[(size_t)Mrows * Cdim];
__device__ __align__(16) __nv_bfloat16 g_xl[(size_t)Mrows * Cdim];
__device__ __align__(16) __nv_bfloat16 g_wah[(size_t)3 * Cdim * Cdim];
__device__ __align__(16) __nv_bfloat16 g_wal[(size_t)3 * Cdim * Cdim];
__device__ __align__(16) __nv_bfloat16 g_wph[(size_t)Cdim * Cdim];
__device__ __align__(16) __nv_bfloat16 g_wpl[(size_t)Cdim * Cdim];
__device__ __align__(16) __nv_bfloat16 g_qh[(size_t)Bdim * Hdim * Tdim * Ddim];
__device__ __align__(16) __nv_bfloat16 g_ql[(size_t)Bdim * Hdim * Tdim * Ddim];
__device__ __align__(16) __nv_bfloat16 g_kh[(size_t)Bdim * Hdim * Tdim * Ddim];
__device__ __align__(16) __nv_bfloat16 g_kl[(size_t)Bdim * Hdim * Tdim * Ddim];
__device__ __align__(16) __nv_bfloat16 g_vh[(size_t)Bdim * Hdim * Tdim * Ddim];
__device__ __align__(16) __nv_bfloat16 g_vl[(size_t)Bdim * Hdim * Tdim * Ddim];
__device__ __align__(16) __nv_bfloat16 g_yh[(size_t)Bdim * Tdim * Cdim];
__device__ __align__(16) __nv_bfloat16 g_yl[(size_t)Bdim * Tdim * Cdim];

// ---------------------------------------------------------------------------
// Helpers
// ---------------------------------------------------------------------------
__device__ __forceinline__ uint32_t smem_u32(const void* p) {
    uint32_t a;
    asm("{ .reg .u64 t; cvta.to.shared.u64 t, %1; cvt.u32.u64 %0, t; }" : "=r"(a) : "l"(p));
    return a;
}

__device__ __forceinline__ void ldsm_x4(uint32_t& r0, uint32_t& r1, uint32_t& r2, uint32_t& r3,
                                        uint32_t addr) {
    asm volatile("ldmatrix.sync.aligned.m8n8.x4.shared.b16 {%0,%1,%2,%3}, [%4];"
                 : "=r"(r0), "=r"(r1), "=r"(r2), "=r"(r3) : "r"(addr));
}
__device__ __forceinline__ void ldsm_x4_t(uint32_t& r0, uint32_t& r1, uint32_t& r2, uint32_t& r3,
                                          uint32_t addr) {
    asm volatile("ldmatrix.sync.aligned.m8n8.x4.trans.shared.b16 {%0,%1,%2,%3}, [%4];"
                 : "=r"(r0), "=r"(r1), "=r"(r2), "=r"(r3) : "r"(addr));
}

__device__ __forceinline__ void mma16816(float* c, const uint32_t* a, const uint32_t* b) {
    asm volatile(
        "mma.sync.aligned.m16n8k16.row.col.f32.bf16.bf16.f32 "
        "{%0,%1,%2,%3}, {%4,%5,%6,%7}, {%8,%9}, {%0,%1,%2,%3};"
        : "+f"(c[0]), "+f"(c[1]), "+f"(c[2]), "+f"(c[3])
        : "r"(a[0]), "r"(a[1]), "r"(a[2]), "r"(a[3]), "r"(b[0]), "r"(b[1]));
}

__device__ __forceinline__ uint32_t pack2bf16(float x, float y) {
    __nv_bfloat162 t;
    t.x = __float2bfloat16_rn(x);
    t.y = __float2bfloat16_rn(y);
    return *reinterpret_cast<uint32_t*>(&t);
}
__device__ __forceinline__ uint32_t pack2bf16_lo(float x, float y) {
    float hx = __bfloat162float(__float2bfloat16_rn(x));
    float hy = __bfloat162float(__float2bfloat16_rn(y));
    __nv_bfloat162 t;
    t.x = __float2bfloat16_rn(x - hx);
    t.y = __float2bfloat16_rn(y - hy);
    return *reinterpret_cast<uint32_t*>(&t);
}

#define SROW 40    // GEMM smem row stride in bf16 (32-col chunks; conflict-free ldmatrix)
#define SROWA 72   // Attention smem row stride in bf16 (64-col tiles; conflict-free)

// GEMM smem layout (bytes): 2 stages, each 4 tiles of 128*SROW bf16
#define GTILE 10240            // 128*40*2
#define GSTAGE 40960           // 4*GTILE
#define GSMEM (2 * GSTAGE)     // 81920

// Attention smem layout: 2 stages, each Khi/Klo/Vhi/Vlo of 64*SROWA bf16
#define ATILE 9216             // 64*72*2
#define ASTAGE 36864           // 4*ATILE
#define ASMEM (2 * ASTAGE)     // 73728

// ---------------------------------------------------------------------------
// Pre-pass: split fp32 array into bf16 hi/lo arrays. n4 = n/4.
// ---------------------------------------------------------------------------
__global__ void split2_kernel(const float* __restrict__ src, __nv_bfloat16* __restrict__ hi,
                              __nv_bfloat16* __restrict__ lo, int n4) {
    int i = blockIdx.x * blockDim.x + threadIdx.x;
    if (i < n4) {
        float4 v = ((const float4*)src)[i];
        ((uint2*)hi)[i] = make_uint2(pack2bf16(v.x, v.y), pack2bf16(v.z, v.w));
        ((uint2*)lo)[i] = make_uint2(pack2bf16_lo(v.x, v.y), pack2bf16_lo(v.z, v.w));
    }
}

// ---------------------------------------------------------------------------
// Tensor-core GEMM (NT), pre-split bf16 hi/lo, double-buffered smem,
// MMA passes separated so accumulator reuse distance = 16 MMAs (no RAW stall).
// ---------------------------------------------------------------------------
template <int MODE>
__global__ void __launch_bounds__(256, 2) gemm_bf(const __nv_bfloat16* __restrict__ Ah,
                                                  const __nv_bfloat16* __restrict__ Al,
                                                  const __nv_bfloat16* __restrict__ Bh,
                                                  const __nv_bfloat16* __restrict__ Bl,
                                                  float* __restrict__ Cout,
                                                  int M, int N, int K) {
    extern __shared__ __align__(16) char smem[];
    const uint32_t sb = smem_u32(smem);

    const int tid = threadIdx.x;
    const int lane = tid & 31;
    const int wid = tid >> 5;
    const int wm = wid >> 2;
    const int wn = wid & 3;
    const int bm = blockIdx.y * 128;
    const int bn = blockIdx.x * 128;

    const int lrow0 = tid >> 2;
    const int lc8 = (tid & 3) * 8;

    const __nv_bfloat16* Agh = Ah + (size_t)bm * K;
    const __nv_bfloat16* Agl = Al + (size_t)bm * K;
    const __nv_bfloat16* Bgh = Bh + (size_t)bn * K;
    const __nv_bfloat16* Bgl = Bl + (size_t)bn * K;

    uint4 rAh[2], rAl[2], rBh[2], rBl[2];
    const int nch = K / 32;

    auto ldchunk = [&](int ch) {
        const int koff = ch * 32 + lc8;
#pragma unroll
        for (int p = 0; p < 2; p++) {
            int row = lrow0 + 64 * p;
            rAh[p] = *(const uint4*)&Agh[(size_t)row * K + koff];
            rAl[p] = *(const uint4*)&Agl[(size_t)row * K + koff];
            rBh[p] = *(const uint4*)&Bgh[(size_t)row * K + koff];
            rBl[p] = *(const uint4*)&Bgl[(size_t)row * K + koff];
        }
    };
    auto stchunk = [&](uint32_t stOff) {
#pragma unroll
        for (int p = 0; p < 2; p++) {
            uint32_t so = (uint32_t)((lrow0 + 64 * p) * SROW + lc8) * 2;
            *(uint4*)(smem + stOff + 0 * GTILE + so) = rAh[p];
            *(uint4*)(smem + stOff + 1 * GTILE + so) = rAl[p];
            *(uint4*)(smem + stOff + 2 * GTILE + so) = rBh[p];
            *(uint4*)(smem + stOff + 3 * GTILE + so) = rBl[p];
        }
    };

    float acc[4][4][4];
#pragma unroll
    for (int i = 0; i < 4; i++)
#pragma unroll
        for (int j = 0; j < 4; j++)
#pragma unroll
            for (int r = 0; r < 4; r++) acc[i][j][r] = 0.f;

    const uint32_t aOff = (uint32_t)((wm * 64 + (lane & 15)) * SROW + (lane >> 4) * 8) * 2;
    const uint32_t bOff = (uint32_t)((wn * 32 + (lane >> 4) * 8 + (lane & 7)) * SROW +
                                     ((lane >> 3) & 1) * 8) * 2;

    ldchunk(0);
    stchunk(0);
    ldchunk(1);
    __syncthreads();

    for (int ch = 0; ch < nch; ch++) {
        const int s = ch & 1;
        const uint32_t cur = (uint32_t)s * GSTAGE;
        const uint32_t nxt = (uint32_t)(s ^ 1) * GSTAGE;

        if (ch + 1 < nch) stchunk(nxt);
        if (ch + 2 < nch) ldchunk(ch + 2);

        const uint32_t aHiB = sb + cur + 0 * GTILE;
        const uint32_t aLoB = sb + cur + 1 * GTILE;
        const uint32_t bHiB = sb + cur + 2 * GTILE;
        const uint32_t bLoB = sb + cur + 3 * GTILE;

#pragma unroll
        for (int kk = 0; kk < 2; kk++) {
            const uint32_t kByte = (uint32_t)(kk * 16 * 2);
            uint32_t af[4][4];
            uint32_t bh[4][2], bl[4][2];
#pragma unroll
            for (int i = 0; i < 4; i++)
                ldsm_x4(af[i][0], af[i][1], af[i][2], af[i][3],
                        aHiB + aOff + kByte + (uint32_t)(i * 16 * SROW * 2));
#pragma unroll
            for (int jp = 0; jp < 2; jp++) {
                uint32_t r0_, r1_, r2_, r3_;
                ldsm_x4(r0_, r1_, r2_, r3_, bHiB + bOff + kByte + (uint32_t)(jp * 16 * SROW * 2));
                bh[jp * 2][0] = r0_; bh[jp * 2][1] = r1_;
                bh[jp * 2 + 1][0] = r2_; bh[jp * 2 + 1][1] = r3_;
                ldsm_x4(r0_, r1_, r2_, r3_, bLoB + bOff + kByte + (uint32_t)(jp * 16 * SROW * 2));
                bl[jp * 2][0] = r0_; bl[jp * 2][1] = r1_;
                bl[jp * 2 + 1][0] = r2_; bl[jp * 2 + 1][1] = r3_;
            }
            // pass 1: Ahi * Bhi  (16 independent accumulators)
#pragma unroll
            for (int i = 0; i < 4; i++)
#pragma unroll
                for (int j = 0; j < 4; j++)
                    mma16816(acc[i][j], af[i], bh[j]);
            // pass 2: Ahi * Blo
#pragma unroll
            for (int i = 0; i < 4; i++)
#pragma unroll
                for (int j = 0; j < 4; j++)
                    mma16816(acc[i][j], af[i], bl[j]);
            // reload A frags with lo
#pragma unroll
            for (int i = 0; i < 4; i++)
                ldsm_x4(af[i][0], af[i][1], af[i][2], af[i][3],
                        aLoB + aOff + kByte + (uint32_t)(i * 16 * SROW * 2));
            // pass 3: Alo * Bhi
#pragma unroll
            for (int i = 0; i < 4; i++)
#pragma unroll
                for (int j = 0; j < 4; j++)
                    mma16816(acc[i][j], af[i], bh[j]);
        }
        __syncthreads();
    }

    const int lr = lane >> 2;
    const int lc = (lane & 3) * 2;

    if (MODE == 0) {
#pragma unroll
        for (int i = 0; i < 4; i++) {
            int rowA = bm + wm * 64 + i * 16 + lr;
#pragma unroll
            for (int j = 0; j < 4; j++) {
                int col = bn + wn * 32 + j * 8 + lc;
                *(float2*)&Cout[(size_t)rowA * N + col] = make_float2(acc[i][j][0], acc[i][j][1]);
                *(float2*)&Cout[(size_t)(rowA + 8) * N + col] = make_float2(acc[i][j][2], acc[i][j][3]);
            }
        }
    } else {
        int col0 = bn + wn * 32;
        int sdx = col0 >> 10;
        int rr = col0 & (Cdim - 1);
        int h = rr >> 6;
        int d0 = (rr & (Ddim - 1)) + lc;
        __nv_bfloat16* dh = (sdx == 0) ? g_qh : (sdx == 1) ? g_kh : g_vh;
        __nv_bfloat16* dl = (sdx == 0) ? g_ql : (sdx == 1) ? g_kl : g_vl;
        float sc = (sdx == 0) ? 0.125f : 1.0f;
#pragma unroll
        for (int i = 0; i < 4; i++) {
            int rowA = bm + wm * 64 + i * 16 + lr;
#pragma unroll
            for (int hh = 0; hh < 2; hh++) {
                int row = rowA + hh * 8;
                int b = row >> 11;
                int t = row & (Tdim - 1);
                size_t off = ((size_t)(b * Hdim + h) * Tdim + t) * Ddim;
#pragma unroll
                for (int j = 0; j < 4; j++) {
                    float f0 = acc[i][j][hh * 2] * sc;
                    float f1 = acc[i][j][hh * 2 + 1] * sc;
                    *(uint32_t*)&dh[off + d0 + j * 8] = pack2bf16(f0, f1);
                    *(uint32_t*)&dl[off + d0 + j * 8] = pack2bf16_lo(f0, f1);
                }
            }
        }
    }
}

// ---------------------------------------------------------------------------
// Tensor-core causal flash attention; MMA term-passes separated (reuse dist 8).
// ---------------------------------------------------------------------------
__global__ void __launch_bounds__(256) attn_mma() {
    extern __shared__ __align__(16) char sbuf[];
    const uint32_t sb = smem_u32(sbuf);
    const int tid = threadIdx.x;
    const int lane = tid & 31;
    const int w = tid >> 5;
    const int bh = blockIdx.y;
    const int q0 = (int)(gridDim.x - 1 - blockIdx.x) * 128;   // heavy tiles first

    const size_t headoff = (size_t)bh * Tdim * Ddim;
    const int ktmax = (q0 + 127) >> 6;

    const int arow = tid >> 3;
    const int ac8 = (tid & 7) * 8;
    uint4 kh_r[2], kl_r[2], vh_r[2], vl_r[2];

    auto ldkv = [&](int kt) {
        const size_t base = headoff + (size_t)(kt * 64) * Ddim;
#pragma unroll
        for (int p = 0; p < 2; p++) {
            size_t o = base + (size_t)(arow + 32 * p) * Ddim + ac8;
            kh_r[p] = *(const uint4*)&g_kh[o];
            kl_r[p] = *(const uint4*)&g_kl[o];
            vh_r[p] = *(const uint4*)&g_vh[o];
            vl_r[p] = *(const uint4*)&g_vl[o];
        }
    };
    auto stkv = [&](uint32_t stOff) {
#pragma unroll
        for (int p = 0; p < 2; p++) {
            uint32_t so = (uint32_t)((arow + 32 * p) * SROWA + ac8) * 2;
            *(uint4*)(sbuf + stOff + 0 * ATILE + so) = kh_r[p];
            *(uint4*)(sbuf + stOff + 1 * ATILE + so) = kl_r[p];
            *(uint4*)(sbuf + stOff + 2 * ATILE + so) = vh_r[p];
            *(uint4*)(sbuf + stOff + 3 * ATILE + so) = vl_r[p];
        }
    };

    // ---- stage Q (128x64) hi/lo, load A-fragments ----
    ldkv(0);
    {
        const uint4* qgh = (const uint4*)(g_qh + headoff + (size_t)q0 * Ddim);
        const uint4* qgl = (const uint4*)(g_ql + headoff + (size_t)q0 * Ddim);
#pragma unroll
        for (int p = 0; p < 4; p++) {
            int u = p * 256 + tid;
            int row = u >> 3;
            int c8 = (u & 7) * 8;
            uint32_t so = (uint32_t)(row * SROWA + c8) * 2;
            *(uint4*)(sbuf + so) = qgh[u];
            *(uint4*)(sbuf + 18432 + so) = qgl[u];
        }
    }
    __syncthreads();

    uint32_t qh[4][4], ql[4][4];
#pragma unroll
    for (int kk = 0; kk < 4; kk++) {
        uint32_t off = (uint32_t)((16 * w + (lane & 15)) * SROWA + 16 * kk + 8 * (lane >> 4)) * 2;
        ldsm_x4(qh[kk][0], qh[kk][1], qh[kk][2], qh[kk][3], sb + off);
        ldsm_x4(ql[kk][0], ql[kk][1], ql[kk][2], ql[kk][3], sb + 18432 + off);
    }
    __syncthreads();

    stkv(0);
    ldkv(1);
    __syncthreads();

    float oacc[8][4];
#pragma unroll
    for (int j = 0; j < 8; j++)
#pragma unroll
        for (int r = 0; r < 4; r++) oacc[j][r] = 0.f;
    float m1 = -1e30f, m2 = -1e30f, l1 = 0.f, l2 = 0.f;

    const int r1 = q0 + 16 * w + (lane >> 2);
    const int r2 = r1 + 8;

    for (int kt = 0; kt <= ktmax; kt++) {
        const int kbase = kt * 64;
        const int s = kt & 1;
        const uint32_t cur = (uint32_t)s * ASTAGE;
        const uint32_t nxt = (uint32_t)(s ^ 1) * ASTAGE;

        if (kt + 1 <= ktmax) stkv(nxt);
        if (kt + 2 <= ktmax) ldkv(kt + 2);

        const uint32_t oKhi = cur + 0 * ATILE, oKlo = cur + 1 * ATILE;
        const uint32_t oVhi = cur + 2 * ATILE, oVlo = cur + 3 * ATILE;

        // ---- S = Q.K^T (3-term, separated passes) ----
        float sacc[8][4];
#pragma unroll
        for (int j = 0; j < 8; j++)
#pragma unroll
            for (int r = 0; r < 4; r++) sacc[j][r] = 0.f;

#pragma unroll
        for (int kk = 0; kk < 4; kk++) {
            uint32_t bhp[8][2], blp[8][2];
#pragma unroll
            for (int np = 0; np < 4; np++) {
                uint32_t off = (uint32_t)((np * 16 + (lane >> 4) * 8 + (lane & 7)) * SROWA +
                                          ((lane >> 3) & 1) * 8 + 16 * kk) * 2;
                uint32_t t0, t1, t2, t3;
                ldsm_x4(t0, t1, t2, t3, sb + oKhi + off);
                bhp[2 * np][0] = t0; bhp[2 * np][1] = t1;
                bhp[2 * np + 1][0] = t2; bhp[2 * np + 1][1] = t3;
                ldsm_x4(t0, t1, t2, t3, sb + oKlo + off);
                blp[2 * np][0] = t0; blp[2 * np][1] = t1;
                blp[2 * np + 1][0] = t2; blp[2 * np + 1][1] = t3;
            }
#pragma unroll
            for (int j = 0; j < 8; j++) mma16816(sacc[j], qh[kk], bhp[j]);
#pragma unroll
            for (int j = 0; j < 8; j++) mma16816(sacc[j], qh[kk], blp[j]);
#pragma unroll
            for (int j = 0; j < 8; j++) mma16816(sacc[j], ql[kk], bhp[j]);
        }

        // ---- causal mask ----
        if (kbase + 63 > q0 + 16 * w) {
            const int c0 = kbase + 2 * (lane & 3);
#pragma unroll
            for (int j = 0; j < 8; j++) {
                int cj = c0 + 8 * j;
                if (cj > r1)     sacc[j][0] = -1e30f;
                if (cj + 1 > r1) sacc[j][1] = -1e30f;
                if (cj > r2)     sacc[j][2] = -1e30f;
                if (cj + 1 > r2) sacc[j][3] = -1e30f;
            }
        }

        // ---- online softmax ----
        float t1m = -1e30f, t2m = -1e30f;
#pragma unroll
        for (int j = 0; j < 8; j++) {
            t1m = fmaxf(t1m, fmaxf(sacc[j][0], sacc[j][1]));
            t2m = fmaxf(t2m, fmaxf(sacc[j][2], sacc[j][3]));
        }
        t1m = fmaxf(t1m, __shfl_xor_sync(0xffffffffu, t1m, 1));
        t1m = fmaxf(t1m, __shfl_xor_sync(0xffffffffu, t1m, 2));
        t2m = fmaxf(t2m, __shfl_xor_sync(0xffffffffu, t2m, 1));
        t2m = fmaxf(t2m, __shfl_xor_sync(0xffffffffu, t2m, 2));

        float nm1 = fmaxf(m1, t1m), nm2 = fmaxf(m2, t2m);
        float corr1 = __expf(m1 - nm1), corr2 = __expf(m2 - nm2);
        m1 = nm1; m2 = nm2;

        float s1 = 0.f, s2 = 0.f;
#pragma unroll
        for (int j = 0; j < 8; j++) {
            sacc[j][0] = __expf(sacc[j][0] - m1);
            sacc[j][1] = __expf(sacc[j][1] - m1);
            sacc[j][2] = __expf(sacc[j][2] - m2);
            sacc[j][3] = __expf(sacc[j][3] - m2);
            s1 += sacc[j][0] + sacc[j][1];
            s2 += sacc[j][2] + sacc[j][3];
        }
        s1 += __shfl_xor_sync(0xffffffffu, s1, 1);
        s1 += __shfl_xor_sync(0xffffffffu, s1, 2);
        s2 += __shfl_xor_sync(0xffffffffu, s2, 1);
        s2 += __shfl_xor_sync(0xffffffffu, s2, 2);
        l1 = l1 * corr1 + s1;
        l2 = l2 * corr2 + s2;

        // pack P into A-fragments (hi/lo)
        uint32_t ph[4][4], pl[4][4];
#pragma unroll
        for (int kk = 0; kk < 4; kk++) {
            int j0 = 2 * kk, j1 = 2 * kk + 1;
            ph[kk][0] = pack2bf16(sacc[j0][0], sacc[j0][1]);
            ph[kk][1] = pack2bf16(sacc[j0][2], sacc[j0][3]);
            ph[kk][2] = pack2bf16(sacc[j1][0], sacc[j1][1]);
            ph[kk][3] = pack2bf16(sacc[j1][2], sacc[j1][3]);
            pl[kk][0] = pack2bf16_lo(sacc[j0][0], sacc[j0][1]);
            pl[kk][1] = pack2bf16_lo(sacc[j0][2], sacc[j0][3]);
            pl[kk][2] = pack2bf16_lo(sacc[j1][0], sacc[j1][1]);
            pl[kk][3] = pack2bf16_lo(sacc[j1][2], sacc[j1][3]);
        }

        // rescale O
#pragma unroll
        for (int j = 0; j < 8; j++) {
            oacc[j][0] *= corr1; oacc[j][1] *= corr1;
            oacc[j][2] *= corr2; oacc[j][3] *= corr2;
        }

        // ---- O += P.V (3-term, separated passes) ----
#pragma unroll
        for (int kk = 0; kk < 4; kk++) {
            uint32_t vbh[8][2], vbl[8][2];
#pragma unroll
            for (int np = 0; np < 4; np++) {
                uint32_t off = (uint32_t)((16 * kk + (lane & 15)) * SROWA +
                                          16 * np + 8 * (lane >> 4)) * 2;
                uint32_t t0, t1, t2, t3;
                ldsm_x4_t(t0, t1, t2, t3, sb + oVhi + off);
                vbh[2 * np][0] = t0; vbh[2 * np][1] = t1;
                vbh[2 * np + 1][0] = t2; vbh[2 * np + 1][1] = t3;
                ldsm_x4_t(t0, t1, t2, t3, sb + oVlo + off);
                vbl[2 * np][0] = t0; vbl[2 * np][1] = t1;
                vbl[2 * np + 1][0] = t2; vbl[2 * np + 1][1] = t3;
            }
#pragma unroll
            for (int j = 0; j < 8; j++) mma16816(oacc[j], ph[kk], vbh[j]);
#pragma unroll
            for (int j = 0; j < 8; j++) mma16816(oacc[j], ph[kk], vbl[j]);
#pragma unroll
            for (int j = 0; j < 8; j++) mma16816(oacc[j], pl[kk], vbh[j]);
        }
        __syncthreads();
    }

    // ---- epilogue: y[B,T,H,D] as bf16 hi/lo ----
    float inv1 = 1.0f / l1, inv2 = 1.0f / l2;
    int b = bh >> 4, h = bh & 15;
    size_t off1 = ((size_t)(b * Tdim + r1) * Hdim + h) * Ddim;
    size_t off2 = ((size_t)(b * Tdim + r2) * Hdim + h) * Ddim;
    int d0 = 2 * (lane & 3);
#pragma unroll
    for (int j = 0; j < 8; j++) {
        float a0 = oacc[j][0] * inv1, a1 = oacc[j][1] * inv1;
        float b0 = oacc[j][2] * inv2, b1 = oacc[j][3] * inv2;
        *(uint32_t*)&g_yh[off1 + 8 * j + d0] = pack2bf16(a0, a1);
        *(uint32_t*)&g_yl[off1 + 8 * j + d0] = pack2bf16_lo(a0, a1);
        *(uint32_t*)&g_yh[off2 + 8 * j + d0] = pack2bf16(b0, b1);
        *(uint32_t*)&g_yl[off2 + 8 * j + d0] = pack2bf16_lo(b0, b1);
    }
}

// ---------------------------------------------------------------------------
extern "C" void kernel_launch(void* const* d_in, const int* in_sizes, int n_in,
                              void* d_out, int out_size) {
    const float* x = (const float*)d_in[0];        // [B,T,C]
    const float* w_attn = (const float*)d_in[1];   // [3C,C]
    const float* w_proj = (const float*)d_in[2];   // [C,C]
    float* out = (float*)d_out;                    // [B,T,C]

    __nv_bfloat16 *xh, *xl, *wah, *wal, *wph, *wpl, *yh, *yl;
    cudaGetSymbolAddress((void**)&xh, g_xh);
    cudaGetSymbolAddress((void**)&xl, g_xl);
    cudaGetSymbolAddress((void**)&wah, g_wah);
    cudaGetSymbolAddress((void**)&wal, g_wal);
    cudaGetSymbolAddress((void**)&wph, g_wph);
    cudaGetSymbolAddress((void**)&wpl, g_wpl);
    cudaGetSymbolAddress((void**)&yh, g_yh);
    cudaGetSymbolAddress((void**)&yl, g_yl);

    cudaFuncSetAttribute(gemm_bf<0>, cudaFuncAttributeMaxDynamicSharedMemorySize, GSMEM);
    cudaFuncSetAttribute(gemm_bf<1>, cudaFuncAttributeMaxDynamicSharedMemorySize, GSMEM);
    cudaFuncSetAttribute(attn_mma, cudaFuncAttributeMaxDynamicSharedMemorySize, ASMEM);

    const int nx4 = Mrows * Cdim / 4;
    const int nwa4 = 3 * Cdim * Cdim / 4;
    const int nwp4 = Cdim * Cdim / 4;
    split2_kernel<<<(nx4 + 255) / 256, 256>>>(x, xh, xl, nx4);
    split2_kernel<<<(nwa4 + 255) / 256, 256>>>(w_attn, wah, wal, nwa4);
    split2_kernel<<<(nwp4 + 255) / 256, 256>>>(w_proj, wph, wpl, nwp4);

    dim3 g1(3 * Cdim / 128, Mrows / 128);   // (24, 32)
    gemm_bf<1><<<g1, 256, GSMEM>>>(xh, xl, wah, wal, nullptr, Mrows, 3 * Cdim, Cdim);

    dim3 ga(Tdim / 128, Bdim * Hdim);       // (16, 32)
    attn_mma<<<ga, 256, ASMEM>>>();

    dim3 g2(Cdim / 128, Mrows / 128);       // (8, 32)
    gemm_bf<0><<<g2, 256, GSMEM>>>(yh, yl, wph, wpl, out, Mrows, Cdim, Cdim);
}

// round 9
// speedup vs baseline: 1.0930x; 1.0739x over previous
#include <cuda_runtime.h>
#include <cuda_bf16.h>
#include <cstdint>
#include <math.h>

// Problem constants
#define Bdim 2
#define Tdim 2048
#define Cdim 1024
#define Hdim 16
#define Ddim 64
#define Mrows (Bdim * Tdim)   // 4096

// Device-global scratch, all bf16 hi/lo pairs (allocation-free)
__device__ __align__(16) __nv_bfloat16 g_xh[(size_t)Mrows * Cdim];
__device__ __align__(16) __nv_bfloat16 g_xl[(size_t)Mrows * Cdim];
__device__ __align__(16) __nv_bfloat16 g_wah[(size_t)3 * Cdim * Cdim];
__device__ __align__(16) __nv_bfloat16 g_wal[(size_t)3 * Cdim * Cdim];
__device__ __align__(16) __nv_bfloat16 g_wph[(size_t)Cdim * Cdim];
__device__ __align__(16) __nv_bfloat16 g_wpl[(size_t)Cdim * Cdim];
__device__ __align__(16) __nv_bfloat16 g_qh[(size_t)Bdim * Hdim * Tdim * Ddim];
__device__ __align__(16) __nv_bfloat16 g_ql[(size_t)Bdim * Hdim * Tdim * Ddim];
__device__ __align__(16) __nv_bfloat16 g_kh[(size_t)Bdim * Hdim * Tdim * Ddim];
__device__ __align__(16) __nv_bfloat16 g_kl[(size_t)Bdim * Hdim * Tdim * Ddim];
__device__ __align__(16) __nv_bfloat16 g_vh[(size_t)Bdim * Hdim * Tdim * Ddim];
__device__ __align__(16) __nv_bfloat16 g_vl[(size_t)Bdim * Hdim * Tdim * Ddim];
__device__ __align__(16) __nv_bfloat16 g_yh[(size_t)Bdim * Tdim * Cdim];
__device__ __align__(16) __nv_bfloat16 g_yl[(size_t)Bdim * Tdim * Cdim];

// ---------------------------------------------------------------------------
// Helpers
// ---------------------------------------------------------------------------
__device__ __forceinline__ uint32_t smem_u32(const void* p) {
    uint32_t a;
    asm("{ .reg .u64 t; cvta.to.shared.u64 t, %1; cvt.u32.u64 %0, t; }" : "=r"(a) : "l"(p));
    return a;
}

__device__ __forceinline__ void ldsm_x4(uint32_t& r0, uint32_t& r1, uint32_t& r2, uint32_t& r3,
                                        uint32_t addr) {
    asm volatile("ldmatrix.sync.aligned.m8n8.x4.shared.b16 {%0,%1,%2,%3}, [%4];"
                 : "=r"(r0), "=r"(r1), "=r"(r2), "=r"(r3) : "r"(addr));
}
__device__ __forceinline__ void ldsm_x4_t(uint32_t& r0, uint32_t& r1, uint32_t& r2, uint32_t& r3,
                                          uint32_t addr) {
    asm volatile("ldmatrix.sync.aligned.m8n8.x4.trans.shared.b16 {%0,%1,%2,%3}, [%4];"
                 : "=r"(r0), "=r"(r1), "=r"(r2), "=r"(r3) : "r"(addr));
}

__device__ __forceinline__ void mma16816(float* c, const uint32_t* a, const uint32_t* b) {
    asm volatile(
        "mma.sync.aligned.m16n8k16.row.col.f32.bf16.bf16.f32 "
        "{%0,%1,%2,%3}, {%4,%5,%6,%7}, {%8,%9}, {%0,%1,%2,%3};"
        : "+f"(c[0]), "+f"(c[1]), "+f"(c[2]), "+f"(c[3])
        : "r"(a[0]), "r"(a[1]), "r"(a[2]), "r"(a[3]), "r"(b[0]), "r"(b[1]));
}

__device__ __forceinline__ uint32_t pack2bf16(float x, float y) {
    __nv_bfloat162 t;
    t.x = __float2bfloat16_rn(x);
    t.y = __float2bfloat16_rn(y);
    return *reinterpret_cast<uint32_t*>(&t);
}
__device__ __forceinline__ uint32_t pack2bf16_lo(float x, float y) {
    float hx = __bfloat162float(__float2bfloat16_rn(x));
    float hy = __bfloat162float(__float2bfloat16_rn(y));
    __nv_bfloat162 t;
    t.x = __float2bfloat16_rn(x - hx);
    t.y = __float2bfloat16_rn(y - hy);
    return *reinterpret_cast<uint32_t*>(&t);
}

// cp.async (LDGSTS): global -> smem, 16B, L1-bypass (.cg)
#define CPASYNC(saddr, gptr) \
    asm volatile("cp.async.cg.shared.global [%0], [%1], 16;" :: "r"(saddr), "l"(gptr))
#define CPCOMMIT() asm volatile("cp.async.commit_group;" ::: "memory")
#define CPWAIT1() asm volatile("cp.async.wait_group 1;" ::: "memory")
#define CPWAIT0() asm volatile("cp.async.wait_group 0;" ::: "memory")

#define SROW 40    // GEMM smem row stride in bf16 (80B; 16B-aligned, conflict-free ldmatrix)
#define SROWA 72   // Attention smem row stride in bf16

// GEMM smem: per stage Ahi/Alo (128x32) + Bhi/Blo (256x32)
#define GT_A 10240             // 128*40*2
#define GT_B 20480             // 256*40*2
#define GSTAGE2 (2 * GT_A + 2 * GT_B)   // 61440
#define GSMEM2 (2 * GSTAGE2)            // 122880

// Attention smem: 2 stages, each Khi/Klo/Vhi/Vlo of 64*SROWA bf16
#define ATILE 9216             // 64*72*2
#define ASTAGE 36864           // 4*ATILE
#define ASMEM (2 * ASTAGE)     // 73728

// ---------------------------------------------------------------------------
// Pre-pass: split fp32 array into bf16 hi/lo arrays. n4 = n/4.
// ---------------------------------------------------------------------------
__global__ void split2_kernel(const float* __restrict__ src, __nv_bfloat16* __restrict__ hi,
                              __nv_bfloat16* __restrict__ lo, int n4) {
    int i = blockIdx.x * blockDim.x + threadIdx.x;
    if (i < n4) {
        float4 v = ((const float4*)src)[i];
        ((uint2*)hi)[i] = make_uint2(pack2bf16(v.x, v.y), pack2bf16(v.z, v.w));
        ((uint2*)lo)[i] = make_uint2(pack2bf16_lo(v.x, v.y), pack2bf16_lo(v.z, v.w));
    }
}

// ---------------------------------------------------------------------------
// Tensor-core GEMM (NT), bf16 hi/lo 3-term, CTA tile 128x256, warp tile 64x64,
// cp.async double-buffered. C[M,N] = A[M,K] @ B[N,K]^T.
// MODE 0: fp32 store. MODE 1: scatter bf16 hi/lo q/k/v [B,H,T,D], q*0.125.
// ---------------------------------------------------------------------------
template <int MODE>
__global__ void __launch_bounds__(256, 1) gemm_bf(const __nv_bfloat16* __restrict__ Ah,
                                                  const __nv_bfloat16* __restrict__ Al,
                                                  const __nv_bfloat16* __restrict__ Bh,
                                                  const __nv_bfloat16* __restrict__ Bl,
                                                  float* __restrict__ Cout,
                                                  int M, int N, int K) {
    extern __shared__ __align__(16) char smem[];
    const uint32_t sb = smem_u32(smem);

    const int tid = threadIdx.x;
    const int lane = tid & 31;
    const int wid = tid >> 5;
    const int wm = wid >> 2;        // 0..1  (64 rows)
    const int wn = wid & 3;         // 0..3  (64 cols)
    const int bm = blockIdx.y * 128;
    const int bn = blockIdx.x * 256;

    const __nv_bfloat16* Agh = Ah + (size_t)bm * K;
    const __nv_bfloat16* Agl = Al + (size_t)bm * K;
    const __nv_bfloat16* Bgh = Bh + (size_t)bn * K;
    const __nv_bfloat16* Bgl = Bl + (size_t)bn * K;

    const int nch = K / 32;

    // cp.async issue of one 32-wide K chunk into stage st
    auto issue = [&](int ch, uint32_t st) {
        const int koff = ch * 32;
#pragma unroll
        for (int p = 0; p < 2; p++) {          // A: 128 rows x 4 segs
            int u = tid + 256 * p;
            int row = u >> 2, seg = u & 3;
            uint32_t so = sb + st + (uint32_t)(row * 80 + seg * 16);
            size_t go = (size_t)row * K + koff + seg * 8;
            CPASYNC(so, Agh + go);
            CPASYNC(so + GT_A, Agl + go);
        }
#pragma unroll
        for (int p = 0; p < 4; p++) {          // B: 256 rows x 4 segs
            int u = tid + 256 * p;
            int row = u >> 2, seg = u & 3;
            uint32_t so = sb + st + 2 * GT_A + (uint32_t)(row * 80 + seg * 16);
            size_t go = (size_t)row * K + koff + seg * 8;
            CPASYNC(so, Bgh + go);
            CPASYNC(so + GT_B, Bgl + go);
        }
    };

    float acc[4][8][4];
#pragma unroll
    for (int i = 0; i < 4; i++)
#pragma unroll
        for (int j = 0; j < 8; j++)
#pragma unroll
            for (int r = 0; r < 4; r++) acc[i][j][r] = 0.f;

    const uint32_t aOff = (uint32_t)((wm * 64 + (lane & 15)) * SROW + (lane >> 4) * 8) * 2;
    const uint32_t bOff = (uint32_t)((wn * 64 + (lane >> 4) * 8 + (lane & 7)) * SROW +
                                     ((lane >> 3) & 1) * 8) * 2;

    issue(0, 0); CPCOMMIT();
    issue(1, GSTAGE2); CPCOMMIT();
    CPWAIT1();
    __syncthreads();

    for (int ch = 0; ch < nch; ch++) {
        const uint32_t cur = (uint32_t)(ch & 1) * GSTAGE2;
        const uint32_t aHiB = sb + cur;
        const uint32_t aLoB = sb + cur + GT_A;
        const uint32_t bHiB = sb + cur + 2 * GT_A;
        const uint32_t bLoB = sb + cur + 2 * GT_A + GT_B;

#pragma unroll
        for (int kk = 0; kk < 2; kk++) {
            const uint32_t kByte = (uint32_t)(kk * 16 * 2);
            uint32_t bh[8][2], bl[8][2];
#pragma unroll
            for (int jp = 0; jp < 4; jp++) {
                uint32_t o = bOff + kByte + (uint32_t)(jp * 16 * SROW * 2);
                uint32_t t0, t1, t2, t3;
                ldsm_x4(t0, t1, t2, t3, bHiB + o);
                bh[2 * jp][0] = t0; bh[2 * jp][1] = t1;
                bh[2 * jp + 1][0] = t2; bh[2 * jp + 1][1] = t3;
                ldsm_x4(t0, t1, t2, t3, bLoB + o);
                bl[2 * jp][0] = t0; bl[2 * jp][1] = t1;
                bl[2 * jp + 1][0] = t2; bl[2 * jp + 1][1] = t3;
            }
            uint32_t af[4][4];
#pragma unroll
            for (int i = 0; i < 4; i++)
                ldsm_x4(af[i][0], af[i][1], af[i][2], af[i][3],
                        aHiB + aOff + kByte + (uint32_t)(i * 16 * SROW * 2));
            // pass 1: Ahi*Bhi
#pragma unroll
            for (int i = 0; i < 4; i++)
#pragma unroll
                for (int j = 0; j < 8; j++) mma16816(acc[i][j], af[i], bh[j]);
            // pass 2: Ahi*Blo
#pragma unroll
            for (int i = 0; i < 4; i++)
#pragma unroll
                for (int j = 0; j < 8; j++) mma16816(acc[i][j], af[i], bl[j]);
            // reload A lo
#pragma unroll
            for (int i = 0; i < 4; i++)
                ldsm_x4(af[i][0], af[i][1], af[i][2], af[i][3],
                        aLoB + aOff + kByte + (uint32_t)(i * 16 * SROW * 2));
            // pass 3: Alo*Bhi
#pragma unroll
            for (int i = 0; i < 4; i++)
#pragma unroll
                for (int j = 0; j < 8; j++) mma16816(acc[i][j], af[i], bh[j]);
        }
        __syncthreads();
        if (ch + 1 < nch) {
            if (ch + 2 < nch) { issue(ch + 2, cur); CPCOMMIT(); CPWAIT1(); }
            else { CPWAIT0(); }
            __syncthreads();
        }
    }

    const int lr = lane >> 2;
    const int lc = (lane & 3) * 2;

    if (MODE == 0) {
#pragma unroll
        for (int i = 0; i < 4; i++) {
            int rowA = bm + wm * 64 + i * 16 + lr;
#pragma unroll
            for (int j = 0; j < 8; j++) {
                int col = bn + wn * 64 + j * 8 + lc;
                *(float2*)&Cout[(size_t)rowA * N + col] = make_float2(acc[i][j][0], acc[i][j][1]);
                *(float2*)&Cout[(size_t)(rowA + 8) * N + col] = make_float2(acc[i][j][2], acc[i][j][3]);
            }
        }
    } else {
        // warp covers exactly one head's 64 cols
        int col0 = bn + wn * 64;
        int sdx = col0 >> 10;
        int h = (col0 & (Cdim - 1)) >> 6;
        __nv_bfloat16* dh = (sdx == 0) ? g_qh : (sdx == 1) ? g_kh : g_vh;
        __nv_bfloat16* dl = (sdx == 0) ? g_ql : (sdx == 1) ? g_kl : g_vl;
        float sc = (sdx == 0) ? 0.125f : 1.0f;
#pragma unroll
        for (int i = 0; i < 4; i++) {
            int rowA = bm + wm * 64 + i * 16 + lr;
#pragma unroll
            for (int hh = 0; hh < 2; hh++) {
                int row = rowA + hh * 8;
                int b = row >> 11;
                int t = row & (Tdim - 1);
                size_t off = ((size_t)(b * Hdim + h) * Tdim + t) * Ddim + lc;
#pragma unroll
                for (int j = 0; j < 8; j++) {
                    float f0 = acc[i][j][hh * 2] * sc;
                    float f1 = acc[i][j][hh * 2 + 1] * sc;
                    *(uint32_t*)&dh[off + j * 8] = pack2bf16(f0, f1);
                    *(uint32_t*)&dl[off + j * 8] = pack2bf16_lo(f0, f1);
                }
            }
        }
    }
}

// ---------------------------------------------------------------------------
// Tensor-core causal flash attention (unchanged from best-known-good).
// ---------------------------------------------------------------------------
__global__ void __launch_bounds__(256) attn_mma() {
    extern __shared__ __align__(16) char sbuf[];
    const uint32_t sb = smem_u32(sbuf);
    const int tid = threadIdx.x;
    const int lane = tid & 31;
    const int w = tid >> 5;
    const int bh = blockIdx.y;
    const int q0 = (int)(gridDim.x - 1 - blockIdx.x) * 128;

    const size_t headoff = (size_t)bh * Tdim * Ddim;
    const int ktmax = (q0 + 127) >> 6;

    const int arow = tid >> 3;
    const int ac8 = (tid & 7) * 8;
    uint4 kh_r[2], kl_r[2], vh_r[2], vl_r[2];

    auto ldkv = [&](int kt) {
        const size_t base = headoff + (size_t)(kt * 64) * Ddim;
#pragma unroll
        for (int p = 0; p < 2; p++) {
            size_t o = base + (size_t)(arow + 32 * p) * Ddim + ac8;
            kh_r[p] = *(const uint4*)&g_kh[o];
            kl_r[p] = *(const uint4*)&g_kl[o];
            vh_r[p] = *(const uint4*)&g_vh[o];
            vl_r[p] = *(const uint4*)&g_vl[o];
        }
    };
    auto stkv = [&](uint32_t stOff) {
#pragma unroll
        for (int p = 0; p < 2; p++) {
            uint32_t so = (uint32_t)((arow + 32 * p) * SROWA + ac8) * 2;
            *(uint4*)(sbuf + stOff + 0 * ATILE + so) = kh_r[p];
            *(uint4*)(sbuf + stOff + 1 * ATILE + so) = kl_r[p];
            *(uint4*)(sbuf + stOff + 2 * ATILE + so) = vh_r[p];
            *(uint4*)(sbuf + stOff + 3 * ATILE + so) = vl_r[p];
        }
    };

    ldkv(0);
    {
        const uint4* qgh = (const uint4*)(g_qh + headoff + (size_t)q0 * Ddim);
        const uint4* qgl = (const uint4*)(g_ql + headoff + (size_t)q0 * Ddim);
#pragma unroll
        for (int p = 0; p < 4; p++) {
            int u = p * 256 + tid;
            int row = u >> 3;
            int c8 = (u & 7) * 8;
            uint32_t so = (uint32_t)(row * SROWA + c8) * 2;
            *(uint4*)(sbuf + so) = qgh[u];
            *(uint4*)(sbuf + 18432 + so) = qgl[u];
        }
    }
    __syncthreads();

    uint32_t qh[4][4], ql[4][4];
#pragma unroll
    for (int kk = 0; kk < 4; kk++) {
        uint32_t off = (uint32_t)((16 * w + (lane & 15)) * SROWA + 16 * kk + 8 * (lane >> 4)) * 2;
        ldsm_x4(qh[kk][0], qh[kk][1], qh[kk][2], qh[kk][3], sb + off);
        ldsm_x4(ql[kk][0], ql[kk][1], ql[kk][2], ql[kk][3], sb + 18432 + off);
    }
    __syncthreads();

    stkv(0);
    ldkv(1);
    __syncthreads();

    float oacc[8][4];
#pragma unroll
    for (int j = 0; j < 8; j++)
#pragma unroll
        for (int r = 0; r < 4; r++) oacc[j][r] = 0.f;
    float m1 = -1e30f, m2 = -1e30f, l1 = 0.f, l2 = 0.f;

    const int r1 = q0 + 16 * w + (lane >> 2);
    const int r2 = r1 + 8;

    for (int kt = 0; kt <= ktmax; kt++) {
        const int kbase = kt * 64;
        const int s = kt & 1;
        const uint32_t cur = (uint32_t)s * ASTAGE;
        const uint32_t nxt = (uint32_t)(s ^ 1) * ASTAGE;

        if (kt + 1 <= ktmax) stkv(nxt);
        if (kt + 2 <= ktmax) ldkv(kt + 2);

        const uint32_t oKhi = cur + 0 * ATILE, oKlo = cur + 1 * ATILE;
        const uint32_t oVhi = cur + 2 * ATILE, oVlo = cur + 3 * ATILE;

        float sacc[8][4];
#pragma unroll
        for (int j = 0; j < 8; j++)
#pragma unroll
            for (int r = 0; r < 4; r++) sacc[j][r] = 0.f;

#pragma unroll
        for (int kk = 0; kk < 4; kk++) {
            uint32_t bhp[8][2], blp[8][2];
#pragma unroll
            for (int np = 0; np < 4; np++) {
                uint32_t off = (uint32_t)((np * 16 + (lane >> 4) * 8 + (lane & 7)) * SROWA +
                                          ((lane >> 3) & 1) * 8 + 16 * kk) * 2;
                uint32_t t0, t1, t2, t3;
                ldsm_x4(t0, t1, t2, t3, sb + oKhi + off);
                bhp[2 * np][0] = t0; bhp[2 * np][1] = t1;
                bhp[2 * np + 1][0] = t2; bhp[2 * np + 1][1] = t3;
                ldsm_x4(t0, t1, t2, t3, sb + oKlo + off);
                blp[2 * np][0] = t0; blp[2 * np][1] = t1;
                blp[2 * np + 1][0] = t2; blp[2 * np + 1][1] = t3;
            }
#pragma unroll
            for (int j = 0; j < 8; j++) mma16816(sacc[j], qh[kk], bhp[j]);
#pragma unroll
            for (int j = 0; j < 8; j++) mma16816(sacc[j], qh[kk], blp[j]);
#pragma unroll
            for (int j = 0; j < 8; j++) mma16816(sacc[j], ql[kk], bhp[j]);
        }

        if (kbase + 63 > q0 + 16 * w) {
            const int c0 = kbase + 2 * (lane & 3);
#pragma unroll
            for (int j = 0; j < 8; j++) {
                int cj = c0 + 8 * j;
                if (cj > r1)     sacc[j][0] = -1e30f;
                if (cj + 1 > r1) sacc[j][1] = -1e30f;
                if (cj > r2)     sacc[j][2] = -1e30f;
                if (cj + 1 > r2) sacc[j][3] = -1e30f;
            }
        }

        float t1m = -1e30f, t2m = -1e30f;
#pragma unroll
        for (int j = 0; j < 8; j++) {
            t1m = fmaxf(t1m, fmaxf(sacc[j][0], sacc[j][1]));
            t2m = fmaxf(t2m, fmaxf(sacc[j][2], sacc[j][3]));
        }
        t1m = fmaxf(t1m, __shfl_xor_sync(0xffffffffu, t1m, 1));
        t1m = fmaxf(t1m, __shfl_xor_sync(0xffffffffu, t1m, 2));
        t2m = fmaxf(t2m, __shfl_xor_sync(0xffffffffu, t2m, 1));
        t2m = fmaxf(t2m, __shfl_xor_sync(0xffffffffu, t2m, 2));

        float nm1 = fmaxf(m1, t1m), nm2 = fmaxf(m2, t2m);
        float corr1 = __expf(m1 - nm1), corr2 = __expf(m2 - nm2);
        m1 = nm1; m2 = nm2;

        float s1 = 0.f, s2 = 0.f;
#pragma unroll
        for (int j = 0; j < 8; j++) {
            sacc[j][0] = __expf(sacc[j][0] - m1);
            sacc[j][1] = __expf(sacc[j][1] - m1);
            sacc[j][2] = __expf(sacc[j][2] - m2);
            sacc[j][3] = __expf(sacc[j][3] - m2);
            s1 += sacc[j][0] + sacc[j][1];
            s2 += sacc[j][2] + sacc[j][3];
        }
        s1 += __shfl_xor_sync(0xffffffffu, s1, 1);
        s1 += __shfl_xor_sync(0xffffffffu, s1, 2);
        s2 += __shfl_xor_sync(0xffffffffu, s2, 1);
        s2 += __shfl_xor_sync(0xffffffffu, s2, 2);
        l1 = l1 * corr1 + s1;
        l2 = l2 * corr2 + s2;

        uint32_t ph[4][4], pl[4][4];
#pragma unroll
        for (int kk = 0; kk < 4; kk++) {
            int j0 = 2 * kk, j1 = 2 * kk + 1;
            ph[kk][0] = pack2bf16(sacc[j0][0], sacc[j0][1]);
            ph[kk][1] = pack2bf16(sacc[j0][2], sacc[j0][3]);
            ph[kk][2] = pack2bf16(sacc[j1][0], sacc[j1][1]);
            ph[kk][3] = pack2bf16(sacc[j1][2], sacc[j1][3]);
            pl[kk][0] = pack2bf16_lo(sacc[j0][0], sacc[j0][1]);
            pl[kk][1] = pack2bf16_lo(sacc[j0][2], sacc[j0][3]);
            pl[kk][2] = pack2bf16_lo(sacc[j1][0], sacc[j1][1]);
            pl[kk][3] = pack2bf16_lo(sacc[j1][2], sacc[j1][3]);
        }

#pragma unroll
        for (int j = 0; j < 8; j++) {
            oacc[j][0] *= corr1; oacc[j][1] *= corr1;
            oacc[j][2] *= corr2; oacc[j][3] *= corr2;
        }

#pragma unroll
        for (int kk = 0; kk < 4; kk++) {
            uint32_t vbh[8][2], vbl[8][2];
#pragma unroll
            for (int np = 0; np < 4; np++) {
                uint32_t off = (uint32_t)((16 * kk + (lane & 15)) * SROWA +
                                          16 * np + 8 * (lane >> 4)) * 2;
                uint32_t t0, t1, t2, t3;
                ldsm_x4_t(t0, t1, t2, t3, sb + oVhi + off);
                vbh[2 * np][0] = t0; vbh[2 * np][1] = t1;
                vbh[2 * np + 1][0] = t2; vbh[2 * np + 1][1] = t3;
                ldsm_x4_t(t0, t1, t2, t3, sb + oVlo + off);
                vbl[2 * np][0] = t0; vbl[2 * np][1] = t1;
                vbl[2 * np + 1][0] = t2; vbl[2 * np + 1][1] = t3;
            }
#pragma unroll
            for (int j = 0; j < 8; j++) mma16816(oacc[j], ph[kk], vbh[j]);
#pragma unroll
            for (int j = 0; j < 8; j++) mma16816(oacc[j], ph[kk], vbl[j]);
#pragma unroll
            for (int j = 0; j < 8; j++) mma16816(oacc[j], pl[kk], vbh[j]);
        }
        __syncthreads();
    }

    float inv1 = 1.0f / l1, inv2 = 1.0f / l2;
    int b = bh >> 4, h = bh & 15;
    size_t off1 = ((size_t)(b * Tdim + r1) * Hdim + h) * Ddim;
    size_t off2 = ((size_t)(b * Tdim + r2) * Hdim + h) * Ddim;
    int d0 = 2 * (lane & 3);
#pragma unroll
    for (int j = 0; j < 8; j++) {
        float a0 = oacc[j][0] * inv1, a1 = oacc[j][1] * inv1;
        float b0 = oacc[j][2] * inv2, b1 = oacc[j][3] * inv2;
        *(uint32_t*)&g_yh[off1 + 8 * j + d0] = pack2bf16(a0, a1);
        *(uint32_t*)&g_yl[off1 + 8 * j + d0] = pack2bf16_lo(a0, a1);
        *(uint32_t*)&g_yh[off2 + 8 * j + d0] = pack2bf16(b0, b1);
        *(uint32_t*)&g_yl[off2 + 8 * j + d0] = pack2bf16_lo(b0, b1);
    }
}

// ---------------------------------------------------------------------------
extern "C" void kernel_launch(void* const* d_in, const int* in_sizes, int n_in,
                              void* d_out, int out_size) {
    const float* x = (const float*)d_in[0];
    const float* w_attn = (const float*)d_in[1];
    const float* w_proj = (const float*)d_in[2];
    float* out = (float*)d_out;

    __nv_bfloat16 *xh, *xl, *wah, *wal, *wph, *wpl, *yh, *yl;
    cudaGetSymbolAddress((void**)&xh, g_xh);
    cudaGetSymbolAddress((void**)&xl, g_xl);
    cudaGetSymbolAddress((void**)&wah, g_wah);
    cudaGetSymbolAddress((void**)&wal, g_wal);
    cudaGetSymbolAddress((void**)&wph, g_wph);
    cudaGetSymbolAddress((void**)&wpl, g_wpl);
    cudaGetSymbolAddress((void**)&yh, g_yh);
    cudaGetSymbolAddress((void**)&yl, g_yl);

    cudaFuncSetAttribute(gemm_bf<0>, cudaFuncAttributeMaxDynamicSharedMemorySize, GSMEM2);
    cudaFuncSetAttribute(gemm_bf<1>, cudaFuncAttributeMaxDynamicSharedMemorySize, GSMEM2);
    cudaFuncSetAttribute(attn_mma, cudaFuncAttributeMaxDynamicSharedMemorySize, ASMEM);

    const int nx4 = Mrows * Cdim / 4;
    const int nwa4 = 3 * Cdim * Cdim / 4;
    const int nwp4 = Cdim * Cdim / 4;
    split2_kernel<<<(nx4 + 255) / 256, 256>>>(x, xh, xl, nx4);
    split2_kernel<<<(nwa4 + 255) / 256, 256>>>(w_attn, wah, wal, nwa4);
    split2_kernel<<<(nwp4 + 255) / 256, 256>>>(w_proj, wph, wpl, nwp4);

    // GEMM1: qkv = x @ w_attn^T  (CTA tile 128x256)
    dim3 g1(3 * Cdim / 256, Mrows / 128);   // (12, 32)
    gemm_bf<1><<<g1, 256, GSMEM2>>>(xh, xl, wah, wal, nullptr, Mrows, 3 * Cdim, Cdim);

    // Attention
    dim3 ga(Tdim / 128, Bdim * Hdim);       // (16, 32)
    attn_mma<<<ga, 256, ASMEM>>>();

    // GEMM2: out = y @ w_proj^T
    dim3 g2(Cdim / 256, Mrows / 128);       // (4, 32)
    gemm_bf<0><<<g2, 256, GSMEM2>>>(yh, yl, wph, wpl, out, Mrows, Cdim, Cdim);
}

// round 10
// speedup vs baseline: 1.2807x; 1.1718x over previous
#include <cuda_runtime.h>
#include <cuda_bf16.h>
#include <cuda_fp16.h>
#include <cstdint>
#include <math.h>

// Problem constants
#define Bdim 2
#define Tdim 2048
#define Cdim 1024
#define Hdim 16
#define Ddim 64
#define Mrows (Bdim * Tdim)   // 4096

// Device-global scratch (allocation-free)
// bf16 path (x, w_attn qk-rows, q, k)
__device__ __align__(16) __nv_bfloat16 g_xh[(size_t)Mrows * Cdim];
__device__ __align__(16) __nv_bfloat16 g_xl[(size_t)Mrows * Cdim];
__device__ __align__(16) __nv_bfloat16 g_wah[(size_t)2 * Cdim * Cdim];
__device__ __align__(16) __nv_bfloat16 g_wal[(size_t)2 * Cdim * Cdim];
__device__ __align__(16) __nv_bfloat16 g_qh[(size_t)Bdim * Hdim * Tdim * Ddim];
__device__ __align__(16) __nv_bfloat16 g_ql[(size_t)Bdim * Hdim * Tdim * Ddim];
__device__ __align__(16) __nv_bfloat16 g_kh[(size_t)Bdim * Hdim * Tdim * Ddim];
__device__ __align__(16) __nv_bfloat16 g_kl[(size_t)Bdim * Hdim * Tdim * Ddim];
// fp16 path (x, w_attn v-rows, w_proj, v, y)
__device__ __align__(16) __half g_xh2[(size_t)Mrows * Cdim];
__device__ __align__(16) __half g_xl2[(size_t)Mrows * Cdim];
__device__ __align__(16) __half g_wv[(size_t)Cdim * Cdim];
__device__ __align__(16) __half g_wp[(size_t)Cdim * Cdim];
__device__ __align__(16) __half g_vh2[(size_t)Bdim * Hdim * Tdim * Ddim];
__device__ __align__(16) __half g_yh2[(size_t)Mrows * Cdim];
__device__ __align__(16) __half g_yl2[(size_t)Mrows * Cdim];

// ---------------------------------------------------------------------------
// Helpers
// ---------------------------------------------------------------------------
__device__ __forceinline__ uint32_t smem_u32(const void* p) {
    uint32_t a;
    asm("{ .reg .u64 t; cvta.to.shared.u64 t, %1; cvt.u32.u64 %0, t; }" : "=r"(a) : "l"(p));
    return a;
}

__device__ __forceinline__ void ldsm_x4(uint32_t& r0, uint32_t& r1, uint32_t& r2, uint32_t& r3,
                                        uint32_t addr) {
    asm volatile("ldmatrix.sync.aligned.m8n8.x4.shared.b16 {%0,%1,%2,%3}, [%4];"
                 : "=r"(r0), "=r"(r1), "=r"(r2), "=r"(r3) : "r"(addr));
}
__device__ __forceinline__ void ldsm_x4_t(uint32_t& r0, uint32_t& r1, uint32_t& r2, uint32_t& r3,
                                          uint32_t addr) {
    asm volatile("ldmatrix.sync.aligned.m8n8.x4.trans.shared.b16 {%0,%1,%2,%3}, [%4];"
                 : "=r"(r0), "=r"(r1), "=r"(r2), "=r"(r3) : "r"(addr));
}

__device__ __forceinline__ void mma16816(float* c, const uint32_t* a, const uint32_t* b) {
    asm volatile(
        "mma.sync.aligned.m16n8k16.row.col.f32.bf16.bf16.f32 "
        "{%0,%1,%2,%3}, {%4,%5,%6,%7}, {%8,%9}, {%0,%1,%2,%3};"
        : "+f"(c[0]), "+f"(c[1]), "+f"(c[2]), "+f"(c[3])
        : "r"(a[0]), "r"(a[1]), "r"(a[2]), "r"(a[3]), "r"(b[0]), "r"(b[1]));
}
__device__ __forceinline__ void mma16816h(float* c, const uint32_t* a, const uint32_t* b) {
    asm volatile(
        "mma.sync.aligned.m16n8k16.row.col.f32.f16.f16.f32 "
        "{%0,%1,%2,%3}, {%4,%5,%6,%7}, {%8,%9}, {%0,%1,%2,%3};"
        : "+f"(c[0]), "+f"(c[1]), "+f"(c[2]), "+f"(c[3])
        : "r"(a[0]), "r"(a[1]), "r"(a[2]), "r"(a[3]), "r"(b[0]), "r"(b[1]));
}

__device__ __forceinline__ uint32_t pack2bf16(float x, float y) {
    __nv_bfloat162 t;
    t.x = __float2bfloat16_rn(x);
    t.y = __float2bfloat16_rn(y);
    return *reinterpret_cast<uint32_t*>(&t);
}
__device__ __forceinline__ uint32_t pack2bf16_lo(float x, float y) {
    float hx = __bfloat162float(__float2bfloat16_rn(x));
    float hy = __bfloat162float(__float2bfloat16_rn(y));
    __nv_bfloat162 t;
    t.x = __float2bfloat16_rn(x - hx);
    t.y = __float2bfloat16_rn(y - hy);
    return *reinterpret_cast<uint32_t*>(&t);
}
__device__ __forceinline__ uint32_t pack2h(float x, float y) {
    __half2 t;
    t.x = __float2half_rn(x);
    t.y = __float2half_rn(y);
    return *reinterpret_cast<uint32_t*>(&t);
}
__device__ __forceinline__ uint32_t pack2h_lo(float x, float y) {
    float hx = __half2float(__float2half_rn(x));
    float hy = __half2float(__float2half_rn(y));
    __half2 t;
    t.x = __float2half_rn(x - hx);
    t.y = __float2half_rn(y - hy);
    return *reinterpret_cast<uint32_t*>(&t);
}

// cp.async (LDGSTS): global -> smem, 16B, L1-bypass (.cg)
#define CPASYNC(saddr, gptr) \
    asm volatile("cp.async.cg.shared.global [%0], [%1], 16;" :: "r"(saddr), "l"(gptr))
#define CPCOMMIT() asm volatile("cp.async.commit_group;" ::: "memory")
#define CPWAIT1() asm volatile("cp.async.wait_group 1;" ::: "memory")
#define CPWAIT0() asm volatile("cp.async.wait_group 0;" ::: "memory")

#define SROW 40    // GEMM smem row stride (elements; 80B, conflict-free ldmatrix)
#define SROWA 72   // Attention smem row stride (elements)

// bf16 3-term GEMM smem: per stage Ahi/Alo (128x32) + Bhi/Blo (256x32)
#define GT_A 10240             // 128*40*2
#define GT_B 20480             // 256*40*2
#define GSTAGE2 (2 * GT_A + 2 * GT_B)   // 61440
#define GSMEM2 (2 * GSTAGE2)            // 122880
// fp16 2-term GEMM smem: per stage Ahi/Alo + Bh only
#define GSTAGE_H (2 * GT_A + GT_B)      // 40960
#define GSMEM_H (2 * GSTAGE_H)          // 81920

// Attention smem: 2 stages, each Khi/Klo (bf16) + Vh (fp16), 64 rows x SROWA
#define ATILE 9216             // 64*72*2
#define ASTAGE (3 * ATILE)     // 27648
#define ASMEM (2 * ASTAGE)     // 55296

// ---------------------------------------------------------------------------
// Pre-pass split kernels
// ---------------------------------------------------------------------------
__global__ void split2_kernel(const float* __restrict__ src, __nv_bfloat16* __restrict__ hi,
                              __nv_bfloat16* __restrict__ lo, int n4) {
    int i = blockIdx.x * blockDim.x + threadIdx.x;
    if (i < n4) {
        float4 v = ((const float4*)src)[i];
        ((uint2*)hi)[i] = make_uint2(pack2bf16(v.x, v.y), pack2bf16(v.z, v.w));
        ((uint2*)lo)[i] = make_uint2(pack2bf16_lo(v.x, v.y), pack2bf16_lo(v.z, v.w));
    }
}
__global__ void split2h_kernel(const float* __restrict__ src, __half* __restrict__ hi,
                               __half* __restrict__ lo, int n4) {
    int i = blockIdx.x * blockDim.x + threadIdx.x;
    if (i < n4) {
        float4 v = ((const float4*)src)[i];
        ((uint2*)hi)[i] = make_uint2(pack2h(v.x, v.y), pack2h(v.z, v.w));
        ((uint2*)lo)[i] = make_uint2(pack2h_lo(v.x, v.y), pack2h_lo(v.z, v.w));
    }
}
__global__ void round1h_kernel(const float* __restrict__ src, __half* __restrict__ dst, int n4) {
    int i = blockIdx.x * blockDim.x + threadIdx.x;
    if (i < n4) {
        float4 v = ((const float4*)src)[i];
        ((uint2*)dst)[i] = make_uint2(pack2h(v.x, v.y), pack2h(v.z, v.w));
    }
}

// ---------------------------------------------------------------------------
// bf16 3-term GEMM (NT), CTA 128x256, cp.async double-buffered.
// Used for GEMM1 q,k columns only (MODE 1 epilogue; col0 < 2048).
// ---------------------------------------------------------------------------
__global__ void __launch_bounds__(256, 1) gemm_bf3(const __nv_bfloat16* __restrict__ Ah,
                                                   const __nv_bfloat16* __restrict__ Al,
                                                   const __nv_bfloat16* __restrict__ Bh,
                                                   const __nv_bfloat16* __restrict__ Bl,
                                                   int K) {
    extern __shared__ __align__(16) char smem[];
    const uint32_t sb = smem_u32(smem);

    const int tid = threadIdx.x;
    const int lane = tid & 31;
    const int wid = tid >> 5;
    const int wm = wid >> 2;
    const int wn = wid & 3;
    const int bm = blockIdx.y * 128;
    const int bn = blockIdx.x * 256;

    const __nv_bfloat16* Agh = Ah + (size_t)bm * K;
    const __nv_bfloat16* Agl = Al + (size_t)bm * K;
    const __nv_bfloat16* Bgh = Bh + (size_t)bn * K;
    const __nv_bfloat16* Bgl = Bl + (size_t)bn * K;

    const int nch = K / 32;

    auto issue = [&](int ch, uint32_t st) {
        const int koff = ch * 32;
#pragma unroll
        for (int p = 0; p < 2; p++) {
            int u = tid + 256 * p;
            int row = u >> 2, seg = u & 3;
            uint32_t so = sb + st + (uint32_t)(row * 80 + seg * 16);
            size_t go = (size_t)row * K + koff + seg * 8;
            CPASYNC(so, Agh + go);
            CPASYNC(so + GT_A, Agl + go);
        }
#pragma unroll
        for (int p = 0; p < 4; p++) {
            int u = tid + 256 * p;
            int row = u >> 2, seg = u & 3;
            uint32_t so = sb + st + 2 * GT_A + (uint32_t)(row * 80 + seg * 16);
            size_t go = (size_t)row * K + koff + seg * 8;
            CPASYNC(so, Bgh + go);
            CPASYNC(so + GT_B, Bgl + go);
        }
    };

    float acc[4][8][4];
#pragma unroll
    for (int i = 0; i < 4; i++)
#pragma unroll
        for (int j = 0; j < 8; j++)
#pragma unroll
            for (int r = 0; r < 4; r++) acc[i][j][r] = 0.f;

    const uint32_t aOff = (uint32_t)((wm * 64 + (lane & 15)) * SROW + (lane >> 4) * 8) * 2;
    const uint32_t bOff = (uint32_t)((wn * 64 + (lane >> 4) * 8 + (lane & 7)) * SROW +
                                     ((lane >> 3) & 1) * 8) * 2;

    issue(0, 0); CPCOMMIT();
    issue(1, GSTAGE2); CPCOMMIT();
    CPWAIT1();
    __syncthreads();

    for (int ch = 0; ch < nch; ch++) {
        const uint32_t cur = (uint32_t)(ch & 1) * GSTAGE2;
        const uint32_t aHiB = sb + cur;
        const uint32_t aLoB = sb + cur + GT_A;
        const uint32_t bHiB = sb + cur + 2 * GT_A;
        const uint32_t bLoB = sb + cur + 2 * GT_A + GT_B;

#pragma unroll
        for (int kk = 0; kk < 2; kk++) {
            const uint32_t kByte = (uint32_t)(kk * 16 * 2);
            uint32_t bh[8][2], bl[8][2];
#pragma unroll
            for (int jp = 0; jp < 4; jp++) {
                uint32_t o = bOff + kByte + (uint32_t)(jp * 16 * SROW * 2);
                uint32_t t0, t1, t2, t3;
                ldsm_x4(t0, t1, t2, t3, bHiB + o);
                bh[2 * jp][0] = t0; bh[2 * jp][1] = t1;
                bh[2 * jp + 1][0] = t2; bh[2 * jp + 1][1] = t3;
                ldsm_x4(t0, t1, t2, t3, bLoB + o);
                bl[2 * jp][0] = t0; bl[2 * jp][1] = t1;
                bl[2 * jp + 1][0] = t2; bl[2 * jp + 1][1] = t3;
            }
            uint32_t af[4][4];
#pragma unroll
            for (int i = 0; i < 4; i++)
                ldsm_x4(af[i][0], af[i][1], af[i][2], af[i][3],
                        aHiB + aOff + kByte + (uint32_t)(i * 16 * SROW * 2));
#pragma unroll
            for (int i = 0; i < 4; i++)
#pragma unroll
                for (int j = 0; j < 8; j++) mma16816(acc[i][j], af[i], bh[j]);
#pragma unroll
            for (int i = 0; i < 4; i++)
#pragma unroll
                for (int j = 0; j < 8; j++) mma16816(acc[i][j], af[i], bl[j]);
#pragma unroll
            for (int i = 0; i < 4; i++)
                ldsm_x4(af[i][0], af[i][1], af[i][2], af[i][3],
                        aLoB + aOff + kByte + (uint32_t)(i * 16 * SROW * 2));
#pragma unroll
            for (int i = 0; i < 4; i++)
#pragma unroll
                for (int j = 0; j < 8; j++) mma16816(acc[i][j], af[i], bh[j]);
        }
        __syncthreads();
        if (ch + 1 < nch) {
            if (ch + 2 < nch) { issue(ch + 2, cur); CPCOMMIT(); CPWAIT1(); }
            else { CPWAIT0(); }
            __syncthreads();
        }
    }

    const int lr = lane >> 2;
    const int lc = (lane & 3) * 2;

    // epilogue: q (col0<1024, *0.125) / k -> bf16 hi/lo [B,H,T,D]
    int col0 = bn + wn * 64;
    int sdx = col0 >> 10;                  // 0=q, 1=k
    int h = (col0 & (Cdim - 1)) >> 6;
    __nv_bfloat16* dh = (sdx == 0) ? g_qh : g_kh;
    __nv_bfloat16* dl = (sdx == 0) ? g_ql : g_kl;
    float sc = (sdx == 0) ? 0.125f : 1.0f;
#pragma unroll
    for (int i = 0; i < 4; i++) {
        int rowA = bm + wm * 64 + i * 16 + lr;
#pragma unroll
        for (int hh = 0; hh < 2; hh++) {
            int row = rowA + hh * 8;
            int b = row >> 11;
            int t = row & (Tdim - 1);
            size_t off = ((size_t)(b * Hdim + h) * Tdim + t) * Ddim + lc;
#pragma unroll
            for (int j = 0; j < 8; j++) {
                float f0 = acc[i][j][hh * 2] * sc;
                float f1 = acc[i][j][hh * 2 + 1] * sc;
                *(uint32_t*)&dh[off + j * 8] = pack2bf16(f0, f1);
                *(uint32_t*)&dl[off + j * 8] = pack2bf16_lo(f0, f1);
            }
        }
    }
}

// ---------------------------------------------------------------------------
// fp16 2-term asymmetric GEMM (NT): C = (Ah+Al) @ Bh^T. CTA 128x256.
// MODE 0: fp32 store to Cout.  MODE 2: v scatter as single fp16 [B,H,T,D].
// ---------------------------------------------------------------------------
template <int MODE>
__global__ void __launch_bounds__(256, 1) gemm_h2(const __half* __restrict__ Ah,
                                                  const __half* __restrict__ Al,
                                                  const __half* __restrict__ Bh,
                                                  float* __restrict__ Cout,
                                                  int K, int N) {
    extern __shared__ __align__(16) char smem[];
    const uint32_t sb = smem_u32(smem);

    const int tid = threadIdx.x;
    const int lane = tid & 31;
    const int wid = tid >> 5;
    const int wm = wid >> 2;
    const int wn = wid & 3;
    const int bm = blockIdx.y * 128;
    const int bn = blockIdx.x * 256;

    const __half* Agh = Ah + (size_t)bm * K;
    const __half* Agl = Al + (size_t)bm * K;
    const __half* Bgh = Bh + (size_t)bn * K;

    const int nch = K / 32;

    auto issue = [&](int ch, uint32_t st) {
        const int koff = ch * 32;
#pragma unroll
        for (int p = 0; p < 2; p++) {
            int u = tid + 256 * p;
            int row = u >> 2, seg = u & 3;
            uint32_t so = sb + st + (uint32_t)(row * 80 + seg * 16);
            size_t go = (size_t)row * K + koff + seg * 8;
            CPASYNC(so, Agh + go);
            CPASYNC(so + GT_A, Agl + go);
        }
#pragma unroll
        for (int p = 0; p < 4; p++) {
            int u = tid + 256 * p;
            int row = u >> 2, seg = u & 3;
            uint32_t so = sb + st + 2 * GT_A + (uint32_t)(row * 80 + seg * 16);
            size_t go = (size_t)row * K + koff + seg * 8;
            CPASYNC(so, Bgh + go);
        }
    };

    float acc[4][8][4];
#pragma unroll
    for (int i = 0; i < 4; i++)
#pragma unroll
        for (int j = 0; j < 8; j++)
#pragma unroll
            for (int r = 0; r < 4; r++) acc[i][j][r] = 0.f;

    const uint32_t aOff = (uint32_t)((wm * 64 + (lane & 15)) * SROW + (lane >> 4) * 8) * 2;
    const uint32_t bOff = (uint32_t)((wn * 64 + (lane >> 4) * 8 + (lane & 7)) * SROW +
                                     ((lane >> 3) & 1) * 8) * 2;

    issue(0, 0); CPCOMMIT();
    issue(1, GSTAGE_H); CPCOMMIT();
    CPWAIT1();
    __syncthreads();

    for (int ch = 0; ch < nch; ch++) {
        const uint32_t cur = (uint32_t)(ch & 1) * GSTAGE_H;
        const uint32_t aHiB = sb + cur;
        const uint32_t aLoB = sb + cur + GT_A;
        const uint32_t bHiB = sb + cur + 2 * GT_A;

#pragma unroll
        for (int kk = 0; kk < 2; kk++) {
            const uint32_t kByte = (uint32_t)(kk * 16 * 2);
            uint32_t bh[8][2];
#pragma unroll
            for (int jp = 0; jp < 4; jp++) {
                uint32_t o = bOff + kByte + (uint32_t)(jp * 16 * SROW * 2);
                uint32_t t0, t1, t2, t3;
                ldsm_x4(t0, t1, t2, t3, bHiB + o);
                bh[2 * jp][0] = t0; bh[2 * jp][1] = t1;
                bh[2 * jp + 1][0] = t2; bh[2 * jp + 1][1] = t3;
            }
            uint32_t af[4][4];
#pragma unroll
            for (int i = 0; i < 4; i++)
                ldsm_x4(af[i][0], af[i][1], af[i][2], af[i][3],
                        aHiB + aOff + kByte + (uint32_t)(i * 16 * SROW * 2));
#pragma unroll
            for (int i = 0; i < 4; i++)
#pragma unroll
                for (int j = 0; j < 8; j++) mma16816h(acc[i][j], af[i], bh[j]);
#pragma unroll
            for (int i = 0; i < 4; i++)
                ldsm_x4(af[i][0], af[i][1], af[i][2], af[i][3],
                        aLoB + aOff + kByte + (uint32_t)(i * 16 * SROW * 2));
#pragma unroll
            for (int i = 0; i < 4; i++)
#pragma unroll
                for (int j = 0; j < 8; j++) mma16816h(acc[i][j], af[i], bh[j]);
        }
        __syncthreads();
        if (ch + 1 < nch) {
            if (ch + 2 < nch) { issue(ch + 2, cur); CPCOMMIT(); CPWAIT1(); }
            else { CPWAIT0(); }
            __syncthreads();
        }
    }

    const int lr = lane >> 2;
    const int lc = (lane & 3) * 2;

    if (MODE == 0) {
#pragma unroll
        for (int i = 0; i < 4; i++) {
            int rowA = bm + wm * 64 + i * 16 + lr;
#pragma unroll
            for (int j = 0; j < 8; j++) {
                int col = bn + wn * 64 + j * 8 + lc;
                *(float2*)&Cout[(size_t)rowA * N + col] = make_float2(acc[i][j][0], acc[i][j][1]);
                *(float2*)&Cout[(size_t)(rowA + 8) * N + col] = make_float2(acc[i][j][2], acc[i][j][3]);
            }
        }
    } else {
        // v epilogue: single fp16 [B,H,T,D]; B matrix = w_attn v-rows, so
        // head h = local col / 64
        int col0 = bn + wn * 64;
        int h = col0 >> 6;
#pragma unroll
        for (int i = 0; i < 4; i++) {
            int rowA = bm + wm * 64 + i * 16 + lr;
#pragma unroll
            for (int hh = 0; hh < 2; hh++) {
                int row = rowA + hh * 8;
                int b = row >> 11;
                int t = row & (Tdim - 1);
                size_t off = ((size_t)(b * Hdim + h) * Tdim + t) * Ddim + lc;
#pragma unroll
                for (int j = 0; j < 8; j++) {
                    *(uint32_t*)&g_vh2[off + j * 8] =
                        pack2h(acc[i][j][hh * 2], acc[i][j][hh * 2 + 1]);
                }
            }
        }
    }
}

// ---------------------------------------------------------------------------
// Tensor-core causal flash attention.
// S = Q.K^T: bf16 3-term (accuracy-critical). P.V: fp16 2-term (P hi/lo, V single).
// Writes y as fp16 hi/lo for GEMM2.
// ---------------------------------------------------------------------------
__global__ void __launch_bounds__(256) attn_mma() {
    extern __shared__ __align__(16) char sbuf[];
    const uint32_t sb = smem_u32(sbuf);
    const int tid = threadIdx.x;
    const int lane = tid & 31;
    const int w = tid >> 5;
    const int bh = blockIdx.y;
    const int q0 = (int)(gridDim.x - 1 - blockIdx.x) * 128;

    const size_t headoff = (size_t)bh * Tdim * Ddim;
    const int ktmax = (q0 + 127) >> 6;

    const int arow = tid >> 3;
    const int ac8 = (tid & 7) * 8;
    uint4 kh_r[2], kl_r[2], vh_r[2];

    auto ldkv = [&](int kt) {
        const size_t base = headoff + (size_t)(kt * 64) * Ddim;
#pragma unroll
        for (int p = 0; p < 2; p++) {
            size_t o = base + (size_t)(arow + 32 * p) * Ddim + ac8;
            kh_r[p] = *(const uint4*)&g_kh[o];
            kl_r[p] = *(const uint4*)&g_kl[o];
            vh_r[p] = *(const uint4*)&g_vh2[o];
        }
    };
    auto stkv = [&](uint32_t stOff) {
#pragma unroll
        for (int p = 0; p < 2; p++) {
            uint32_t so = (uint32_t)((arow + 32 * p) * SROWA + ac8) * 2;
            *(uint4*)(sbuf + stOff + 0 * ATILE + so) = kh_r[p];
            *(uint4*)(sbuf + stOff + 1 * ATILE + so) = kl_r[p];
            *(uint4*)(sbuf + stOff + 2 * ATILE + so) = vh_r[p];
        }
    };

    ldkv(0);
    {
        const uint4* qgh = (const uint4*)(g_qh + headoff + (size_t)q0 * Ddim);
        const uint4* qgl = (const uint4*)(g_ql + headoff + (size_t)q0 * Ddim);
#pragma unroll
        for (int p = 0; p < 4; p++) {
            int u = p * 256 + tid;
            int row = u >> 3;
            int c8 = (u & 7) * 8;
            uint32_t so = (uint32_t)(row * SROWA + c8) * 2;
            *(uint4*)(sbuf + so) = qgh[u];
            *(uint4*)(sbuf + 18432 + so) = qgl[u];
        }
    }
    __syncthreads();

    uint32_t qh[4][4], ql[4][4];
#pragma unroll
    for (int kk = 0; kk < 4; kk++) {
        uint32_t off = (uint32_t)((16 * w + (lane & 15)) * SROWA + 16 * kk + 8 * (lane >> 4)) * 2;
        ldsm_x4(qh[kk][0], qh[kk][1], qh[kk][2], qh[kk][3], sb + off);
        ldsm_x4(ql[kk][0], ql[kk][1], ql[kk][2], ql[kk][3], sb + 18432 + off);
    }
    __syncthreads();

    stkv(0);
    ldkv(1);
    __syncthreads();

    float oacc[8][4];
#pragma unroll
    for (int j = 0; j < 8; j++)
#pragma unroll
        for (int r = 0; r < 4; r++) oacc[j][r] = 0.f;
    float m1 = -1e30f, m2 = -1e30f, l1 = 0.f, l2 = 0.f;

    const int r1 = q0 + 16 * w + (lane >> 2);
    const int r2 = r1 + 8;

    for (int kt = 0; kt <= ktmax; kt++) {
        const int kbase = kt * 64;
        const int s = kt & 1;
        const uint32_t cur = (uint32_t)s * ASTAGE;
        const uint32_t nxt = (uint32_t)(s ^ 1) * ASTAGE;

        if (kt + 1 <= ktmax) stkv(nxt);
        if (kt + 2 <= ktmax) ldkv(kt + 2);

        const uint32_t oKhi = cur + 0 * ATILE, oKlo = cur + 1 * ATILE;
        const uint32_t oVh = cur + 2 * ATILE;

        // ---- S = Q.K^T (bf16 3-term) ----
        float sacc[8][4];
#pragma unroll
        for (int j = 0; j < 8; j++)
#pragma unroll
            for (int r = 0; r < 4; r++) sacc[j][r] = 0.f;

#pragma unroll
        for (int kk = 0; kk < 4; kk++) {
            uint32_t bhp[8][2], blp[8][2];
#pragma unroll
            for (int np = 0; np < 4; np++) {
                uint32_t off = (uint32_t)((np * 16 + (lane >> 4) * 8 + (lane & 7)) * SROWA +
                                          ((lane >> 3) & 1) * 8 + 16 * kk) * 2;
                uint32_t t0, t1, t2, t3;
                ldsm_x4(t0, t1, t2, t3, sb + oKhi + off);
                bhp[2 * np][0] = t0; bhp[2 * np][1] = t1;
                bhp[2 * np + 1][0] = t2; bhp[2 * np + 1][1] = t3;
                ldsm_x4(t0, t1, t2, t3, sb + oKlo + off);
                blp[2 * np][0] = t0; blp[2 * np][1] = t1;
                blp[2 * np + 1][0] = t2; blp[2 * np + 1][1] = t3;
            }
#pragma unroll
            for (int j = 0; j < 8; j++) mma16816(sacc[j], qh[kk], bhp[j]);
#pragma unroll
            for (int j = 0; j < 8; j++) mma16816(sacc[j], qh[kk], blp[j]);
#pragma unroll
            for (int j = 0; j < 8; j++) mma16816(sacc[j], ql[kk], bhp[j]);
        }

        if (kbase + 63 > q0 + 16 * w) {
            const int c0 = kbase + 2 * (lane & 3);
#pragma unroll
            for (int j = 0; j < 8; j++) {
                int cj = c0 + 8 * j;
                if (cj > r1)     sacc[j][0] = -1e30f;
                if (cj + 1 > r1) sacc[j][1] = -1e30f;
                if (cj > r2)     sacc[j][2] = -1e30f;
                if (cj + 1 > r2) sacc[j][3] = -1e30f;
            }
        }

        float t1m = -1e30f, t2m = -1e30f;
#pragma unroll
        for (int j = 0; j < 8; j++) {
            t1m = fmaxf(t1m, fmaxf(sacc[j][0], sacc[j][1]));
            t2m = fmaxf(t2m, fmaxf(sacc[j][2], sacc[j][3]));
        }
        t1m = fmaxf(t1m, __shfl_xor_sync(0xffffffffu, t1m, 1));
        t1m = fmaxf(t1m, __shfl_xor_sync(0xffffffffu, t1m, 2));
        t2m = fmaxf(t2m, __shfl_xor_sync(0xffffffffu, t2m, 1));
        t2m = fmaxf(t2m, __shfl_xor_sync(0xffffffffu, t2m, 2));

        float nm1 = fmaxf(m1, t1m), nm2 = fmaxf(m2, t2m);
        float corr1 = __expf(m1 - nm1), corr2 = __expf(m2 - nm2);
        m1 = nm1; m2 = nm2;

        float s1 = 0.f, s2 = 0.f;
#pragma unroll
        for (int j = 0; j < 8; j++) {
            sacc[j][0] = __expf(sacc[j][0] - m1);
            sacc[j][1] = __expf(sacc[j][1] - m1);
            sacc[j][2] = __expf(sacc[j][2] - m2);
            sacc[j][3] = __expf(sacc[j][3] - m2);
            s1 += sacc[j][0] + sacc[j][1];
            s2 += sacc[j][2] + sacc[j][3];
        }
        s1 += __shfl_xor_sync(0xffffffffu, s1, 1);
        s1 += __shfl_xor_sync(0xffffffffu, s1, 2);
        s2 += __shfl_xor_sync(0xffffffffu, s2, 1);
        s2 += __shfl_xor_sync(0xffffffffu, s2, 2);
        l1 = l1 * corr1 + s1;
        l2 = l2 * corr2 + s2;

        // pack P into fp16 A-fragments (hi/lo)
        uint32_t ph[4][4], pl[4][4];
#pragma unroll
        for (int kk = 0; kk < 4; kk++) {
            int j0 = 2 * kk, j1 = 2 * kk + 1;
            ph[kk][0] = pack2h(sacc[j0][0], sacc[j0][1]);
            ph[kk][1] = pack2h(sacc[j0][2], sacc[j0][3]);
            ph[kk][2] = pack2h(sacc[j1][0], sacc[j1][1]);
            ph[kk][3] = pack2h(sacc[j1][2], sacc[j1][3]);
            pl[kk][0] = pack2h_lo(sacc[j0][0], sacc[j0][1]);
            pl[kk][1] = pack2h_lo(sacc[j0][2], sacc[j0][3]);
            pl[kk][2] = pack2h_lo(sacc[j1][0], sacc[j1][1]);
            pl[kk][3] = pack2h_lo(sacc[j1][2], sacc[j1][3]);
        }

#pragma unroll
        for (int j = 0; j < 8; j++) {
            oacc[j][0] *= corr1; oacc[j][1] *= corr1;
            oacc[j][2] *= corr2; oacc[j][3] *= corr2;
        }

        // ---- O += P.V (fp16 2-term: Ph.V + Pl.V) ----
#pragma unroll
        for (int kk = 0; kk < 4; kk++) {
            uint32_t vb[8][2];
#pragma unroll
            for (int np = 0; np < 4; np++) {
                uint32_t off = (uint32_t)((16 * kk + (lane & 15)) * SROWA +
                                          16 * np + 8 * (lane >> 4)) * 2;
                uint32_t t0, t1, t2, t3;
                ldsm_x4_t(t0, t1, t2, t3, sb + oVh + off);
                vb[2 * np][0] = t0; vb[2 * np][1] = t1;
                vb[2 * np + 1][0] = t2; vb[2 * np + 1][1] = t3;
            }
#pragma unroll
            for (int j = 0; j < 8; j++) mma16816h(oacc[j], ph[kk], vb[j]);
#pragma unroll
            for (int j = 0; j < 8; j++) mma16816h(oacc[j], pl[kk], vb[j]);
        }
        __syncthreads();
    }

    // ---- epilogue: y[B,T,H,D] as fp16 hi/lo ----
    float inv1 = 1.0f / l1, inv2 = 1.0f / l2;
    int b = bh >> 4, h = bh & 15;
    size_t off1 = ((size_t)(b * Tdim + r1) * Hdim + h) * Ddim;
    size_t off2 = ((size_t)(b * Tdim + r2) * Hdim + h) * Ddim;
    int d0 = 2 * (lane & 3);
#pragma unroll
    for (int j = 0; j < 8; j++) {
        float a0 = oacc[j][0] * inv1, a1 = oacc[j][1] * inv1;
        float b0 = oacc[j][2] * inv2, b1 = oacc[j][3] * inv2;
        *(uint32_t*)&g_yh2[off1 + 8 * j + d0] = pack2h(a0, a1);
        *(uint32_t*)&g_yl2[off1 + 8 * j + d0] = pack2h_lo(a0, a1);
        *(uint32_t*)&g_yh2[off2 + 8 * j + d0] = pack2h(b0, b1);
        *(uint32_t*)&g_yl2[off2 + 8 * j + d0] = pack2h_lo(b0, b1);
    }
}

// ---------------------------------------------------------------------------
extern "C" void kernel_launch(void* const* d_in, const int* in_sizes, int n_in,
                              void* d_out, int out_size) {
    const float* x = (const float*)d_in[0];        // [B,T,C]
    const float* w_attn = (const float*)d_in[1];   // [3C,C]
    const float* w_proj = (const float*)d_in[2];   // [C,C]
    float* out = (float*)d_out;                    // [B,T,C]

    __nv_bfloat16 *xh, *xl, *wah, *wal;
    __half *xh2, *xl2, *wv, *wp, *yh2, *yl2;
    cudaGetSymbolAddress((void**)&xh, g_xh);
    cudaGetSymbolAddress((void**)&xl, g_xl);
    cudaGetSymbolAddress((void**)&wah, g_wah);
    cudaGetSymbolAddress((void**)&wal, g_wal);
    cudaGetSymbolAddress((void**)&xh2, g_xh2);
    cudaGetSymbolAddress((void**)&xl2, g_xl2);
    cudaGetSymbolAddress((void**)&wv, g_wv);
    cudaGetSymbolAddress((void**)&wp, g_wp);
    cudaGetSymbolAddress((void**)&yh2, g_yh2);
    cudaGetSymbolAddress((void**)&yl2, g_yl2);

    cudaFuncSetAttribute(gemm_bf3, cudaFuncAttributeMaxDynamicSharedMemorySize, GSMEM2);
    cudaFuncSetAttribute(gemm_h2<0>, cudaFuncAttributeMaxDynamicSharedMemorySize, GSMEM_H);
    cudaFuncSetAttribute(gemm_h2<2>, cudaFuncAttributeMaxDynamicSharedMemorySize, GSMEM_H);
    cudaFuncSetAttribute(attn_mma, cudaFuncAttributeMaxDynamicSharedMemorySize, ASMEM);

    // Pre-pass splits
    const int nx4 = Mrows * Cdim / 4;              // 1M
    const int nwqk4 = 2 * Cdim * Cdim / 4;         // 512K
    const int nwv4 = Cdim * Cdim / 4;              // 256K
    split2_kernel<<<(nx4 + 255) / 256, 256>>>(x, xh, xl, nx4);
    split2_kernel<<<(nwqk4 + 255) / 256, 256>>>(w_attn, wah, wal, nwqk4);
    split2h_kernel<<<(nx4 + 255) / 256, 256>>>(x, xh2, xl2, nx4);
    round1h_kernel<<<(nwv4 + 255) / 256, 256>>>(w_attn + (size_t)2 * Cdim * Cdim, wv, nwv4);
    round1h_kernel<<<(nwv4 + 255) / 256, 256>>>(w_proj, wp, nwv4);

    // GEMM1 q,k columns (bf16 3-term): cols [0, 2048)
    dim3 g1(2 * Cdim / 256, Mrows / 128);   // (8, 32)
    gemm_bf3<<<g1, 256, GSMEM2>>>(xh, xl, wah, wal, Cdim);

    // GEMM1 v columns (fp16 2-term): w_attn rows [2048, 3072)
    dim3 gv(Cdim / 256, Mrows / 128);       // (4, 32)
    gemm_h2<2><<<gv, 256, GSMEM_H>>>(xh2, xl2, wv, nullptr, Cdim, Cdim);

    // Attention
    dim3 ga(Tdim / 128, Bdim * Hdim);       // (16, 32)
    attn_mma<<<ga, 256, ASMEM>>>();

    // GEMM2: out = y @ w_proj^T (fp16 2-term)
    dim3 g2(Cdim / 256, Mrows / 128);       // (4, 32)
    gemm_h2<0><<<g2, 256, GSMEM_H>>>(yh2, yl2, wp, out, Cdim, Cdim);
}

// round 11
// speedup vs baseline: 1.4599x; 1.1399x over previous
#include <cuda_runtime.h>
#include <cuda_fp16.h>
#include <cstdint>
#include <math.h>

// Problem constants
#define Bdim 2
#define Tdim 2048
#define Cdim 1024
#define Hdim 16
#define Ddim 64
#define Mrows (Bdim * Tdim)   // 4096

// Device-global scratch (allocation-free), all fp16
__device__ __align__(16) __half g_xh2[(size_t)Mrows * Cdim];
__device__ __align__(16) __half g_xl2[(size_t)Mrows * Cdim];
__device__ __align__(16) __half g_wa[(size_t)3 * Cdim * Cdim];
__device__ __align__(16) __half g_wp[(size_t)Cdim * Cdim];
__device__ __align__(16) __half g_qh2[(size_t)Bdim * Hdim * Tdim * Ddim];
__device__ __align__(16) __half g_ql2[(size_t)Bdim * Hdim * Tdim * Ddim];
__device__ __align__(16) __half g_kh2[(size_t)Bdim * Hdim * Tdim * Ddim];
__device__ __align__(16) __half g_vh2[(size_t)Bdim * Hdim * Tdim * Ddim];
__device__ __align__(16) __half g_yh2[(size_t)Mrows * Cdim];
__device__ __align__(16) __half g_yl2[(size_t)Mrows * Cdim];

// ---------------------------------------------------------------------------
// Helpers
// ---------------------------------------------------------------------------
__device__ __forceinline__ uint32_t smem_u32(const void* p) {
    uint32_t a;
    asm("{ .reg .u64 t; cvta.to.shared.u64 t, %1; cvt.u32.u64 %0, t; }" : "=r"(a) : "l"(p));
    return a;
}

__device__ __forceinline__ void ldsm_x4(uint32_t& r0, uint32_t& r1, uint32_t& r2, uint32_t& r3,
                                        uint32_t addr) {
    asm volatile("ldmatrix.sync.aligned.m8n8.x4.shared.b16 {%0,%1,%2,%3}, [%4];"
                 : "=r"(r0), "=r"(r1), "=r"(r2), "=r"(r3) : "r"(addr));
}
__device__ __forceinline__ void ldsm_x4_t(uint32_t& r0, uint32_t& r1, uint32_t& r2, uint32_t& r3,
                                          uint32_t addr) {
    asm volatile("ldmatrix.sync.aligned.m8n8.x4.trans.shared.b16 {%0,%1,%2,%3}, [%4];"
                 : "=r"(r0), "=r"(r1), "=r"(r2), "=r"(r3) : "r"(addr));
}

__device__ __forceinline__ void mma16816h(float* c, const uint32_t* a, const uint32_t* b) {
    asm volatile(
        "mma.sync.aligned.m16n8k16.row.col.f32.f16.f16.f32 "
        "{%0,%1,%2,%3}, {%4,%5,%6,%7}, {%8,%9}, {%0,%1,%2,%3};"
        : "+f"(c[0]), "+f"(c[1]), "+f"(c[2]), "+f"(c[3])
        : "r"(a[0]), "r"(a[1]), "r"(a[2]), "r"(a[3]), "r"(b[0]), "r"(b[1]));
}

__device__ __forceinline__ uint32_t pack2h(float x, float y) {
    __half2 t;
    t.x = __float2half_rn(x);
    t.y = __float2half_rn(y);
    return *reinterpret_cast<uint32_t*>(&t);
}
__device__ __forceinline__ uint32_t pack2h_lo(float x, float y) {
    float hx = __half2float(__float2half_rn(x));
    float hy = __half2float(__float2half_rn(y));
    __half2 t;
    t.x = __float2half_rn(x - hx);
    t.y = __float2half_rn(y - hy);
    return *reinterpret_cast<uint32_t*>(&t);
}

// cp.async (LDGSTS): global -> smem, 16B, L1-bypass (.cg)
#define CPASYNC(saddr, gptr) \
    asm volatile("cp.async.cg.shared.global [%0], [%1], 16;" :: "r"(saddr), "l"(gptr))
#define CPCOMMIT() asm volatile("cp.async.commit_group;" ::: "memory")
#define CPWAIT1() asm volatile("cp.async.wait_group 1;" ::: "memory")
#define CPWAIT0() asm volatile("cp.async.wait_group 0;" ::: "memory")

#define SROW 40    // GEMM smem row stride (elements; 80B, conflict-free ldmatrix)
#define SROWA 72   // Attention smem row stride (elements)

// fp16 2-term GEMM smem: per stage Ahi/Alo (128x32) + Bh (256x32)
#define GT_A 10240             // 128*40*2
#define GT_B 20480             // 256*40*2
#define GSTAGE_H (2 * GT_A + GT_B)      // 40960
#define GSMEM_H (2 * GSTAGE_H)          // 81920

// Attention smem: 2 stages, each Kh + Vh (single fp16), 64 rows x SROWA
#define ATILE 9216             // 64*72*2
#define ASTAGE (2 * ATILE)     // 18432
#define ASMEM (2 * ASTAGE)     // 36864

// ---------------------------------------------------------------------------
// Pre-pass split kernels
// ---------------------------------------------------------------------------
__global__ void split2h_kernel(const float* __restrict__ src, __half* __restrict__ hi,
                               __half* __restrict__ lo, int n4) {
    int i = blockIdx.x * blockDim.x + threadIdx.x;
    if (i < n4) {
        float4 v = ((const float4*)src)[i];
        ((uint2*)hi)[i] = make_uint2(pack2h(v.x, v.y), pack2h(v.z, v.w));
        ((uint2*)lo)[i] = make_uint2(pack2h_lo(v.x, v.y), pack2h_lo(v.z, v.w));
    }
}
__global__ void round1h_kernel(const float* __restrict__ src, __half* __restrict__ dst, int n4) {
    int i = blockIdx.x * blockDim.x + threadIdx.x;
    if (i < n4) {
        float4 v = ((const float4*)src)[i];
        ((uint2*)dst)[i] = make_uint2(pack2h(v.x, v.y), pack2h(v.z, v.w));
    }
}

// ---------------------------------------------------------------------------
// fp16 2-term asymmetric GEMM (NT): C = (Ah+Al) @ Bh^T. CTA 128x256,
// cp.async double-buffered.
// MODE 0: fp32 store to Cout.
// MODE 1: qkv scatter: q -> fp16 hi/lo *0.125; k,v -> single fp16 [B,H,T,D].
// ---------------------------------------------------------------------------
template <int MODE>
__global__ void __launch_bounds__(256, 1) gemm_h2(const __half* __restrict__ Ah,
                                                  const __half* __restrict__ Al,
                                                  const __half* __restrict__ Bh,
                                                  float* __restrict__ Cout,
                                                  int K, int N) {
    extern __shared__ __align__(16) char smem[];
    const uint32_t sb = smem_u32(smem);

    const int tid = threadIdx.x;
    const int lane = tid & 31;
    const int wid = tid >> 5;
    const int wm = wid >> 2;
    const int wn = wid & 3;
    const int bm = blockIdx.y * 128;
    const int bn = blockIdx.x * 256;

    const __half* Agh = Ah + (size_t)bm * K;
    const __half* Agl = Al + (size_t)bm * K;
    const __half* Bgh = Bh + (size_t)bn * K;

    const int nch = K / 32;

    auto issue = [&](int ch, uint32_t st) {
        const int koff = ch * 32;
#pragma unroll
        for (int p = 0; p < 2; p++) {
            int u = tid + 256 * p;
            int row = u >> 2, seg = u & 3;
            uint32_t so = sb + st + (uint32_t)(row * 80 + seg * 16);
            size_t go = (size_t)row * K + koff + seg * 8;
            CPASYNC(so, Agh + go);
            CPASYNC(so + GT_A, Agl + go);
        }
#pragma unroll
        for (int p = 0; p < 4; p++) {
            int u = tid + 256 * p;
            int row = u >> 2, seg = u & 3;
            uint32_t so = sb + st + 2 * GT_A + (uint32_t)(row * 80 + seg * 16);
            size_t go = (size_t)row * K + koff + seg * 8;
            CPASYNC(so, Bgh + go);
        }
    };

    float acc[4][8][4];
#pragma unroll
    for (int i = 0; i < 4; i++)
#pragma unroll
        for (int j = 0; j < 8; j++)
#pragma unroll
            for (int r = 0; r < 4; r++) acc[i][j][r] = 0.f;

    const uint32_t aOff = (uint32_t)((wm * 64 + (lane & 15)) * SROW + (lane >> 4) * 8) * 2;
    const uint32_t bOff = (uint32_t)((wn * 64 + (lane >> 4) * 8 + (lane & 7)) * SROW +
                                     ((lane >> 3) & 1) * 8) * 2;

    issue(0, 0); CPCOMMIT();
    issue(1, GSTAGE_H); CPCOMMIT();
    CPWAIT1();
    __syncthreads();

    for (int ch = 0; ch < nch; ch++) {
        const uint32_t cur = (uint32_t)(ch & 1) * GSTAGE_H;
        const uint32_t aHiB = sb + cur;
        const uint32_t aLoB = sb + cur + GT_A;
        const uint32_t bHiB = sb + cur + 2 * GT_A;

#pragma unroll
        for (int kk = 0; kk < 2; kk++) {
            const uint32_t kByte = (uint32_t)(kk * 16 * 2);
            uint32_t bh[8][2];
#pragma unroll
            for (int jp = 0; jp < 4; jp++) {
                uint32_t o = bOff + kByte + (uint32_t)(jp * 16 * SROW * 2);
                uint32_t t0, t1, t2, t3;
                ldsm_x4(t0, t1, t2, t3, bHiB + o);
                bh[2 * jp][0] = t0; bh[2 * jp][1] = t1;
                bh[2 * jp + 1][0] = t2; bh[2 * jp + 1][1] = t3;
            }
            uint32_t af[4][4];
#pragma unroll
            for (int i = 0; i < 4; i++)
                ldsm_x4(af[i][0], af[i][1], af[i][2], af[i][3],
                        aHiB + aOff + kByte + (uint32_t)(i * 16 * SROW * 2));
#pragma unroll
            for (int i = 0; i < 4; i++)
#pragma unroll
                for (int j = 0; j < 8; j++) mma16816h(acc[i][j], af[i], bh[j]);
#pragma unroll
            for (int i = 0; i < 4; i++)
                ldsm_x4(af[i][0], af[i][1], af[i][2], af[i][3],
                        aLoB + aOff + kByte + (uint32_t)(i * 16 * SROW * 2));
#pragma unroll
            for (int i = 0; i < 4; i++)
#pragma unroll
                for (int j = 0; j < 8; j++) mma16816h(acc[i][j], af[i], bh[j]);
        }
        __syncthreads();
        if (ch + 1 < nch) {
            if (ch + 2 < nch) { issue(ch + 2, cur); CPCOMMIT(); CPWAIT1(); }
            else { CPWAIT0(); }
            __syncthreads();
        }
    }

    const int lr = lane >> 2;
    const int lc = (lane & 3) * 2;

    if (MODE == 0) {
#pragma unroll
        for (int i = 0; i < 4; i++) {
            int rowA = bm + wm * 64 + i * 16 + lr;
#pragma unroll
            for (int j = 0; j < 8; j++) {
                int col = bn + wn * 64 + j * 8 + lc;
                *(float2*)&Cout[(size_t)rowA * N + col] = make_float2(acc[i][j][0], acc[i][j][1]);
                *(float2*)&Cout[(size_t)(rowA + 8) * N + col] = make_float2(acc[i][j][2], acc[i][j][3]);
            }
        }
    } else {
        // warp covers one head's 64 cols. sdx: 0=q 1=k 2=v
        int col0 = bn + wn * 64;
        int sdx = col0 >> 10;
        int h = (col0 & (Cdim - 1)) >> 6;
        if (sdx == 0) {
            // q: fp16 hi/lo, pre-scaled by 1/sqrt(D)
#pragma unroll
            for (int i = 0; i < 4; i++) {
                int rowA = bm + wm * 64 + i * 16 + lr;
#pragma unroll
                for (int hh = 0; hh < 2; hh++) {
                    int row = rowA + hh * 8;
                    int b = row >> 11;
                    int t = row & (Tdim - 1);
                    size_t off = ((size_t)(b * Hdim + h) * Tdim + t) * Ddim + lc;
#pragma unroll
                    for (int j = 0; j < 8; j++) {
                        float f0 = acc[i][j][hh * 2] * 0.125f;
                        float f1 = acc[i][j][hh * 2 + 1] * 0.125f;
                        *(uint32_t*)&g_qh2[off + j * 8] = pack2h(f0, f1);
                        *(uint32_t*)&g_ql2[off + j * 8] = pack2h_lo(f0, f1);
                    }
                }
            }
        } else {
            __half* dst = (sdx == 1) ? g_kh2 : g_vh2;
#pragma unroll
            for (int i = 0; i < 4; i++) {
                int rowA = bm + wm * 64 + i * 16 + lr;
#pragma unroll
                for (int hh = 0; hh < 2; hh++) {
                    int row = rowA + hh * 8;
                    int b = row >> 11;
                    int t = row & (Tdim - 1);
                    size_t off = ((size_t)(b * Hdim + h) * Tdim + t) * Ddim + lc;
#pragma unroll
                    for (int j = 0; j < 8; j++) {
                        *(uint32_t*)&dst[off + j * 8] =
                            pack2h(acc[i][j][hh * 2], acc[i][j][hh * 2 + 1]);
                    }
                }
            }
        }
    }
}

// ---------------------------------------------------------------------------
// Tensor-core causal flash attention, all fp16 2-term:
// S = (Qh+Ql).K^T (K single fp16), P.V = (Ph+Pl).V (V single fp16).
// Writes y as fp16 hi/lo for GEMM2.
// ---------------------------------------------------------------------------
__global__ void __launch_bounds__(256) attn_mma() {
    extern __shared__ __align__(16) char sbuf[];
    const uint32_t sb = smem_u32(sbuf);
    const int tid = threadIdx.x;
    const int lane = tid & 31;
    const int w = tid >> 5;
    const int bh = blockIdx.y;
    const int q0 = (int)(gridDim.x - 1 - blockIdx.x) * 128;

    const size_t headoff = (size_t)bh * Tdim * Ddim;
    const int ktmax = (q0 + 127) >> 6;

    const int arow = tid >> 3;
    const int ac8 = (tid & 7) * 8;
    uint4 kh_r[2], vh_r[2];

    auto ldkv = [&](int kt) {
        const size_t base = headoff + (size_t)(kt * 64) * Ddim;
#pragma unroll
        for (int p = 0; p < 2; p++) {
            size_t o = base + (size_t)(arow + 32 * p) * Ddim + ac8;
            kh_r[p] = *(const uint4*)&g_kh2[o];
            vh_r[p] = *(const uint4*)&g_vh2[o];
        }
    };
    auto stkv = [&](uint32_t stOff) {
#pragma unroll
        for (int p = 0; p < 2; p++) {
            uint32_t so = (uint32_t)((arow + 32 * p) * SROWA + ac8) * 2;
            *(uint4*)(sbuf + stOff + 0 * ATILE + so) = kh_r[p];
            *(uint4*)(sbuf + stOff + 1 * ATILE + so) = vh_r[p];
        }
    };

    ldkv(0);
    {
        const uint4* qgh = (const uint4*)(g_qh2 + headoff + (size_t)q0 * Ddim);
        const uint4* qgl = (const uint4*)(g_ql2 + headoff + (size_t)q0 * Ddim);
#pragma unroll
        for (int p = 0; p < 4; p++) {
            int u = p * 256 + tid;
            int row = u >> 3;
            int c8 = (u & 7) * 8;
            uint32_t so = (uint32_t)(row * SROWA + c8) * 2;
            *(uint4*)(sbuf + so) = qgh[u];
            *(uint4*)(sbuf + 18432 + so) = qgl[u];
        }
    }
    __syncthreads();

    uint32_t qh[4][4], ql[4][4];
#pragma unroll
    for (int kk = 0; kk < 4; kk++) {
        uint32_t off = (uint32_t)((16 * w + (lane & 15)) * SROWA + 16 * kk + 8 * (lane >> 4)) * 2;
        ldsm_x4(qh[kk][0], qh[kk][1], qh[kk][2], qh[kk][3], sb + off);
        ldsm_x4(ql[kk][0], ql[kk][1], ql[kk][2], ql[kk][3], sb + 18432 + off);
    }
    __syncthreads();

    stkv(0);
    ldkv(1);
    __syncthreads();

    float oacc[8][4];
#pragma unroll
    for (int j = 0; j < 8; j++)
#pragma unroll
        for (int r = 0; r < 4; r++) oacc[j][r] = 0.f;
    float m1 = -1e30f, m2 = -1e30f, l1 = 0.f, l2 = 0.f;

    const int r1 = q0 + 16 * w + (lane >> 2);
    const int r2 = r1 + 8;

    for (int kt = 0; kt <= ktmax; kt++) {
        const int kbase = kt * 64;
        const int s = kt & 1;
        const uint32_t cur = (uint32_t)s * ASTAGE;
        const uint32_t nxt = (uint32_t)(s ^ 1) * ASTAGE;

        if (kt + 1 <= ktmax) stkv(nxt);
        if (kt + 2 <= ktmax) ldkv(kt + 2);

        const uint32_t oKh = cur + 0 * ATILE;
        const uint32_t oVh = cur + 1 * ATILE;

        // ---- S = Q.K^T (fp16 2-term: Qh.K + Ql.K) ----
        float sacc[8][4];
#pragma unroll
        for (int j = 0; j < 8; j++)
#pragma unroll
            for (int r = 0; r < 4; r++) sacc[j][r] = 0.f;

#pragma unroll
        for (int kk = 0; kk < 4; kk++) {
            uint32_t bk[8][2];
#pragma unroll
            for (int np = 0; np < 4; np++) {
                uint32_t off = (uint32_t)((np * 16 + (lane >> 4) * 8 + (lane & 7)) * SROWA +
                                          ((lane >> 3) & 1) * 8 + 16 * kk) * 2;
                uint32_t t0, t1, t2, t3;
                ldsm_x4(t0, t1, t2, t3, sb + oKh + off);
                bk[2 * np][0] = t0; bk[2 * np][1] = t1;
                bk[2 * np + 1][0] = t2; bk[2 * np + 1][1] = t3;
            }
#pragma unroll
            for (int j = 0; j < 8; j++) mma16816h(sacc[j], qh[kk], bk[j]);
#pragma unroll
            for (int j = 0; j < 8; j++) mma16816h(sacc[j], ql[kk], bk[j]);
        }

        if (kbase + 63 > q0 + 16 * w) {
            const int c0 = kbase + 2 * (lane & 3);
#pragma unroll
            for (int j = 0; j < 8; j++) {
                int cj = c0 + 8 * j;
                if (cj > r1)     sacc[j][0] = -1e30f;
                if (cj + 1 > r1) sacc[j][1] = -1e30f;
                if (cj > r2)     sacc[j][2] = -1e30f;
                if (cj + 1 > r2) sacc[j][3] = -1e30f;
            }
        }

        float t1m = -1e30f, t2m = -1e30f;
#pragma unroll
        for (int j = 0; j < 8; j++) {
            t1m = fmaxf(t1m, fmaxf(sacc[j][0], sacc[j][1]));
            t2m = fmaxf(t2m, fmaxf(sacc[j][2], sacc[j][3]));
        }
        t1m = fmaxf(t1m, __shfl_xor_sync(0xffffffffu, t1m, 1));
        t1m = fmaxf(t1m, __shfl_xor_sync(0xffffffffu, t1m, 2));
        t2m = fmaxf(t2m, __shfl_xor_sync(0xffffffffu, t2m, 1));
        t2m = fmaxf(t2m, __shfl_xor_sync(0xffffffffu, t2m, 2));

        float nm1 = fmaxf(m1, t1m), nm2 = fmaxf(m2, t2m);
        float corr1 = __expf(m1 - nm1), corr2 = __expf(m2 - nm2);
        m1 = nm1; m2 = nm2;

        float s1 = 0.f, s2 = 0.f;
#pragma unroll
        for (int j = 0; j < 8; j++) {
            sacc[j][0] = __expf(sacc[j][0] - m1);
            sacc[j][1] = __expf(sacc[j][1] - m1);
            sacc[j][2] = __expf(sacc[j][2] - m2);
            sacc[j][3] = __expf(sacc[j][3] - m2);
            s1 += sacc[j][0] + sacc[j][1];
            s2 += sacc[j][2] + sacc[j][3];
        }
        s1 += __shfl_xor_sync(0xffffffffu, s1, 1);
        s1 += __shfl_xor_sync(0xffffffffu, s1, 2);
        s2 += __shfl_xor_sync(0xffffffffu, s2, 1);
        s2 += __shfl_xor_sync(0xffffffffu, s2, 2);
        l1 = l1 * corr1 + s1;
        l2 = l2 * corr2 + s2;

        // pack P into fp16 A-fragments (hi/lo)
        uint32_t ph[4][4], pl[4][4];
#pragma unroll
        for (int kk = 0; kk < 4; kk++) {
            int j0 = 2 * kk, j1 = 2 * kk + 1;
            ph[kk][0] = pack2h(sacc[j0][0], sacc[j0][1]);
            ph[kk][1] = pack2h(sacc[j0][2], sacc[j0][3]);
            ph[kk][2] = pack2h(sacc[j1][0], sacc[j1][1]);
            ph[kk][3] = pack2h(sacc[j1][2], sacc[j1][3]);
            pl[kk][0] = pack2h_lo(sacc[j0][0], sacc[j0][1]);
            pl[kk][1] = pack2h_lo(sacc[j0][2], sacc[j0][3]);
            pl[kk][2] = pack2h_lo(sacc[j1][0], sacc[j1][1]);
            pl[kk][3] = pack2h_lo(sacc[j1][2], sacc[j1][3]);
        }

#pragma unroll
        for (int j = 0; j < 8; j++) {
            oacc[j][0] *= corr1; oacc[j][1] *= corr1;
            oacc[j][2] *= corr2; oacc[j][3] *= corr2;
        }

        // ---- O += P.V (fp16 2-term: Ph.V + Pl.V) ----
#pragma unroll
        for (int kk = 0; kk < 4; kk++) {
            uint32_t vb[8][2];
#pragma unroll
            for (int np = 0; np < 4; np++) {
                uint32_t off = (uint32_t)((16 * kk + (lane & 15)) * SROWA +
                                          16 * np + 8 * (lane >> 4)) * 2;
                uint32_t t0, t1, t2, t3;
                ldsm_x4_t(t0, t1, t2, t3, sb + oVh + off);
                vb[2 * np][0] = t0; vb[2 * np][1] = t1;
                vb[2 * np + 1][0] = t2; vb[2 * np + 1][1] = t3;
            }
#pragma unroll
            for (int j = 0; j < 8; j++) mma16816h(oacc[j], ph[kk], vb[j]);
#pragma unroll
            for (int j = 0; j < 8; j++) mma16816h(oacc[j], pl[kk], vb[j]);
        }
        __syncthreads();
    }

    // ---- epilogue: y[B,T,H,D] as fp16 hi/lo ----
    float inv1 = 1.0f / l1, inv2 = 1.0f / l2;
    int b = bh >> 4, h = bh & 15;
    size_t off1 = ((size_t)(b * Tdim + r1) * Hdim + h) * Ddim;
    size_t off2 = ((size_t)(b * Tdim + r2) * Hdim + h) * Ddim;
    int d0 = 2 * (lane & 3);
#pragma unroll
    for (int j = 0; j < 8; j++) {
        float a0 = oacc[j][0] * inv1, a1 = oacc[j][1] * inv1;
        float b0 = oacc[j][2] * inv2, b1 = oacc[j][3] * inv2;
        *(uint32_t*)&g_yh2[off1 + 8 * j + d0] = pack2h(a0, a1);
        *(uint32_t*)&g_yl2[off1 + 8 * j + d0] = pack2h_lo(a0, a1);
        *(uint32_t*)&g_yh2[off2 + 8 * j + d0] = pack2h(b0, b1);
        *(uint32_t*)&g_yl2[off2 + 8 * j + d0] = pack2h_lo(b0, b1);
    }
}

// ---------------------------------------------------------------------------
extern "C" void kernel_launch(void* const* d_in, const int* in_sizes, int n_in,
                              void* d_out, int out_size) {
    const float* x = (const float*)d_in[0];        // [B,T,C]
    const float* w_attn = (const float*)d_in[1];   // [3C,C]
    const float* w_proj = (const float*)d_in[2];   // [C,C]
    float* out = (float*)d_out;                    // [B,T,C]

    __half *xh2, *xl2, *wa, *wp, *yh2, *yl2;
    cudaGetSymbolAddress((void**)&xh2, g_xh2);
    cudaGetSymbolAddress((void**)&xl2, g_xl2);
    cudaGetSymbolAddress((void**)&wa, g_wa);
    cudaGetSymbolAddress((void**)&wp, g_wp);
    cudaGetSymbolAddress((void**)&yh2, g_yh2);
    cudaGetSymbolAddress((void**)&yl2, g_yl2);

    cudaFuncSetAttribute(gemm_h2<0>, cudaFuncAttributeMaxDynamicSharedMemorySize, GSMEM_H);
    cudaFuncSetAttribute(gemm_h2<1>, cudaFuncAttributeMaxDynamicSharedMemorySize, GSMEM_H);
    cudaFuncSetAttribute(attn_mma, cudaFuncAttributeMaxDynamicSharedMemorySize, ASMEM);

    // Pre-pass splits
    const int nx4 = Mrows * Cdim / 4;              // 1M
    const int nwa4 = 3 * Cdim * Cdim / 4;          // 768K
    const int nwp4 = Cdim * Cdim / 4;              // 256K
    split2h_kernel<<<(nx4 + 255) / 256, 256>>>(x, xh2, xl2, nx4);
    round1h_kernel<<<(nwa4 + 255) / 256, 256>>>(w_attn, wa, nwa4);
    round1h_kernel<<<(nwp4 + 255) / 256, 256>>>(w_proj, wp, nwp4);

    // GEMM1: qkv = x @ w_attn^T (fp16 2-term), scatter epilogue
    dim3 g1(3 * Cdim / 256, Mrows / 128);   // (12, 32)
    gemm_h2<1><<<g1, 256, GSMEM_H>>>(xh2, xl2, wa, nullptr, Cdim, 3 * Cdim);

    // Attention
    dim3 ga(Tdim / 128, Bdim * Hdim);       // (16, 32)
    attn_mma<<<ga, 256, ASMEM>>>();

    // GEMM2: out = y @ w_proj^T (fp16 2-term)
    dim3 g2(Cdim / 256, Mrows / 128);       // (4, 32)
    gemm_h2<0><<<g2, 256, GSMEM_H>>>(yh2, yl2, wp, out, Cdim, Cdim);
}

// round 12
// speedup vs baseline: 2.3328x; 1.5979x over previous
#include <cuda_runtime.h>
#include <cuda_fp16.h>
#include <cstdint>
#include <math.h>

// Problem constants
#define Bdim 2
#define Tdim 2048
#define Cdim 1024
#define Hdim 16
#define Ddim 64
#define Mrows (Bdim * Tdim)   // 4096

// Device-global scratch (allocation-free), all single fp16
__device__ __align__(16) __half g_x2[(size_t)Mrows * Cdim];
__device__ __align__(16) __half g_wa[(size_t)3 * Cdim * Cdim];
__device__ __align__(16) __half g_wp[(size_t)Cdim * Cdim];
__device__ __align__(16) __half g_q2[(size_t)Bdim * Hdim * Tdim * Ddim];
__device__ __align__(16) __half g_k2[(size_t)Bdim * Hdim * Tdim * Ddim];
__device__ __align__(16) __half g_v2[(size_t)Bdim * Hdim * Tdim * Ddim];
__device__ __align__(16) __half g_y2[(size_t)Mrows * Cdim];

// ---------------------------------------------------------------------------
// Helpers
// ---------------------------------------------------------------------------
__device__ __forceinline__ uint32_t smem_u32(const void* p) {
    uint32_t a;
    asm("{ .reg .u64 t; cvta.to.shared.u64 t, %1; cvt.u32.u64 %0, t; }" : "=r"(a) : "l"(p));
    return a;
}

__device__ __forceinline__ void ldsm_x4(uint32_t& r0, uint32_t& r1, uint32_t& r2, uint32_t& r3,
                                        uint32_t addr) {
    asm volatile("ldmatrix.sync.aligned.m8n8.x4.shared.b16 {%0,%1,%2,%3}, [%4];"
                 : "=r"(r0), "=r"(r1), "=r"(r2), "=r"(r3) : "r"(addr));
}
__device__ __forceinline__ void ldsm_x4_t(uint32_t& r0, uint32_t& r1, uint32_t& r2, uint32_t& r3,
                                          uint32_t addr) {
    asm volatile("ldmatrix.sync.aligned.m8n8.x4.trans.shared.b16 {%0,%1,%2,%3}, [%4];"
                 : "=r"(r0), "=r"(r1), "=r"(r2), "=r"(r3) : "r"(addr));
}

__device__ __forceinline__ void mma16816h(float* c, const uint32_t* a, const uint32_t* b) {
    asm volatile(
        "mma.sync.aligned.m16n8k16.row.col.f32.f16.f16.f32 "
        "{%0,%1,%2,%3}, {%4,%5,%6,%7}, {%8,%9}, {%0,%1,%2,%3};"
        : "+f"(c[0]), "+f"(c[1]), "+f"(c[2]), "+f"(c[3])
        : "r"(a[0]), "r"(a[1]), "r"(a[2]), "r"(a[3]), "r"(b[0]), "r"(b[1]));
}

__device__ __forceinline__ uint32_t pack2h(float x, float y) {
    __half2 t;
    t.x = __float2half_rn(x);
    t.y = __float2half_rn(y);
    return *reinterpret_cast<uint32_t*>(&t);
}

// cp.async (LDGSTS): global -> smem, 16B, L1-bypass (.cg)
#define CPASYNC(saddr, gptr) \
    asm volatile("cp.async.cg.shared.global [%0], [%1], 16;" :: "r"(saddr), "l"(gptr))
#define CPCOMMIT() asm volatile("cp.async.commit_group;" ::: "memory")
#define CPWAIT1() asm volatile("cp.async.wait_group 1;" ::: "memory")
#define CPWAIT0() asm volatile("cp.async.wait_group 0;" ::: "memory")

#define SROW 40    // GEMM smem row stride (elements; 80B, conflict-free ldmatrix)
#define SROWA 72   // Attention smem row stride (elements)

// fp16 1-term GEMM smem: per stage A (128x32) + B (256x32)
#define GT_A 10240             // 128*40*2
#define GT_B 20480             // 256*40*2
#define GSTAGE1 (GT_A + GT_B)           // 30720
#define GSMEM1 (2 * GSTAGE1)            // 61440

// Attention smem: 2 stages, each K + V (single fp16), 64 rows x SROWA
#define ATILE 9216             // 64*72*2
#define ASTAGE (2 * ATILE)     // 18432
#define ASMEM (2 * ASTAGE)     // 36864

// ---------------------------------------------------------------------------
// Pre-pass: round fp32 -> single fp16
// ---------------------------------------------------------------------------
__global__ void round1h_kernel(const float* __restrict__ src, __half* __restrict__ dst, int n4) {
    int i = blockIdx.x * blockDim.x + threadIdx.x;
    if (i < n4) {
        float4 v = ((const float4*)src)[i];
        ((uint2*)dst)[i] = make_uint2(pack2h(v.x, v.y), pack2h(v.z, v.w));
    }
}

// ---------------------------------------------------------------------------
// fp16 1-term GEMM (NT): C = A @ B^T, both single fp16. CTA 128x256,
// cp.async double-buffered.
// MODE 0: fp32 store to Cout.
// MODE 1: qkv scatter: q (*0.125), k, v -> single fp16 [B,H,T,D].
// ---------------------------------------------------------------------------
template <int MODE>
__global__ void __launch_bounds__(256, 1) gemm_h1(const __half* __restrict__ Ah,
                                                  const __half* __restrict__ Bh,
                                                  float* __restrict__ Cout,
                                                  int K, int N) {
    extern __shared__ __align__(16) char smem[];
    const uint32_t sb = smem_u32(smem);

    const int tid = threadIdx.x;
    const int lane = tid & 31;
    const int wid = tid >> 5;
    const int wm = wid >> 2;
    const int wn = wid & 3;
    const int bm = blockIdx.y * 128;
    const int bn = blockIdx.x * 256;

    const __half* Agh = Ah + (size_t)bm * K;
    const __half* Bgh = Bh + (size_t)bn * K;

    const int nch = K / 32;

    auto issue = [&](int ch, uint32_t st) {
        const int koff = ch * 32;
#pragma unroll
        for (int p = 0; p < 2; p++) {
            int u = tid + 256 * p;
            int row = u >> 2, seg = u & 3;
            uint32_t so = sb + st + (uint32_t)(row * 80 + seg * 16);
            size_t go = (size_t)row * K + koff + seg * 8;
            CPASYNC(so, Agh + go);
        }
#pragma unroll
        for (int p = 0; p < 4; p++) {
            int u = tid + 256 * p;
            int row = u >> 2, seg = u & 3;
            uint32_t so = sb + st + GT_A + (uint32_t)(row * 80 + seg * 16);
            size_t go = (size_t)row * K + koff + seg * 8;
            CPASYNC(so, Bgh + go);
        }
    };

    float acc[4][8][4];
#pragma unroll
    for (int i = 0; i < 4; i++)
#pragma unroll
        for (int j = 0; j < 8; j++)
#pragma unroll
            for (int r = 0; r < 4; r++) acc[i][j][r] = 0.f;

    const uint32_t aOff = (uint32_t)((wm * 64 + (lane & 15)) * SROW + (lane >> 4) * 8) * 2;
    const uint32_t bOff = (uint32_t)((wn * 64 + (lane >> 4) * 8 + (lane & 7)) * SROW +
                                     ((lane >> 3) & 1) * 8) * 2;

    issue(0, 0); CPCOMMIT();
    issue(1, GSTAGE1); CPCOMMIT();
    CPWAIT1();
    __syncthreads();

    for (int ch = 0; ch < nch; ch++) {
        const uint32_t cur = (uint32_t)(ch & 1) * GSTAGE1;
        const uint32_t aB = sb + cur;
        const uint32_t bB = sb + cur + GT_A;

#pragma unroll
        for (int kk = 0; kk < 2; kk++) {
            const uint32_t kByte = (uint32_t)(kk * 16 * 2);
            uint32_t bh[8][2];
#pragma unroll
            for (int jp = 0; jp < 4; jp++) {
                uint32_t o = bOff + kByte + (uint32_t)(jp * 16 * SROW * 2);
                uint32_t t0, t1, t2, t3;
                ldsm_x4(t0, t1, t2, t3, bB + o);
                bh[2 * jp][0] = t0; bh[2 * jp][1] = t1;
                bh[2 * jp + 1][0] = t2; bh[2 * jp + 1][1] = t3;
            }
            uint32_t af[4][4];
#pragma unroll
            for (int i = 0; i < 4; i++)
                ldsm_x4(af[i][0], af[i][1], af[i][2], af[i][3],
                        aB + aOff + kByte + (uint32_t)(i * 16 * SROW * 2));
#pragma unroll
            for (int i = 0; i < 4; i++)
#pragma unroll
                for (int j = 0; j < 8; j++) mma16816h(acc[i][j], af[i], bh[j]);
        }
        __syncthreads();
        if (ch + 1 < nch) {
            if (ch + 2 < nch) { issue(ch + 2, cur); CPCOMMIT(); CPWAIT1(); }
            else { CPWAIT0(); }
            __syncthreads();
        }
    }

    const int lr = lane >> 2;
    const int lc = (lane & 3) * 2;

    if (MODE == 0) {
#pragma unroll
        for (int i = 0; i < 4; i++) {
            int rowA = bm + wm * 64 + i * 16 + lr;
#pragma unroll
            for (int j = 0; j < 8; j++) {
                int col = bn + wn * 64 + j * 8 + lc;
                *(float2*)&Cout[(size_t)rowA * N + col] = make_float2(acc[i][j][0], acc[i][j][1]);
                *(float2*)&Cout[(size_t)(rowA + 8) * N + col] = make_float2(acc[i][j][2], acc[i][j][3]);
            }
        }
    } else {
        // warp covers one head's 64 cols. sdx: 0=q 1=k 2=v
        int col0 = bn + wn * 64;
        int sdx = col0 >> 10;
        int h = (col0 & (Cdim - 1)) >> 6;
        __half* dst = (sdx == 0) ? g_q2 : (sdx == 1) ? g_k2 : g_v2;
        float sc = (sdx == 0) ? 0.125f : 1.0f;
#pragma unroll
        for (int i = 0; i < 4; i++) {
            int rowA = bm + wm * 64 + i * 16 + lr;
#pragma unroll
            for (int hh = 0; hh < 2; hh++) {
                int row = rowA + hh * 8;
                int b = row >> 11;
                int t = row & (Tdim - 1);
                size_t off = ((size_t)(b * Hdim + h) * Tdim + t) * Ddim + lc;
#pragma unroll
                for (int j = 0; j < 8; j++) {
                    *(uint32_t*)&dst[off + j * 8] =
                        pack2h(acc[i][j][hh * 2] * sc, acc[i][j][hh * 2 + 1] * sc);
                }
            }
        }
    }
}

// ---------------------------------------------------------------------------
// Tensor-core causal flash attention, full 1-term fp16:
// S = Q.K^T (single pass), P.V (single pass). Writes y single fp16.
// ---------------------------------------------------------------------------
__global__ void __launch_bounds__(256) attn_mma() {
    extern __shared__ __align__(16) char sbuf[];
    const uint32_t sb = smem_u32(sbuf);
    const int tid = threadIdx.x;
    const int lane = tid & 31;
    const int w = tid >> 5;
    const int bh = blockIdx.y;
    const int q0 = (int)(gridDim.x - 1 - blockIdx.x) * 128;

    const size_t headoff = (size_t)bh * Tdim * Ddim;
    const int ktmax = (q0 + 127) >> 6;

    const int arow = tid >> 3;
    const int ac8 = (tid & 7) * 8;
    uint4 kh_r[2], vh_r[2];

    auto ldkv = [&](int kt) {
        const size_t base = headoff + (size_t)(kt * 64) * Ddim;
#pragma unroll
        for (int p = 0; p < 2; p++) {
            size_t o = base + (size_t)(arow + 32 * p) * Ddim + ac8;
            kh_r[p] = *(const uint4*)&g_k2[o];
            vh_r[p] = *(const uint4*)&g_v2[o];
        }
    };
    auto stkv = [&](uint32_t stOff) {
#pragma unroll
        for (int p = 0; p < 2; p++) {
            uint32_t so = (uint32_t)((arow + 32 * p) * SROWA + ac8) * 2;
            *(uint4*)(sbuf + stOff + 0 * ATILE + so) = kh_r[p];
            *(uint4*)(sbuf + stOff + 1 * ATILE + so) = vh_r[p];
        }
    };

    ldkv(0);
    {
        const uint4* qg = (const uint4*)(g_q2 + headoff + (size_t)q0 * Ddim);
#pragma unroll
        for (int p = 0; p < 4; p++) {
            int u = p * 256 + tid;
            int row = u >> 3;
            int c8 = (u & 7) * 8;
            uint32_t so = (uint32_t)(row * SROWA + c8) * 2;
            *(uint4*)(sbuf + so) = qg[u];
        }
    }
    __syncthreads();

    uint32_t qf[4][4];
#pragma unroll
    for (int kk = 0; kk < 4; kk++) {
        uint32_t off = (uint32_t)((16 * w + (lane & 15)) * SROWA + 16 * kk + 8 * (lane >> 4)) * 2;
        ldsm_x4(qf[kk][0], qf[kk][1], qf[kk][2], qf[kk][3], sb + off);
    }
    __syncthreads();

    stkv(0);
    ldkv(1);
    __syncthreads();

    float oacc[8][4];
#pragma unroll
    for (int j = 0; j < 8; j++)
#pragma unroll
        for (int r = 0; r < 4; r++) oacc[j][r] = 0.f;
    float m1 = -1e30f, m2 = -1e30f, l1 = 0.f, l2 = 0.f;

    const int r1 = q0 + 16 * w + (lane >> 2);
    const int r2 = r1 + 8;

    for (int kt = 0; kt <= ktmax; kt++) {
        const int kbase = kt * 64;
        const int s = kt & 1;
        const uint32_t cur = (uint32_t)s * ASTAGE;
        const uint32_t nxt = (uint32_t)(s ^ 1) * ASTAGE;

        if (kt + 1 <= ktmax) stkv(nxt);
        if (kt + 2 <= ktmax) ldkv(kt + 2);

        const uint32_t oKh = cur + 0 * ATILE;
        const uint32_t oVh = cur + 1 * ATILE;

        // ---- S = Q.K^T (single pass) ----
        float sacc[8][4];
#pragma unroll
        for (int j = 0; j < 8; j++)
#pragma unroll
            for (int r = 0; r < 4; r++) sacc[j][r] = 0.f;

#pragma unroll
        for (int kk = 0; kk < 4; kk++) {
            uint32_t bk[8][2];
#pragma unroll
            for (int np = 0; np < 4; np++) {
                uint32_t off = (uint32_t)((np * 16 + (lane >> 4) * 8 + (lane & 7)) * SROWA +
                                          ((lane >> 3) & 1) * 8 + 16 * kk) * 2;
                uint32_t t0, t1, t2, t3;
                ldsm_x4(t0, t1, t2, t3, sb + oKh + off);
                bk[2 * np][0] = t0; bk[2 * np][1] = t1;
                bk[2 * np + 1][0] = t2; bk[2 * np + 1][1] = t3;
            }
#pragma unroll
            for (int j = 0; j < 8; j++) mma16816h(sacc[j], qf[kk], bk[j]);
        }

        if (kbase + 63 > q0 + 16 * w) {
            const int c0 = kbase + 2 * (lane & 3);
#pragma unroll
            for (int j = 0; j < 8; j++) {
                int cj = c0 + 8 * j;
                if (cj > r1)     sacc[j][0] = -1e30f;
                if (cj + 1 > r1) sacc[j][1] = -1e30f;
                if (cj > r2)     sacc[j][2] = -1e30f;
                if (cj + 1 > r2) sacc[j][3] = -1e30f;
            }
        }

        float t1m = -1e30f, t2m = -1e30f;
#pragma unroll
        for (int j = 0; j < 8; j++) {
            t1m = fmaxf(t1m, fmaxf(sacc[j][0], sacc[j][1]));
            t2m = fmaxf(t2m, fmaxf(sacc[j][2], sacc[j][3]));
        }
        t1m = fmaxf(t1m, __shfl_xor_sync(0xffffffffu, t1m, 1));
        t1m = fmaxf(t1m, __shfl_xor_sync(0xffffffffu, t1m, 2));
        t2m = fmaxf(t2m, __shfl_xor_sync(0xffffffffu, t2m, 1));
        t2m = fmaxf(t2m, __shfl_xor_sync(0xffffffffu, t2m, 2));

        float nm1 = fmaxf(m1, t1m), nm2 = fmaxf(m2, t2m);
        float corr1 = __expf(m1 - nm1), corr2 = __expf(m2 - nm2);
        m1 = nm1; m2 = nm2;

        float s1 = 0.f, s2 = 0.f;
#pragma unroll
        for (int j = 0; j < 8; j++) {
            sacc[j][0] = __expf(sacc[j][0] - m1);
            sacc[j][1] = __expf(sacc[j][1] - m1);
            sacc[j][2] = __expf(sacc[j][2] - m2);
            sacc[j][3] = __expf(sacc[j][3] - m2);
            s1 += sacc[j][0] + sacc[j][1];
            s2 += sacc[j][2] + sacc[j][3];
        }
        s1 += __shfl_xor_sync(0xffffffffu, s1, 1);
        s1 += __shfl_xor_sync(0xffffffffu, s1, 2);
        s2 += __shfl_xor_sync(0xffffffffu, s2, 1);
        s2 += __shfl_xor_sync(0xffffffffu, s2, 2);
        l1 = l1 * corr1 + s1;
        l2 = l2 * corr2 + s2;

        // pack P into fp16 A-fragments (single)
        uint32_t ph[4][4];
#pragma unroll
        for (int kk = 0; kk < 4; kk++) {
            int j0 = 2 * kk, j1 = 2 * kk + 1;
            ph[kk][0] = pack2h(sacc[j0][0], sacc[j0][1]);
            ph[kk][1] = pack2h(sacc[j0][2], sacc[j0][3]);
            ph[kk][2] = pack2h(sacc[j1][0], sacc[j1][1]);
            ph[kk][3] = pack2h(sacc[j1][2], sacc[j1][3]);
        }

#pragma unroll
        for (int j = 0; j < 8; j++) {
            oacc[j][0] *= corr1; oacc[j][1] *= corr1;
            oacc[j][2] *= corr2; oacc[j][3] *= corr2;
        }

        // ---- O += P.V (single pass) ----
#pragma unroll
        for (int kk = 0; kk < 4; kk++) {
            uint32_t vb[8][2];
#pragma unroll
            for (int np = 0; np < 4; np++) {
                uint32_t off = (uint32_t)((16 * kk + (lane & 15)) * SROWA +
                                          16 * np + 8 * (lane >> 4)) * 2;
                uint32_t t0, t1, t2, t3;
                ldsm_x4_t(t0, t1, t2, t3, sb + oVh + off);
                vb[2 * np][0] = t0; vb[2 * np][1] = t1;
                vb[2 * np + 1][0] = t2; vb[2 * np + 1][1] = t3;
            }
#pragma unroll
            for (int j = 0; j < 8; j++) mma16816h(oacc[j], ph[kk], vb[j]);
        }
        __syncthreads();
    }

    // ---- epilogue: y[B,T,H,D] single fp16 ----
    float inv1 = 1.0f / l1, inv2 = 1.0f / l2;
    int b = bh >> 4, h = bh & 15;
    size_t off1 = ((size_t)(b * Tdim + r1) * Hdim + h) * Ddim;
    size_t off2 = ((size_t)(b * Tdim + r2) * Hdim + h) * Ddim;
    int d0 = 2 * (lane & 3);
#pragma unroll
    for (int j = 0; j < 8; j++) {
        *(uint32_t*)&g_y2[off1 + 8 * j + d0] = pack2h(oacc[j][0] * inv1, oacc[j][1] * inv1);
        *(uint32_t*)&g_y2[off2 + 8 * j + d0] = pack2h(oacc[j][2] * inv2, oacc[j][3] * inv2);
    }
}

// ---------------------------------------------------------------------------
extern "C" void kernel_launch(void* const* d_in, const int* in_sizes, int n_in,
                              void* d_out, int out_size) {
    const float* x = (const float*)d_in[0];        // [B,T,C]
    const float* w_attn = (const float*)d_in[1];   // [3C,C]
    const float* w_proj = (const float*)d_in[2];   // [C,C]
    float* out = (float*)d_out;                    // [B,T,C]

    __half *x2, *wa, *wp, *y2;
    cudaGetSymbolAddress((void**)&x2, g_x2);
    cudaGetSymbolAddress((void**)&wa, g_wa);
    cudaGetSymbolAddress((void**)&wp, g_wp);
    cudaGetSymbolAddress((void**)&y2, g_y2);

    cudaFuncSetAttribute(gemm_h1<0>, cudaFuncAttributeMaxDynamicSharedMemorySize, GSMEM1);
    cudaFuncSetAttribute(gemm_h1<1>, cudaFuncAttributeMaxDynamicSharedMemorySize, GSMEM1);
    cudaFuncSetAttribute(attn_mma, cudaFuncAttributeMaxDynamicSharedMemorySize, ASMEM);

    // Pre-pass: round inputs to fp16
    const int nx4 = Mrows * Cdim / 4;              // 1M
    const int nwa4 = 3 * Cdim * Cdim / 4;          // 768K
    const int nwp4 = Cdim * Cdim / 4;              // 256K
    round1h_kernel<<<(nx4 + 255) / 256, 256>>>(x, x2, nx4);
    round1h_kernel<<<(nwa4 + 255) / 256, 256>>>(w_attn, wa, nwa4);
    round1h_kernel<<<(nwp4 + 255) / 256, 256>>>(w_proj, wp, nwp4);

    // GEMM1: qkv = x @ w_attn^T (fp16 1-term), scatter epilogue
    dim3 g1(3 * Cdim / 256, Mrows / 128);   // (12, 32)
    gemm_h1<1><<<g1, 256, GSMEM1>>>(x2, wa, nullptr, Cdim, 3 * Cdim);

    // Attention
    dim3 ga(Tdim / 128, Bdim * Hdim);       // (16, 32)
    attn_mma<<<ga, 256, ASMEM>>>();

    // GEMM2: out = y @ w_proj^T (fp16 1-term)
    dim3 g2(Cdim / 256, Mrows / 128);       // (4, 32)
    gemm_h1<0><<<g2, 256, GSMEM1>>>(y2, wp, out, Cdim, Cdim);
}

// round 13
// speedup vs baseline: 2.3795x; 1.0200x over previous
#include <cuda_runtime.h>
#include <cuda_fp16.h>
#include <cstdint>
#include <math.h>

// Problem constants
#define Bdim 2
#define Tdim 2048
#define Cdim 1024
#define Hdim 16
#define Ddim 64
#define Mrows (Bdim * Tdim)   // 4096

// Device-global scratch (allocation-free), all single fp16
__device__ __align__(16) __half g_x2[(size_t)Mrows * Cdim];
__device__ __align__(16) __half g_wa[(size_t)3 * Cdim * Cdim];
__device__ __align__(16) __half g_wp[(size_t)Cdim * Cdim];
__device__ __align__(16) __half g_q2[(size_t)Bdim * Hdim * Tdim * Ddim];
__device__ __align__(16) __half g_k2[(size_t)Bdim * Hdim * Tdim * Ddim];
__device__ __align__(16) __half g_v2[(size_t)Bdim * Hdim * Tdim * Ddim];
__device__ __align__(16) __half g_y2[(size_t)Mrows * Cdim];

// ---------------------------------------------------------------------------
// Helpers
// ---------------------------------------------------------------------------
__device__ __forceinline__ uint32_t smem_u32(const void* p) {
    uint32_t a;
    asm("{ .reg .u64 t; cvta.to.shared.u64 t, %1; cvt.u32.u64 %0, t; }" : "=r"(a) : "l"(p));
    return a;
}

__device__ __forceinline__ void ldsm_x4(uint32_t& r0, uint32_t& r1, uint32_t& r2, uint32_t& r3,
                                        uint32_t addr) {
    asm volatile("ldmatrix.sync.aligned.m8n8.x4.shared.b16 {%0,%1,%2,%3}, [%4];"
                 : "=r"(r0), "=r"(r1), "=r"(r2), "=r"(r3) : "r"(addr));
}
__device__ __forceinline__ void ldsm_x4_t(uint32_t& r0, uint32_t& r1, uint32_t& r2, uint32_t& r3,
                                          uint32_t addr) {
    asm volatile("ldmatrix.sync.aligned.m8n8.x4.trans.shared.b16 {%0,%1,%2,%3}, [%4];"
                 : "=r"(r0), "=r"(r1), "=r"(r2), "=r"(r3) : "r"(addr));
}

__device__ __forceinline__ void mma16816h(float* c, const uint32_t* a, const uint32_t* b) {
    asm volatile(
        "mma.sync.aligned.m16n8k16.row.col.f32.f16.f16.f32 "
        "{%0,%1,%2,%3}, {%4,%5,%6,%7}, {%8,%9}, {%0,%1,%2,%3};"
        : "+f"(c[0]), "+f"(c[1]), "+f"(c[2]), "+f"(c[3])
        : "r"(a[0]), "r"(a[1]), "r"(a[2]), "r"(a[3]), "r"(b[0]), "r"(b[1]));
}

__device__ __forceinline__ uint32_t pack2h(float x, float y) {
    __half2 t;
    t.x = __float2half_rn(x);
    t.y = __float2half_rn(y);
    return *reinterpret_cast<uint32_t*>(&t);
}

// cp.async (LDGSTS): global -> smem, 16B, L1-bypass (.cg)
#define CPASYNC(saddr, gptr) \
    asm volatile("cp.async.cg.shared.global [%0], [%1], 16;" :: "r"(saddr), "l"(gptr))
#define CPCOMMIT() asm volatile("cp.async.commit_group;" ::: "memory")
#define CPWAIT1() asm volatile("cp.async.wait_group 1;" ::: "memory")
#define CPWAIT0() asm volatile("cp.async.wait_group 0;" ::: "memory")

#define SROW 40    // GEMM smem row stride (elements; 80B, conflict-free ldmatrix)
#define SROWA 72   // Attention smem row stride (elements)

// fp16 1-term GEMM smem: CTA tile 128x128; per stage A (128x32) + B (128x32)
#define GT 10240               // 128*40*2
#define GSTAGE1 (2 * GT)       // 20480
#define GSMEM1 (2 * GSTAGE1)   // 40960  (2 CTAs/SM -> 80KB)

// Attention smem: 2 stages, each K + V (single fp16), 64 rows x SROWA
#define ATILE 9216             // 64*72*2
#define ASTAGE (2 * ATILE)     // 18432
#define ASMEM (2 * ASTAGE)     // 36864

// ---------------------------------------------------------------------------
// Pre-pass: round fp32 -> single fp16
// ---------------------------------------------------------------------------
__global__ void round1h_kernel(const float* __restrict__ src, __half* __restrict__ dst, int n4) {
    int i = blockIdx.x * blockDim.x + threadIdx.x;
    if (i < n4) {
        float4 v = ((const float4*)src)[i];
        ((uint2*)dst)[i] = make_uint2(pack2h(v.x, v.y), pack2h(v.z, v.w));
    }
}

// ---------------------------------------------------------------------------
// fp16 1-term GEMM (NT): C = A @ B^T. CTA 128x128, warp 64x32, 2 CTAs/SM,
// cp.async double-buffered.
// MODE 0: fp32 store. MODE 1: qkv scatter (q*0.125, k, v single fp16 [B,H,T,D]).
// ---------------------------------------------------------------------------
template <int MODE>
__global__ void __launch_bounds__(256, 2) gemm_h1(const __half* __restrict__ Ah,
                                                  const __half* __restrict__ Bh,
                                                  float* __restrict__ Cout,
                                                  int K, int N) {
    extern __shared__ __align__(16) char smem[];
    const uint32_t sb = smem_u32(smem);

    const int tid = threadIdx.x;
    const int lane = tid & 31;
    const int wid = tid >> 5;
    const int wm = wid >> 2;        // 0..1 (64 rows)
    const int wn = wid & 3;         // 0..3 (32 cols)
    const int bm = blockIdx.y * 128;
    const int bn = blockIdx.x * 128;

    const __half* Agh = Ah + (size_t)bm * K;
    const __half* Bgh = Bh + (size_t)bn * K;

    const int nch = K / 32;

    auto issue = [&](int ch, uint32_t st) {
        const int koff = ch * 32;
#pragma unroll
        for (int p = 0; p < 2; p++) {          // A: 128 rows x 4 segs
            int u = tid + 256 * p;
            int row = u >> 2, seg = u & 3;
            uint32_t so = sb + st + (uint32_t)(row * 80 + seg * 16);
            size_t go = (size_t)row * K + koff + seg * 8;
            CPASYNC(so, Agh + go);
        }
#pragma unroll
        for (int p = 0; p < 2; p++) {          // B: 128 rows x 4 segs
            int u = tid + 256 * p;
            int row = u >> 2, seg = u & 3;
            uint32_t so = sb + st + GT + (uint32_t)(row * 80 + seg * 16);
            size_t go = (size_t)row * K + koff + seg * 8;
            CPASYNC(so, Bgh + go);
        }
    };

    float acc[4][4][4];
#pragma unroll
    for (int i = 0; i < 4; i++)
#pragma unroll
        for (int j = 0; j < 4; j++)
#pragma unroll
            for (int r = 0; r < 4; r++) acc[i][j][r] = 0.f;

    const uint32_t aOff = (uint32_t)((wm * 64 + (lane & 15)) * SROW + (lane >> 4) * 8) * 2;
    const uint32_t bOff = (uint32_t)((wn * 32 + (lane >> 4) * 8 + (lane & 7)) * SROW +
                                     ((lane >> 3) & 1) * 8) * 2;

    issue(0, 0); CPCOMMIT();
    issue(1, GSTAGE1); CPCOMMIT();
    CPWAIT1();
    __syncthreads();

    for (int ch = 0; ch < nch; ch++) {
        const uint32_t cur = (uint32_t)(ch & 1) * GSTAGE1;
        const uint32_t aB = sb + cur;
        const uint32_t bB = sb + cur + GT;

#pragma unroll
        for (int kk = 0; kk < 2; kk++) {
            const uint32_t kByte = (uint32_t)(kk * 16 * 2);
            uint32_t bh[4][2];
#pragma unroll
            for (int jp = 0; jp < 2; jp++) {
                uint32_t o = bOff + kByte + (uint32_t)(jp * 16 * SROW * 2);
                uint32_t t0, t1, t2, t3;
                ldsm_x4(t0, t1, t2, t3, bB + o);
                bh[2 * jp][0] = t0; bh[2 * jp][1] = t1;
                bh[2 * jp + 1][0] = t2; bh[2 * jp + 1][1] = t3;
            }
            uint32_t af[4][4];
#pragma unroll
            for (int i = 0; i < 4; i++)
                ldsm_x4(af[i][0], af[i][1], af[i][2], af[i][3],
                        aB + aOff + kByte + (uint32_t)(i * 16 * SROW * 2));
#pragma unroll
            for (int i = 0; i < 4; i++)
#pragma unroll
                for (int j = 0; j < 4; j++) mma16816h(acc[i][j], af[i], bh[j]);
        }
        __syncthreads();
        if (ch + 1 < nch) {
            if (ch + 2 < nch) { issue(ch + 2, cur); CPCOMMIT(); CPWAIT1(); }
            else { CPWAIT0(); }
            __syncthreads();
        }
    }

    const int lr = lane >> 2;
    const int lc = (lane & 3) * 2;

    if (MODE == 0) {
#pragma unroll
        for (int i = 0; i < 4; i++) {
            int rowA = bm + wm * 64 + i * 16 + lr;
#pragma unroll
            for (int j = 0; j < 4; j++) {
                int col = bn + wn * 32 + j * 8 + lc;
                *(float2*)&Cout[(size_t)rowA * N + col] = make_float2(acc[i][j][0], acc[i][j][1]);
                *(float2*)&Cout[(size_t)(rowA + 8) * N + col] = make_float2(acc[i][j][2], acc[i][j][3]);
            }
        }
    } else {
        // warp covers 32 cols inside one head block
        int col0 = bn + wn * 32;
        int sdx = col0 >> 10;               // 0=q 1=k 2=v
        int rr = col0 & (Cdim - 1);
        int h = rr >> 6;
        int d0 = (rr & (Ddim - 1)) + lc;
        __half* dst = (sdx == 0) ? g_q2 : (sdx == 1) ? g_k2 : g_v2;
        float sc = (sdx == 0) ? 0.125f : 1.0f;
#pragma unroll
        for (int i = 0; i < 4; i++) {
            int rowA = bm + wm * 64 + i * 16 + lr;
#pragma unroll
            for (int hh = 0; hh < 2; hh++) {
                int row = rowA + hh * 8;
                int b = row >> 11;
                int t = row & (Tdim - 1);
                size_t off = ((size_t)(b * Hdim + h) * Tdim + t) * Ddim + d0;
#pragma unroll
                for (int j = 0; j < 4; j++) {
                    *(uint32_t*)&dst[off + j * 8] =
                        pack2h(acc[i][j][hh * 2] * sc, acc[i][j][hh * 2 + 1] * sc);
                }
            }
        }
    }
}

// ---------------------------------------------------------------------------
// Tensor-core causal flash attention, 1-term fp16, 2 CTAs/SM.
// ---------------------------------------------------------------------------
__global__ void __launch_bounds__(256, 2) attn_mma() {
    extern __shared__ __align__(16) char sbuf[];
    const uint32_t sb = smem_u32(sbuf);
    const int tid = threadIdx.x;
    const int lane = tid & 31;
    const int w = tid >> 5;
    const int bh = blockIdx.y;
    const int q0 = (int)(gridDim.x - 1 - blockIdx.x) * 128;

    const size_t headoff = (size_t)bh * Tdim * Ddim;
    const int ktmax = (q0 + 127) >> 6;

    const int arow = tid >> 3;
    const int ac8 = (tid & 7) * 8;
    uint4 kh_r[2], vh_r[2];

    auto ldkv = [&](int kt) {
        const size_t base = headoff + (size_t)(kt * 64) * Ddim;
#pragma unroll
        for (int p = 0; p < 2; p++) {
            size_t o = base + (size_t)(arow + 32 * p) * Ddim + ac8;
            kh_r[p] = *(const uint4*)&g_k2[o];
            vh_r[p] = *(const uint4*)&g_v2[o];
        }
    };
    auto stkv = [&](uint32_t stOff) {
#pragma unroll
        for (int p = 0; p < 2; p++) {
            uint32_t so = (uint32_t)((arow + 32 * p) * SROWA + ac8) * 2;
            *(uint4*)(sbuf + stOff + 0 * ATILE + so) = kh_r[p];
            *(uint4*)(sbuf + stOff + 1 * ATILE + so) = vh_r[p];
        }
    };

    ldkv(0);
    {
        const uint4* qg = (const uint4*)(g_q2 + headoff + (size_t)q0 * Ddim);
#pragma unroll
        for (int p = 0; p < 4; p++) {
            int u = p * 256 + tid;
            int row = u >> 3;
            int c8 = (u & 7) * 8;
            uint32_t so = (uint32_t)(row * SROWA + c8) * 2;
            *(uint4*)(sbuf + so) = qg[u];
        }
    }
    __syncthreads();

    uint32_t qf[4][4];
#pragma unroll
    for (int kk = 0; kk < 4; kk++) {
        uint32_t off = (uint32_t)((16 * w + (lane & 15)) * SROWA + 16 * kk + 8 * (lane >> 4)) * 2;
        ldsm_x4(qf[kk][0], qf[kk][1], qf[kk][2], qf[kk][3], sb + off);
    }
    __syncthreads();

    stkv(0);
    ldkv(1);
    __syncthreads();

    float oacc[8][4];
#pragma unroll
    for (int j = 0; j < 8; j++)
#pragma unroll
        for (int r = 0; r < 4; r++) oacc[j][r] = 0.f;
    float m1 = -1e30f, m2 = -1e30f, l1 = 0.f, l2 = 0.f;

    const int r1 = q0 + 16 * w + (lane >> 2);
    const int r2 = r1 + 8;

    for (int kt = 0; kt <= ktmax; kt++) {
        const int kbase = kt * 64;
        const int s = kt & 1;
        const uint32_t cur = (uint32_t)s * ASTAGE;
        const uint32_t nxt = (uint32_t)(s ^ 1) * ASTAGE;

        if (kt + 1 <= ktmax) stkv(nxt);
        if (kt + 2 <= ktmax) ldkv(kt + 2);

        const uint32_t oKh = cur + 0 * ATILE;
        const uint32_t oVh = cur + 1 * ATILE;

        // ---- S = Q.K^T ----
        float sacc[8][4];
#pragma unroll
        for (int j = 0; j < 8; j++)
#pragma unroll
            for (int r = 0; r < 4; r++) sacc[j][r] = 0.f;

#pragma unroll
        for (int kk = 0; kk < 4; kk++) {
            uint32_t bk[8][2];
#pragma unroll
            for (int np = 0; np < 4; np++) {
                uint32_t off = (uint32_t)((np * 16 + (lane >> 4) * 8 + (lane & 7)) * SROWA +
                                          ((lane >> 3) & 1) * 8 + 16 * kk) * 2;
                uint32_t t0, t1, t2, t3;
                ldsm_x4(t0, t1, t2, t3, sb + oKh + off);
                bk[2 * np][0] = t0; bk[2 * np][1] = t1;
                bk[2 * np + 1][0] = t2; bk[2 * np + 1][1] = t3;
            }
#pragma unroll
            for (int j = 0; j < 8; j++) mma16816h(sacc[j], qf[kk], bk[j]);
        }

        if (kbase + 63 > q0 + 16 * w) {
            const int c0 = kbase + 2 * (lane & 3);
#pragma unroll
            for (int j = 0; j < 8; j++) {
                int cj = c0 + 8 * j;
                if (cj > r1)     sacc[j][0] = -1e30f;
                if (cj + 1 > r1) sacc[j][1] = -1e30f;
                if (cj > r2)     sacc[j][2] = -1e30f;
                if (cj + 1 > r2) sacc[j][3] = -1e30f;
            }
        }

        float t1m = -1e30f, t2m = -1e30f;
#pragma unroll
        for (int j = 0; j < 8; j++) {
            t1m = fmaxf(t1m, fmaxf(sacc[j][0], sacc[j][1]));
            t2m = fmaxf(t2m, fmaxf(sacc[j][2], sacc[j][3]));
        }
        t1m = fmaxf(t1m, __shfl_xor_sync(0xffffffffu, t1m, 1));
        t1m = fmaxf(t1m, __shfl_xor_sync(0xffffffffu, t1m, 2));
        t2m = fmaxf(t2m, __shfl_xor_sync(0xffffffffu, t2m, 1));
        t2m = fmaxf(t2m, __shfl_xor_sync(0xffffffffu, t2m, 2));

        float nm1 = fmaxf(m1, t1m), nm2 = fmaxf(m2, t2m);
        float corr1 = __expf(m1 - nm1), corr2 = __expf(m2 - nm2);
        m1 = nm1; m2 = nm2;

        float s1 = 0.f, s2 = 0.f;
#pragma unroll
        for (int j = 0; j < 8; j++) {
            sacc[j][0] = __expf(sacc[j][0] - m1);
            sacc[j][1] = __expf(sacc[j][1] - m1);
            sacc[j][2] = __expf(sacc[j][2] - m2);
            sacc[j][3] = __expf(sacc[j][3] - m2);
            s1 += sacc[j][0] + sacc[j][1];
            s2 += sacc[j][2] + sacc[j][3];
        }
        s1 += __shfl_xor_sync(0xffffffffu, s1, 1);
        s1 += __shfl_xor_sync(0xffffffffu, s1, 2);
        s2 += __shfl_xor_sync(0xffffffffu, s2, 1);
        s2 += __shfl_xor_sync(0xffffffffu, s2, 2);
        l1 = l1 * corr1 + s1;
        l2 = l2 * corr2 + s2;

        // pack P into fp16 A-fragments
        uint32_t ph[4][4];
#pragma unroll
        for (int kk = 0; kk < 4; kk++) {
            int j0 = 2 * kk, j1 = 2 * kk + 1;
            ph[kk][0] = pack2h(sacc[j0][0], sacc[j0][1]);
            ph[kk][1] = pack2h(sacc[j0][2], sacc[j0][3]);
            ph[kk][2] = pack2h(sacc[j1][0], sacc[j1][1]);
            ph[kk][3] = pack2h(sacc[j1][2], sacc[j1][3]);
        }

#pragma unroll
        for (int j = 0; j < 8; j++) {
            oacc[j][0] *= corr1; oacc[j][1] *= corr1;
            oacc[j][2] *= corr2; oacc[j][3] *= corr2;
        }

        // ---- O += P.V ----
#pragma unroll
        for (int kk = 0; kk < 4; kk++) {
            uint32_t vb[8][2];
#pragma unroll
            for (int np = 0; np < 4; np++) {
                uint32_t off = (uint32_t)((16 * kk + (lane & 15)) * SROWA +
                                          16 * np + 8 * (lane >> 4)) * 2;
                uint32_t t0, t1, t2, t3;
                ldsm_x4_t(t0, t1, t2, t3, sb + oVh + off);
                vb[2 * np][0] = t0; vb[2 * np][1] = t1;
                vb[2 * np + 1][0] = t2; vb[2 * np + 1][1] = t3;
            }
#pragma unroll
            for (int j = 0; j < 8; j++) mma16816h(oacc[j], ph[kk], vb[j]);
        }
        __syncthreads();
    }

    // ---- epilogue: y[B,T,H,D] single fp16 ----
    float inv1 = 1.0f / l1, inv2 = 1.0f / l2;
    int b = bh >> 4, h = bh & 15;
    size_t off1 = ((size_t)(b * Tdim + r1) * Hdim + h) * Ddim;
    size_t off2 = ((size_t)(b * Tdim + r2) * Hdim + h) * Ddim;
    int d0 = 2 * (lane & 3);
#pragma unroll
    for (int j = 0; j < 8; j++) {
        *(uint32_t*)&g_y2[off1 + 8 * j + d0] = pack2h(oacc[j][0] * inv1, oacc[j][1] * inv1);
        *(uint32_t*)&g_y2[off2 + 8 * j + d0] = pack2h(oacc[j][2] * inv2, oacc[j][3] * inv2);
    }
}

// ---------------------------------------------------------------------------
extern "C" void kernel_launch(void* const* d_in, const int* in_sizes, int n_in,
                              void* d_out, int out_size) {
    const float* x = (const float*)d_in[0];        // [B,T,C]
    const float* w_attn = (const float*)d_in[1];   // [3C,C]
    const float* w_proj = (const float*)d_in[2];   // [C,C]
    float* out = (float*)d_out;                    // [B,T,C]

    __half *x2, *wa, *wp, *y2;
    cudaGetSymbolAddress((void**)&x2, g_x2);
    cudaGetSymbolAddress((void**)&wa, g_wa);
    cudaGetSymbolAddress((void**)&wp, g_wp);
    cudaGetSymbolAddress((void**)&y2, g_y2);

    cudaFuncSetAttribute(gemm_h1<0>, cudaFuncAttributeMaxDynamicSharedMemorySize, GSMEM1);
    cudaFuncSetAttribute(gemm_h1<1>, cudaFuncAttributeMaxDynamicSharedMemorySize, GSMEM1);
    cudaFuncSetAttribute(attn_mma, cudaFuncAttributeMaxDynamicSharedMemorySize, ASMEM);

    // Pre-pass: round inputs to fp16
    const int nx4 = Mrows * Cdim / 4;              // 1M
    const int nwa4 = 3 * Cdim * Cdim / 4;          // 768K
    const int nwp4 = Cdim * Cdim / 4;              // 256K
    round1h_kernel<<<(nx4 + 255) / 256, 256>>>(x, x2, nx4);
    round1h_kernel<<<(nwa4 + 255) / 256, 256>>>(w_attn, wa, nwa4);
    round1h_kernel<<<(nwp4 + 255) / 256, 256>>>(w_proj, wp, nwp4);

    // GEMM1: qkv = x @ w_attn^T (fp16 1-term), scatter epilogue
    dim3 g1(3 * Cdim / 128, Mrows / 128);   // (24, 32)
    gemm_h1<1><<<g1, 256, GSMEM1>>>(x2, wa, nullptr, Cdim, 3 * Cdim);

    // Attention
    dim3 ga(Tdim / 128, Bdim * Hdim);       // (16, 32)
    attn_mma<<<ga, 256, ASMEM>>>();

    // GEMM2: out = y @ w_proj^T (fp16 1-term)
    dim3 g2(Cdim / 128, Mrows / 128);       // (8, 32)
    gemm_h1<0><<<g2, 256, GSMEM1>>>(y2, wp, out, Cdim, Cdim);
}

// round 14
// speedup vs baseline: 2.7268x; 1.1459x over previous
#include <cuda_runtime.h>
#include <cuda_fp16.h>
#include <cstdint>
#include <math.h>

// Problem constants
#define Bdim 2
#define Tdim 2048
#define Cdim 1024
#define Hdim 16
#define Ddim 64
#define Mrows (Bdim * Tdim)   // 4096

// Device-global scratch (allocation-free), all single fp16
__device__ __align__(16) __half g_x2[(size_t)Mrows * Cdim];
__device__ __align__(16) __half g_wa[(size_t)3 * Cdim * Cdim];
__device__ __align__(16) __half g_wp[(size_t)Cdim * Cdim];
__device__ __align__(16) __half g_q2[(size_t)Bdim * Hdim * Tdim * Ddim];
__device__ __align__(16) __half g_k2[(size_t)Bdim * Hdim * Tdim * Ddim];
__device__ __align__(16) __half g_v2[(size_t)Bdim * Hdim * Tdim * Ddim];
__device__ __align__(16) __half g_y2[(size_t)Mrows * Cdim];

// ---------------------------------------------------------------------------
// Helpers
// ---------------------------------------------------------------------------
__device__ __forceinline__ uint32_t smem_u32(const void* p) {
    uint32_t a;
    asm("{ .reg .u64 t; cvta.to.shared.u64 t, %1; cvt.u32.u64 %0, t; }" : "=r"(a) : "l"(p));
    return a;
}

__device__ __forceinline__ void ldsm_x4(uint32_t& r0, uint32_t& r1, uint32_t& r2, uint32_t& r3,
                                        uint32_t addr) {
    asm volatile("ldmatrix.sync.aligned.m8n8.x4.shared.b16 {%0,%1,%2,%3}, [%4];"
                 : "=r"(r0), "=r"(r1), "=r"(r2), "=r"(r3) : "r"(addr));
}
__device__ __forceinline__ void ldsm_x4_t(uint32_t& r0, uint32_t& r1, uint32_t& r2, uint32_t& r3,
                                          uint32_t addr) {
    asm volatile("ldmatrix.sync.aligned.m8n8.x4.trans.shared.b16 {%0,%1,%2,%3}, [%4];"
                 : "=r"(r0), "=r"(r1), "=r"(r2), "=r"(r3) : "r"(addr));
}

__device__ __forceinline__ void mma16816h(float* c, const uint32_t* a, const uint32_t* b) {
    asm volatile(
        "mma.sync.aligned.m16n8k16.row.col.f32.f16.f16.f32 "
        "{%0,%1,%2,%3}, {%4,%5,%6,%7}, {%8,%9}, {%0,%1,%2,%3};"
        : "+f"(c[0]), "+f"(c[1]), "+f"(c[2]), "+f"(c[3])
        : "r"(a[0]), "r"(a[1]), "r"(a[2]), "r"(a[3]), "r"(b[0]), "r"(b[1]));
}

__device__ __forceinline__ uint32_t pack2h(float x, float y) {
    __half2 t;
    t.x = __float2half_rn(x);
    t.y = __float2half_rn(y);
    return *reinterpret_cast<uint32_t*>(&t);
}

// cp.async (LDGSTS): global -> smem, 16B, L1-bypass (.cg)
#define CPASYNC(saddr, gptr) \
    asm volatile("cp.async.cg.shared.global [%0], [%1], 16;" :: "r"(saddr), "l"(gptr))
#define CPCOMMIT() asm volatile("cp.async.commit_group;" ::: "memory")
#define CPWAIT1() asm volatile("cp.async.wait_group 1;" ::: "memory")
#define CPWAIT0() asm volatile("cp.async.wait_group 0;" ::: "memory")

#define SROWG 72   // GEMM smem row stride (elements; 144B, conflict-free ldmatrix)
#define SROWA 72   // Attention smem row stride (elements)

// fp16 1-term GEMM smem: CTA tile 128x128, K-chunk 64; per stage A + B (128x72)
#define GT64 18432             // 128*72*2
#define GSTG (2 * GT64)        // 36864
#define GSM64 (2 * GSTG)       // 73728  (2 CTAs/SM -> 147KB)

// Attention smem: 2 stages, each K + V (single fp16), 64 rows x SROWA
#define ATILE 9216             // 64*72*2
#define ASTAGE (2 * ATILE)     // 18432
#define ASMEM (2 * ASTAGE)     // 36864

// ---------------------------------------------------------------------------
// Fused pre-pass: round all three fp32 arrays to fp16 in one launch.
// ---------------------------------------------------------------------------
#define NX4 (Mrows * Cdim / 4)            // 1048576
#define NWA4 (3 * Cdim * Cdim / 4)        // 786432
#define NWP4 (Cdim * Cdim / 4)            // 262144

__global__ void round_all_kernel(const float* __restrict__ x, const float* __restrict__ wa,
                                 const float* __restrict__ wp, __half* __restrict__ dx,
                                 __half* __restrict__ dwa, __half* __restrict__ dwp) {
    int i = blockIdx.x * blockDim.x + threadIdx.x;
    const float4* s;
    uint2* d;
    int j;
    if (i < NX4) { s = (const float4*)x; d = (uint2*)dx; j = i; }
    else if (i < NX4 + NWA4) { s = (const float4*)wa; d = (uint2*)dwa; j = i - NX4; }
    else if (i < NX4 + NWA4 + NWP4) { s = (const float4*)wp; d = (uint2*)dwp; j = i - NX4 - NWA4; }
    else return;
    float4 v = s[j];
    d[j] = make_uint2(pack2h(v.x, v.y), pack2h(v.z, v.w));
}

// ---------------------------------------------------------------------------
// fp16 1-term GEMM (NT): C = A @ B^T. CTA 128x128, warp 64x32, K-chunk 64,
// 2 CTAs/SM, cp.async double-buffered. 2 syncs per 64-wide chunk (16 chunks).
// MODE 0: fp32 store. MODE 1: qkv scatter (q*0.125, k, v single fp16 [B,H,T,D]).
// ---------------------------------------------------------------------------
template <int MODE>
__global__ void __launch_bounds__(256, 2) gemm_h1(const __half* __restrict__ Ah,
                                                  const __half* __restrict__ Bh,
                                                  float* __restrict__ Cout,
                                                  int K, int N) {
    extern __shared__ __align__(16) char smem[];
    const uint32_t sb = smem_u32(smem);

    const int tid = threadIdx.x;
    const int lane = tid & 31;
    const int wid = tid >> 5;
    const int wm = wid >> 2;        // 0..1 (64 rows)
    const int wn = wid & 3;         // 0..3 (32 cols)
    const int bm = blockIdx.y * 128;
    const int bn = blockIdx.x * 128;

    const __half* Agh = Ah + (size_t)bm * K;
    const __half* Bgh = Bh + (size_t)bn * K;

    const int nch = K / 64;         // 16

    // one 64-wide K chunk: A 128x64 + B 128x64 fp16, row stride 144B
    auto issue = [&](int ch, uint32_t st) {
        const int koff = ch * 64;
#pragma unroll
        for (int p = 0; p < 4; p++) {
            int u = tid + 256 * p;          // 0..1023
            int row = u >> 3;               // 0..127
            int seg = u & 7;                // 8 segs x 16B
            uint32_t so = sb + st + (uint32_t)(row * 144 + seg * 16);
            size_t go = (size_t)row * K + koff + seg * 8;
            CPASYNC(so, Agh + go);
            CPASYNC(so + GT64, Bgh + go);
        }
    };

    float acc[4][4][4];
#pragma unroll
    for (int i = 0; i < 4; i++)
#pragma unroll
        for (int j = 0; j < 4; j++)
#pragma unroll
            for (int r = 0; r < 4; r++) acc[i][j][r] = 0.f;

    const uint32_t aOff = (uint32_t)((wm * 64 + (lane & 15)) * SROWG + (lane >> 4) * 8) * 2;
    const uint32_t bOff = (uint32_t)((wn * 32 + (lane >> 4) * 8 + (lane & 7)) * SROWG +
                                     ((lane >> 3) & 1) * 8) * 2;

    issue(0, 0); CPCOMMIT();
    issue(1, GSTG); CPCOMMIT();
    CPWAIT1();
    __syncthreads();

    for (int ch = 0; ch < nch; ch++) {
        const uint32_t cur = (uint32_t)(ch & 1) * GSTG;
        const uint32_t aB = sb + cur;
        const uint32_t bB = sb + cur + GT64;

#pragma unroll
        for (int kk = 0; kk < 4; kk++) {
            const uint32_t kByte = (uint32_t)(kk * 16 * 2);
            uint32_t bh[4][2];
#pragma unroll
            for (int jp = 0; jp < 2; jp++) {
                uint32_t o = bOff + kByte + (uint32_t)(jp * 16 * SROWG * 2);
                uint32_t t0, t1, t2, t3;
                ldsm_x4(t0, t1, t2, t3, bB + o);
                bh[2 * jp][0] = t0; bh[2 * jp][1] = t1;
                bh[2 * jp + 1][0] = t2; bh[2 * jp + 1][1] = t3;
            }
            uint32_t af[4][4];
#pragma unroll
            for (int i = 0; i < 4; i++)
                ldsm_x4(af[i][0], af[i][1], af[i][2], af[i][3],
                        aB + aOff + kByte + (uint32_t)(i * 16 * SROWG * 2));
#pragma unroll
            for (int i = 0; i < 4; i++)
#pragma unroll
                for (int j = 0; j < 4; j++) mma16816h(acc[i][j], af[i], bh[j]);
        }
        __syncthreads();
        if (ch + 1 < nch) {
            if (ch + 2 < nch) { issue(ch + 2, cur); CPCOMMIT(); CPWAIT1(); }
            else { CPWAIT0(); }
            __syncthreads();
        }
    }

    const int lr = lane >> 2;
    const int lc = (lane & 3) * 2;

    if (MODE == 0) {
#pragma unroll
        for (int i = 0; i < 4; i++) {
            int rowA = bm + wm * 64 + i * 16 + lr;
#pragma unroll
            for (int j = 0; j < 4; j++) {
                int col = bn + wn * 32 + j * 8 + lc;
                *(float2*)&Cout[(size_t)rowA * N + col] = make_float2(acc[i][j][0], acc[i][j][1]);
                *(float2*)&Cout[(size_t)(rowA + 8) * N + col] = make_float2(acc[i][j][2], acc[i][j][3]);
            }
        }
    } else {
        // warp covers 32 cols inside one head block
        int col0 = bn + wn * 32;
        int sdx = col0 >> 10;               // 0=q 1=k 2=v
        int rr = col0 & (Cdim - 1);
        int h = rr >> 6;
        int d0 = (rr & (Ddim - 1)) + lc;
        __half* dst = (sdx == 0) ? g_q2 : (sdx == 1) ? g_k2 : g_v2;
        float sc = (sdx == 0) ? 0.125f : 1.0f;
#pragma unroll
        for (int i = 0; i < 4; i++) {
            int rowA = bm + wm * 64 + i * 16 + lr;
#pragma unroll
            for (int hh = 0; hh < 2; hh++) {
                int row = rowA + hh * 8;
                int b = row >> 11;
                int t = row & (Tdim - 1);
                size_t off = ((size_t)(b * Hdim + h) * Tdim + t) * Ddim + d0;
#pragma unroll
                for (int j = 0; j < 4; j++) {
                    *(uint32_t*)&dst[off + j * 8] =
                        pack2h(acc[i][j][hh * 2] * sc, acc[i][j][hh * 2 + 1] * sc);
                }
            }
        }
    }
}

// ---------------------------------------------------------------------------
// Tensor-core causal flash attention, 1-term fp16, 2 CTAs/SM (unchanged).
// ---------------------------------------------------------------------------
__global__ void __launch_bounds__(256, 2) attn_mma() {
    extern __shared__ __align__(16) char sbuf[];
    const uint32_t sb = smem_u32(sbuf);
    const int tid = threadIdx.x;
    const int lane = tid & 31;
    const int w = tid >> 5;
    const int bh = blockIdx.y;
    const int q0 = (int)(gridDim.x - 1 - blockIdx.x) * 128;

    const size_t headoff = (size_t)bh * Tdim * Ddim;
    const int ktmax = (q0 + 127) >> 6;

    const int arow = tid >> 3;
    const int ac8 = (tid & 7) * 8;
    uint4 kh_r[2], vh_r[2];

    auto ldkv = [&](int kt) {
        const size_t base = headoff + (size_t)(kt * 64) * Ddim;
#pragma unroll
        for (int p = 0; p < 2; p++) {
            size_t o = base + (size_t)(arow + 32 * p) * Ddim + ac8;
            kh_r[p] = *(const uint4*)&g_k2[o];
            vh_r[p] = *(const uint4*)&g_v2[o];
        }
    };
    auto stkv = [&](uint32_t stOff) {
#pragma unroll
        for (int p = 0; p < 2; p++) {
            uint32_t so = (uint32_t)((arow + 32 * p) * SROWA + ac8) * 2;
            *(uint4*)(sbuf + stOff + 0 * ATILE + so) = kh_r[p];
            *(uint4*)(sbuf + stOff + 1 * ATILE + so) = vh_r[p];
        }
    };

    ldkv(0);
    {
        const uint4* qg = (const uint4*)(g_q2 + headoff + (size_t)q0 * Ddim);
#pragma unroll
        for (int p = 0; p < 4; p++) {
            int u = p * 256 + tid;
            int row = u >> 3;
            int c8 = (u & 7) * 8;
            uint32_t so = (uint32_t)(row * SROWA + c8) * 2;
            *(uint4*)(sbuf + so) = qg[u];
        }
    }
    __syncthreads();

    uint32_t qf[4][4];
#pragma unroll
    for (int kk = 0; kk < 4; kk++) {
        uint32_t off = (uint32_t)((16 * w + (lane & 15)) * SROWA + 16 * kk + 8 * (lane >> 4)) * 2;
        ldsm_x4(qf[kk][0], qf[kk][1], qf[kk][2], qf[kk][3], sb + off);
    }
    __syncthreads();

    stkv(0);
    ldkv(1);
    __syncthreads();

    float oacc[8][4];
#pragma unroll
    for (int j = 0; j < 8; j++)
#pragma unroll
        for (int r = 0; r < 4; r++) oacc[j][r] = 0.f;
    float m1 = -1e30f, m2 = -1e30f, l1 = 0.f, l2 = 0.f;

    const int r1 = q0 + 16 * w + (lane >> 2);
    const int r2 = r1 + 8;

    for (int kt = 0; kt <= ktmax; kt++) {
        const int kbase = kt * 64;
        const int s = kt & 1;
        const uint32_t cur = (uint32_t)s * ASTAGE;
        const uint32_t nxt = (uint32_t)(s ^ 1) * ASTAGE;

        if (kt + 1 <= ktmax) stkv(nxt);
        if (kt + 2 <= ktmax) ldkv(kt + 2);

        const uint32_t oKh = cur + 0 * ATILE;
        const uint32_t oVh = cur + 1 * ATILE;

        // ---- S = Q.K^T ----
        float sacc[8][4];
#pragma unroll
        for (int j = 0; j < 8; j++)
#pragma unroll
            for (int r = 0; r < 4; r++) sacc[j][r] = 0.f;

#pragma unroll
        for (int kk = 0; kk < 4; kk++) {
            uint32_t bk[8][2];
#pragma unroll
            for (int np = 0; np < 4; np++) {
                uint32_t off = (uint32_t)((np * 16 + (lane >> 4) * 8 + (lane & 7)) * SROWA +
                                          ((lane >> 3) & 1) * 8 + 16 * kk) * 2;
                uint32_t t0, t1, t2, t3;
                ldsm_x4(t0, t1, t2, t3, sb + oKh + off);
                bk[2 * np][0] = t0; bk[2 * np][1] = t1;
                bk[2 * np + 1][0] = t2; bk[2 * np + 1][1] = t3;
            }
#pragma unroll
            for (int j = 0; j < 8; j++) mma16816h(sacc[j], qf[kk], bk[j]);
        }

        if (kbase + 63 > q0 + 16 * w) {
            const int c0 = kbase + 2 * (lane & 3);
#pragma unroll
            for (int j = 0; j < 8; j++) {
                int cj = c0 + 8 * j;
                if (cj > r1)     sacc[j][0] = -1e30f;
                if (cj + 1 > r1) sacc[j][1] = -1e30f;
                if (cj > r2)     sacc[j][2] = -1e30f;
                if (cj + 1 > r2) sacc[j][3] = -1e30f;
            }
        }

        float t1m = -1e30f, t2m = -1e30f;
#pragma unroll
        for (int j = 0; j < 8; j++) {
            t1m = fmaxf(t1m, fmaxf(sacc[j][0], sacc[j][1]));
            t2m = fmaxf(t2m, fmaxf(sacc[j][2], sacc[j][3]));
        }
        t1m = fmaxf(t1m, __shfl_xor_sync(0xffffffffu, t1m, 1));
        t1m = fmaxf(t1m, __shfl_xor_sync(0xffffffffu, t1m, 2));
        t2m = fmaxf(t2m, __shfl_xor_sync(0xffffffffu, t2m, 1));
        t2m = fmaxf(t2m, __shfl_xor_sync(0xffffffffu, t2m, 2));

        float nm1 = fmaxf(m1, t1m), nm2 = fmaxf(m2, t2m);
        float corr1 = __expf(m1 - nm1), corr2 = __expf(m2 - nm2);
        m1 = nm1; m2 = nm2;

        float s1 = 0.f, s2 = 0.f;
#pragma unroll
        for (int j = 0; j < 8; j++) {
            sacc[j][0] = __expf(sacc[j][0] - m1);
            sacc[j][1] = __expf(sacc[j][1] - m1);
            sacc[j][2] = __expf(sacc[j][2] - m2);
            sacc[j][3] = __expf(sacc[j][3] - m2);
            s1 += sacc[j][0] + sacc[j][1];
            s2 += sacc[j][2] + sacc[j][3];
        }
        s1 += __shfl_xor_sync(0xffffffffu, s1, 1);
        s1 += __shfl_xor_sync(0xffffffffu, s1, 2);
        s2 += __shfl_xor_sync(0xffffffffu, s2, 1);
        s2 += __shfl_xor_sync(0xffffffffu, s2, 2);
        l1 = l1 * corr1 + s1;
        l2 = l2 * corr2 + s2;

        // pack P into fp16 A-fragments
        uint32_t ph[4][4];
#pragma unroll
        for (int kk = 0; kk < 4; kk++) {
            int j0 = 2 * kk, j1 = 2 * kk + 1;
            ph[kk][0] = pack2h(sacc[j0][0], sacc[j0][1]);
            ph[kk][1] = pack2h(sacc[j0][2], sacc[j0][3]);
            ph[kk][2] = pack2h(sacc[j1][0], sacc[j1][1]);
            ph[kk][3] = pack2h(sacc[j1][2], sacc[j1][3]);
        }

#pragma unroll
        for (int j = 0; j < 8; j++) {
            oacc[j][0] *= corr1; oacc[j][1] *= corr1;
            oacc[j][2] *= corr2; oacc[j][3] *= corr2;
        }

        // ---- O += P.V ----
#pragma unroll
        for (int kk = 0; kk < 4; kk++) {
            uint32_t vb[8][2];
#pragma unroll
            for (int np = 0; np < 4; np++) {
                uint32_t off = (uint32_t)((16 * kk + (lane & 15)) * SROWA +
                                          16 * np + 8 * (lane >> 4)) * 2;
                uint32_t t0, t1, t2, t3;
                ldsm_x4_t(t0, t1, t2, t3, sb + oVh + off);
                vb[2 * np][0] = t0; vb[2 * np][1] = t1;
                vb[2 * np + 1][0] = t2; vb[2 * np + 1][1] = t3;
            }
#pragma unroll
            for (int j = 0; j < 8; j++) mma16816h(oacc[j], ph[kk], vb[j]);
        }
        __syncthreads();
    }

    // ---- epilogue: y[B,T,H,D] single fp16 ----
    float inv1 = 1.0f / l1, inv2 = 1.0f / l2;
    int b = bh >> 4, h = bh & 15;
    size_t off1 = ((size_t)(b * Tdim + r1) * Hdim + h) * Ddim;
    size_t off2 = ((size_t)(b * Tdim + r2) * Hdim + h) * Ddim;
    int d0 = 2 * (lane & 3);
#pragma unroll
    for (int j = 0; j < 8; j++) {
        *(uint32_t*)&g_y2[off1 + 8 * j + d0] = pack2h(oacc[j][0] * inv1, oacc[j][1] * inv1);
        *(uint32_t*)&g_y2[off2 + 8 * j + d0] = pack2h(oacc[j][2] * inv2, oacc[j][3] * inv2);
    }
}

// ---------------------------------------------------------------------------
extern "C" void kernel_launch(void* const* d_in, const int* in_sizes, int n_in,
                              void* d_out, int out_size) {
    const float* x = (const float*)d_in[0];        // [B,T,C]
    const float* w_attn = (const float*)d_in[1];   // [3C,C]
    const float* w_proj = (const float*)d_in[2];   // [C,C]
    float* out = (float*)d_out;                    // [B,T,C]

    __half *x2, *wa, *wp, *y2;
    cudaGetSymbolAddress((void**)&x2, g_x2);
    cudaGetSymbolAddress((void**)&wa, g_wa);
    cudaGetSymbolAddress((void**)&wp, g_wp);
    cudaGetSymbolAddress((void**)&y2, g_y2);

    cudaFuncSetAttribute(gemm_h1<0>, cudaFuncAttributeMaxDynamicSharedMemorySize, GSM64);
    cudaFuncSetAttribute(gemm_h1<1>, cudaFuncAttributeMaxDynamicSharedMemorySize, GSM64);
    cudaFuncSetAttribute(attn_mma, cudaFuncAttributeMaxDynamicSharedMemorySize, ASMEM);

    // Fused pre-pass: round all inputs to fp16 (one launch)
    const int ntot = NX4 + NWA4 + NWP4;            // 2097152
    round_all_kernel<<<(ntot + 255) / 256, 256>>>(x, w_attn, w_proj, x2, wa, wp);

    // GEMM1: qkv = x @ w_attn^T (fp16 1-term), scatter epilogue
    dim3 g1(3 * Cdim / 128, Mrows / 128);   // (24, 32)
    gemm_h1<1><<<g1, 256, GSM64>>>(x2, wa, nullptr, Cdim, 3 * Cdim);

    // Attention
    dim3 ga(Tdim / 128, Bdim * Hdim);       // (16, 32)
    attn_mma<<<ga, 256, ASMEM>>>();

    // GEMM2: out = y @ w_proj^T (fp16 1-term)
    dim3 g2(Cdim / 128, Mrows / 128);       // (8, 32)
    gemm_h1<0><<<g2, 256, GSM64>>>(y2, wp, out, Cdim, Cdim);
}

// round 15
// speedup vs baseline: 3.0622x; 1.1230x over previous
#include <cuda_runtime.h>
#include <cuda_fp16.h>
#include <cstdint>
#include <math.h>

// Problem constants
#define Bdim 2
#define Tdim 2048
#define Cdim 1024
#define Hdim 16
#define Ddim 64
#define Mrows (Bdim * Tdim)   // 4096

// Device-global scratch (allocation-free), all single fp16
__device__ __align__(16) __half g_x2[(size_t)Mrows * Cdim];
__device__ __align__(16) __half g_wa[(size_t)3 * Cdim * Cdim];
__device__ __align__(16) __half g_wp[(size_t)Cdim * Cdim];
__device__ __align__(16) __half g_q2[(size_t)Bdim * Hdim * Tdim * Ddim];
__device__ __align__(16) __half g_k2[(size_t)Bdim * Hdim * Tdim * Ddim];
__device__ __align__(16) __half g_v2[(size_t)Bdim * Hdim * Tdim * Ddim];
__device__ __align__(16) __half g_y2[(size_t)Mrows * Cdim];

// ---------------------------------------------------------------------------
// Helpers
// ---------------------------------------------------------------------------
__device__ __forceinline__ uint32_t smem_u32(const void* p) {
    uint32_t a;
    asm("{ .reg .u64 t; cvta.to.shared.u64 t, %1; cvt.u32.u64 %0, t; }" : "=r"(a) : "l"(p));
    return a;
}

__device__ __forceinline__ void ldsm_x4(uint32_t& r0, uint32_t& r1, uint32_t& r2, uint32_t& r3,
                                        uint32_t addr) {
    asm volatile("ldmatrix.sync.aligned.m8n8.x4.shared.b16 {%0,%1,%2,%3}, [%4];"
                 : "=r"(r0), "=r"(r1), "=r"(r2), "=r"(r3) : "r"(addr));
}
__device__ __forceinline__ void ldsm_x4_t(uint32_t& r0, uint32_t& r1, uint32_t& r2, uint32_t& r3,
                                          uint32_t addr) {
    asm volatile("ldmatrix.sync.aligned.m8n8.x4.trans.shared.b16 {%0,%1,%2,%3}, [%4];"
                 : "=r"(r0), "=r"(r1), "=r"(r2), "=r"(r3) : "r"(addr));
}

__device__ __forceinline__ void mma16816h(float* c, const uint32_t* a, const uint32_t* b) {
    asm volatile(
        "mma.sync.aligned.m16n8k16.row.col.f32.f16.f16.f32 "
        "{%0,%1,%2,%3}, {%4,%5,%6,%7}, {%8,%9}, {%0,%1,%2,%3};"
        : "+f"(c[0]), "+f"(c[1]), "+f"(c[2]), "+f"(c[3])
        : "r"(a[0]), "r"(a[1]), "r"(a[2]), "r"(a[3]), "r"(b[0]), "r"(b[1]));
}

__device__ __forceinline__ uint32_t pack2h(float x, float y) {
    __half2 t;
    t.x = __float2half_rn(x);
    t.y = __float2half_rn(y);
    return *reinterpret_cast<uint32_t*>(&t);
}

// cp.async (LDGSTS): global -> smem, 16B, L1-bypass (.cg)
#define CPASYNC(saddr, gptr) \
    asm volatile("cp.async.cg.shared.global [%0], [%1], 16;" :: "r"(saddr), "l"(gptr))
#define CPCOMMIT() asm volatile("cp.async.commit_group;" ::: "memory")
#define CPWAIT1() asm volatile("cp.async.wait_group 1;" ::: "memory")
#define CPWAIT0() asm volatile("cp.async.wait_group 0;" ::: "memory")

#define SROWG 72   // GEMM smem row stride (elements; 144B, conflict-free ldmatrix)
#define SROWA 72   // Attention smem row stride (elements)

// fp16 GEMM smem: CTA tile 128x128, K-chunk 64; per stage A + B (128x72), 3 stages
#define GT64 18432             // 128*72*2
#define GSTG (2 * GT64)        // 36864
#define GSM3 (3 * GSTG)        // 110592 (2 CTAs/SM -> 221KB)

// Attention smem: 2 stages, each K + V (single fp16), 64 rows x SROWA
#define ATILE 9216             // 64*72*2
#define ASTAGE (2 * ATILE)     // 18432
#define ASMEM (2 * ASTAGE)     // 36864

// ---------------------------------------------------------------------------
// Fused pre-pass: round all three fp32 arrays to fp16 in one launch.
// ---------------------------------------------------------------------------
#define NX4 (Mrows * Cdim / 4)            // 1048576
#define NWA4 (3 * Cdim * Cdim / 4)        // 786432
#define NWP4 (Cdim * Cdim / 4)            // 262144

__global__ void round_all_kernel(const float* __restrict__ x, const float* __restrict__ wa,
                                 const float* __restrict__ wp, __half* __restrict__ dx,
                                 __half* __restrict__ dwa, __half* __restrict__ dwp) {
    int i = blockIdx.x * blockDim.x + threadIdx.x;
    const float4* s;
    uint2* d;
    int j;
    if (i < NX4) { s = (const float4*)x; d = (uint2*)dx; j = i; }
    else if (i < NX4 + NWA4) { s = (const float4*)wa; d = (uint2*)dwa; j = i - NX4; }
    else if (i < NX4 + NWA4 + NWP4) { s = (const float4*)wp; d = (uint2*)dwp; j = i - NX4 - NWA4; }
    else return;
    float4 v = s[j];
    d[j] = make_uint2(pack2h(v.x, v.y), pack2h(v.z, v.w));
}

// ---------------------------------------------------------------------------
// fp16 1-term GEMM (NT): C = A @ B^T. CTA 128x128, warp 64x32, K-chunk 64,
// 3-stage cp.async pipeline, ONE __syncthreads per chunk, 2 CTAs/SM.
// MODE 0: fp32 store. MODE 1: qkv scatter (q*0.125, k, v single fp16 [B,H,T,D]).
// ---------------------------------------------------------------------------
template <int MODE>
__global__ void __launch_bounds__(256, 2) gemm_h1(const __half* __restrict__ Ah,
                                                  const __half* __restrict__ Bh,
                                                  float* __restrict__ Cout,
                                                  int K, int N) {
    extern __shared__ __align__(16) char smem[];
    const uint32_t sb = smem_u32(smem);

    const int tid = threadIdx.x;
    const int lane = tid & 31;
    const int wid = tid >> 5;
    const int wm = wid >> 2;        // 0..1 (64 rows)
    const int wn = wid & 3;         // 0..3 (32 cols)
    const int bm = blockIdx.y * 128;
    const int bn = blockIdx.x * 128;

    const __half* Agh = Ah + (size_t)bm * K;
    const __half* Bgh = Bh + (size_t)bn * K;

    const int nch = K / 64;         // 16

    // one 64-wide K chunk: A 128x64 + B 128x64 fp16, row stride 144B
    auto issue = [&](int ch, uint32_t st) {
        const int koff = ch * 64;
#pragma unroll
        for (int p = 0; p < 4; p++) {
            int u = tid + 256 * p;          // 0..1023
            int row = u >> 3;               // 0..127
            int seg = u & 7;                // 8 segs x 16B
            uint32_t so = sb + st + (uint32_t)(row * 144 + seg * 16);
            size_t go = (size_t)row * K + koff + seg * 8;
            CPASYNC(so, Agh + go);
            CPASYNC(so + GT64, Bgh + go);
        }
    };

    float acc[4][4][4];
#pragma unroll
    for (int i = 0; i < 4; i++)
#pragma unroll
        for (int j = 0; j < 4; j++)
#pragma unroll
            for (int r = 0; r < 4; r++) acc[i][j][r] = 0.f;

    const uint32_t aOff = (uint32_t)((wm * 64 + (lane & 15)) * SROWG + (lane >> 4) * 8) * 2;
    const uint32_t bOff = (uint32_t)((wn * 32 + (lane >> 4) * 8 + (lane & 7)) * SROWG +
                                     ((lane >> 3) & 1) * 8) * 2;

    issue(0, 0); CPCOMMIT();
    issue(1, GSTG); CPCOMMIT();

    for (int ch = 0; ch < nch; ch++) {
        if (ch + 1 < nch) { CPWAIT1(); } else { CPWAIT0(); }
        __syncthreads();
        const uint32_t cur = (uint32_t)(ch % 3) * GSTG;
        const uint32_t aB = sb + cur;
        const uint32_t bB = sb + cur + GT64;

#pragma unroll
        for (int kk = 0; kk < 4; kk++) {
            const uint32_t kByte = (uint32_t)(kk * 16 * 2);
            uint32_t bh[4][2];
#pragma unroll
            for (int jp = 0; jp < 2; jp++) {
                uint32_t o = bOff + kByte + (uint32_t)(jp * 16 * SROWG * 2);
                uint32_t t0, t1, t2, t3;
                ldsm_x4(t0, t1, t2, t3, bB + o);
                bh[2 * jp][0] = t0; bh[2 * jp][1] = t1;
                bh[2 * jp + 1][0] = t2; bh[2 * jp + 1][1] = t3;
            }
            uint32_t af[4][4];
#pragma unroll
            for (int i = 0; i < 4; i++)
                ldsm_x4(af[i][0], af[i][1], af[i][2], af[i][3],
                        aB + aOff + kByte + (uint32_t)(i * 16 * SROWG * 2));
#pragma unroll
            for (int i = 0; i < 4; i++)
#pragma unroll
                for (int j = 0; j < 4; j++) mma16816h(acc[i][j], af[i], bh[j]);
        }
        // issue chunk ch+2 into slot (ch+2)%3 == (ch-1)%3: its readers
        // (compute(ch-1)) all passed this iteration's barrier -> WAR-safe.
        if (ch + 2 < nch) { issue(ch + 2, (uint32_t)((ch + 2) % 3) * GSTG); CPCOMMIT(); }
    }

    const int lr = lane >> 2;
    const int lc = (lane & 3) * 2;

    if (MODE == 0) {
#pragma unroll
        for (int i = 0; i < 4; i++) {
            int rowA = bm + wm * 64 + i * 16 + lr;
#pragma unroll
            for (int j = 0; j < 4; j++) {
                int col = bn + wn * 32 + j * 8 + lc;
                *(float2*)&Cout[(size_t)rowA * N + col] = make_float2(acc[i][j][0], acc[i][j][1]);
                *(float2*)&Cout[(size_t)(rowA + 8) * N + col] = make_float2(acc[i][j][2], acc[i][j][3]);
            }
        }
    } else {
        // warp covers 32 cols inside one head block
        int col0 = bn + wn * 32;
        int sdx = col0 >> 10;               // 0=q 1=k 2=v
        int rr = col0 & (Cdim - 1);
        int h = rr >> 6;
        int d0 = (rr & (Ddim - 1)) + lc;
        __half* dst = (sdx == 0) ? g_q2 : (sdx == 1) ? g_k2 : g_v2;
        float sc = (sdx == 0) ? 0.125f : 1.0f;
#pragma unroll
        for (int i = 0; i < 4; i++) {
            int rowA = bm + wm * 64 + i * 16 + lr;
#pragma unroll
            for (int hh = 0; hh < 2; hh++) {
                int row = rowA + hh * 8;
                int b = row >> 11;
                int t = row & (Tdim - 1);
                size_t off = ((size_t)(b * Hdim + h) * Tdim + t) * Ddim + d0;
#pragma unroll
                for (int j = 0; j < 4; j++) {
                    *(uint32_t*)&dst[off + j * 8] =
                        pack2h(acc[i][j][hh * 2] * sc, acc[i][j][hh * 2 + 1] * sc);
                }
            }
        }
    }
}

// ---------------------------------------------------------------------------
// Tensor-core causal flash attention, 1-term fp16, PERSISTENT CTAs.
// Grid = 296 (2/SM); each CTA strides over 512 (head, q-tile) items,
// heavy-first: item it -> bh = it&31, q0 = (15 - it>>5)*128.
// ---------------------------------------------------------------------------
#define NITEMS (Hdim * Bdim * (Tdim / 128))   // 512

__global__ void __launch_bounds__(256, 2) attn_mma() {
    extern __shared__ __align__(16) char sbuf[];
    const uint32_t sb = smem_u32(sbuf);
    const int tid = threadIdx.x;
    const int lane = tid & 31;
    const int w = tid >> 5;

    const int arow = tid >> 3;
    const int ac8 = (tid & 7) * 8;

    for (int it = blockIdx.x; it < NITEMS; it += gridDim.x) {
        const int bh = it & 31;
        const int q0 = (15 - (it >> 5)) * 128;
        const size_t headoff = (size_t)bh * Tdim * Ddim;
        const int ktmax = (q0 + 127) >> 6;

        uint4 kh_r[2], vh_r[2];
        auto ldkv = [&](int kt) {
            const size_t base = headoff + (size_t)(kt * 64) * Ddim;
#pragma unroll
            for (int p = 0; p < 2; p++) {
                size_t o = base + (size_t)(arow + 32 * p) * Ddim + ac8;
                kh_r[p] = *(const uint4*)&g_k2[o];
                vh_r[p] = *(const uint4*)&g_v2[o];
            }
        };
        auto stkv = [&](uint32_t stOff) {
#pragma unroll
            for (int p = 0; p < 2; p++) {
                uint32_t so = (uint32_t)((arow + 32 * p) * SROWA + ac8) * 2;
                *(uint4*)(sbuf + stOff + 0 * ATILE + so) = kh_r[p];
                *(uint4*)(sbuf + stOff + 1 * ATILE + so) = vh_r[p];
            }
        };

        ldkv(0);
        {
            const uint4* qg = (const uint4*)(g_q2 + headoff + (size_t)q0 * Ddim);
#pragma unroll
            for (int p = 0; p < 4; p++) {
                int u = p * 256 + tid;
                int row = u >> 3;
                int c8 = (u & 7) * 8;
                uint32_t so = (uint32_t)(row * SROWA + c8) * 2;
                *(uint4*)(sbuf + so) = qg[u];
            }
        }
        __syncthreads();

        uint32_t qf[4][4];
#pragma unroll
        for (int kk = 0; kk < 4; kk++) {
            uint32_t off = (uint32_t)((16 * w + (lane & 15)) * SROWA + 16 * kk + 8 * (lane >> 4)) * 2;
            ldsm_x4(qf[kk][0], qf[kk][1], qf[kk][2], qf[kk][3], sb + off);
        }
        __syncthreads();

        stkv(0);
        ldkv(1);
        __syncthreads();

        float oacc[8][4];
#pragma unroll
        for (int j = 0; j < 8; j++)
#pragma unroll
            for (int r = 0; r < 4; r++) oacc[j][r] = 0.f;
        float m1 = -1e30f, m2 = -1e30f, l1 = 0.f, l2 = 0.f;

        const int r1 = q0 + 16 * w + (lane >> 2);
        const int r2 = r1 + 8;

        for (int kt = 0; kt <= ktmax; kt++) {
            const int kbase = kt * 64;
            const int s = kt & 1;
            const uint32_t cur = (uint32_t)s * ASTAGE;
            const uint32_t nxt = (uint32_t)(s ^ 1) * ASTAGE;

            if (kt + 1 <= ktmax) stkv(nxt);
            if (kt + 2 <= ktmax) ldkv(kt + 2);

            const uint32_t oKh = cur + 0 * ATILE;
            const uint32_t oVh = cur + 1 * ATILE;

            // ---- S = Q.K^T ----
            float sacc[8][4];
#pragma unroll
            for (int j = 0; j < 8; j++)
#pragma unroll
                for (int r = 0; r < 4; r++) sacc[j][r] = 0.f;

#pragma unroll
            for (int kk = 0; kk < 4; kk++) {
                uint32_t bk[8][2];
#pragma unroll
                for (int np = 0; np < 4; np++) {
                    uint32_t off = (uint32_t)((np * 16 + (lane >> 4) * 8 + (lane & 7)) * SROWA +
                                              ((lane >> 3) & 1) * 8 + 16 * kk) * 2;
                    uint32_t t0, t1, t2, t3;
                    ldsm_x4(t0, t1, t2, t3, sb + oKh + off);
                    bk[2 * np][0] = t0; bk[2 * np][1] = t1;
                    bk[2 * np + 1][0] = t2; bk[2 * np + 1][1] = t3;
                }
#pragma unroll
                for (int j = 0; j < 8; j++) mma16816h(sacc[j], qf[kk], bk[j]);
            }

            if (kbase + 63 > q0 + 16 * w) {
                const int c0 = kbase + 2 * (lane & 3);
#pragma unroll
                for (int j = 0; j < 8; j++) {
                    int cj = c0 + 8 * j;
                    if (cj > r1)     sacc[j][0] = -1e30f;
                    if (cj + 1 > r1) sacc[j][1] = -1e30f;
                    if (cj > r2)     sacc[j][2] = -1e30f;
                    if (cj + 1 > r2) sacc[j][3] = -1e30f;
                }
            }

            float t1m = -1e30f, t2m = -1e30f;
#pragma unroll
            for (int j = 0; j < 8; j++) {
                t1m = fmaxf(t1m, fmaxf(sacc[j][0], sacc[j][1]));
                t2m = fmaxf(t2m, fmaxf(sacc[j][2], sacc[j][3]));
            }
            t1m = fmaxf(t1m, __shfl_xor_sync(0xffffffffu, t1m, 1));
            t1m = fmaxf(t1m, __shfl_xor_sync(0xffffffffu, t1m, 2));
            t2m = fmaxf(t2m, __shfl_xor_sync(0xffffffffu, t2m, 1));
            t2m = fmaxf(t2m, __shfl_xor_sync(0xffffffffu, t2m, 2));

            float nm1 = fmaxf(m1, t1m), nm2 = fmaxf(m2, t2m);
            float corr1 = __expf(m1 - nm1), corr2 = __expf(m2 - nm2);
            m1 = nm1; m2 = nm2;

            float s1 = 0.f, s2 = 0.f;
#pragma unroll
            for (int j = 0; j < 8; j++) {
                sacc[j][0] = __expf(sacc[j][0] - m1);
                sacc[j][1] = __expf(sacc[j][1] - m1);
                sacc[j][2] = __expf(sacc[j][2] - m2);
                sacc[j][3] = __expf(sacc[j][3] - m2);
                s1 += sacc[j][0] + sacc[j][1];
                s2 += sacc[j][2] + sacc[j][3];
            }
            s1 += __shfl_xor_sync(0xffffffffu, s1, 1);
            s1 += __shfl_xor_sync(0xffffffffu, s1, 2);
            s2 += __shfl_xor_sync(0xffffffffu, s2, 1);
            s2 += __shfl_xor_sync(0xffffffffu, s2, 2);
            l1 = l1 * corr1 + s1;
            l2 = l2 * corr2 + s2;

            // pack P into fp16 A-fragments
            uint32_t ph[4][4];
#pragma unroll
            for (int kk = 0; kk < 4; kk++) {
                int j0 = 2 * kk, j1 = 2 * kk + 1;
                ph[kk][0] = pack2h(sacc[j0][0], sacc[j0][1]);
                ph[kk][1] = pack2h(sacc[j0][2], sacc[j0][3]);
                ph[kk][2] = pack2h(sacc[j1][0], sacc[j1][1]);
                ph[kk][3] = pack2h(sacc[j1][2], sacc[j1][3]);
            }

#pragma unroll
            for (int j = 0; j < 8; j++) {
                oacc[j][0] *= corr1; oacc[j][1] *= corr1;
                oacc[j][2] *= corr2; oacc[j][3] *= corr2;
            }

            // ---- O += P.V ----
#pragma unroll
            for (int kk = 0; kk < 4; kk++) {
                uint32_t vb[8][2];
#pragma unroll
                for (int np = 0; np < 4; np++) {
                    uint32_t off = (uint32_t)((16 * kk + (lane & 15)) * SROWA +
                                              16 * np + 8 * (lane >> 4)) * 2;
                    uint32_t t0, t1, t2, t3;
                    ldsm_x4_t(t0, t1, t2, t3, sb + oVh + off);
                    vb[2 * np][0] = t0; vb[2 * np][1] = t1;
                    vb[2 * np + 1][0] = t2; vb[2 * np + 1][1] = t3;
                }
#pragma unroll
                for (int j = 0; j < 8; j++) mma16816h(oacc[j], ph[kk], vb[j]);
            }
            __syncthreads();
        }

        // ---- epilogue: y[B,T,H,D] single fp16 ----
        float inv1 = 1.0f / l1, inv2 = 1.0f / l2;
        int b = bh >> 4, h = bh & 15;
        size_t off1 = ((size_t)(b * Tdim + r1) * Hdim + h) * Ddim;
        size_t off2 = ((size_t)(b * Tdim + r2) * Hdim + h) * Ddim;
        int d0 = 2 * (lane & 3);
#pragma unroll
        for (int j = 0; j < 8; j++) {
            *(uint32_t*)&g_y2[off1 + 8 * j + d0] = pack2h(oacc[j][0] * inv1, oacc[j][1] * inv1);
            *(uint32_t*)&g_y2[off2 + 8 * j + d0] = pack2h(oacc[j][2] * inv2, oacc[j][3] * inv2);
        }
    }
}

// ---------------------------------------------------------------------------
extern "C" void kernel_launch(void* const* d_in, const int* in_sizes, int n_in,
                              void* d_out, int out_size) {
    const float* x = (const float*)d_in[0];        // [B,T,C]
    const float* w_attn = (const float*)d_in[1];   // [3C,C]
    const float* w_proj = (const float*)d_in[2];   // [C,C]
    float* out = (float*)d_out;                    // [B,T,C]

    __half *x2, *wa, *wp, *y2;
    cudaGetSymbolAddress((void**)&x2, g_x2);
    cudaGetSymbolAddress((void**)&wa, g_wa);
    cudaGetSymbolAddress((void**)&wp, g_wp);
    cudaGetSymbolAddress((void**)&y2, g_y2);

    cudaFuncSetAttribute(gemm_h1<0>, cudaFuncAttributeMaxDynamicSharedMemorySize, GSM3);
    cudaFuncSetAttribute(gemm_h1<1>, cudaFuncAttributeMaxDynamicSharedMemorySize, GSM3);
    cudaFuncSetAttribute(attn_mma, cudaFuncAttributeMaxDynamicSharedMemorySize, ASMEM);

    // Fused pre-pass: round all inputs to fp16 (one launch)
    const int ntot = NX4 + NWA4 + NWP4;            // 2097152
    round_all_kernel<<<(ntot + 255) / 256, 256>>>(x, w_attn, w_proj, x2, wa, wp);

    // GEMM1: qkv = x @ w_attn^T (fp16 1-term), scatter epilogue
    dim3 g1(3 * Cdim / 128, Mrows / 128);   // (24, 32)
    gemm_h1<1><<<g1, 256, GSM3>>>(x2, wa, nullptr, Cdim, 3 * Cdim);

    // Attention (persistent, 2 CTAs/SM)
    attn_mma<<<296, 256, ASMEM>>>();

    // GEMM2: out = y @ w_proj^T (fp16 1-term)
    dim3 g2(Cdim / 128, Mrows / 128);       // (8, 32)
    gemm_h1<0><<<g2, 256, GSM3>>>(y2, wp, out, Cdim, Cdim);
}

// round 16
// speedup vs baseline: 3.1659x; 1.0339x over previous
#include <cuda_runtime.h>
#include <cuda_fp16.h>
#include <cstdint>
#include <math.h>

// Problem constants
#define Bdim 2
#define Tdim 2048
#define Cdim 1024
#define Hdim 16
#define Ddim 64
#define Mrows (Bdim * Tdim)   // 4096

// Device-global scratch (allocation-free), all single fp16
__device__ __align__(16) __half g_x2[(size_t)Mrows * Cdim];
__device__ __align__(16) __half g_wa[(size_t)3 * Cdim * Cdim];
__device__ __align__(16) __half g_wp[(size_t)Cdim * Cdim];
__device__ __align__(16) __half g_q2[(size_t)Bdim * Hdim * Tdim * Ddim];
__device__ __align__(16) __half g_k2[(size_t)Bdim * Hdim * Tdim * Ddim];
__device__ __align__(16) __half g_v2[(size_t)Bdim * Hdim * Tdim * Ddim];
__device__ __align__(16) __half g_y2[(size_t)Mrows * Cdim];

// ---------------------------------------------------------------------------
// Helpers
// ---------------------------------------------------------------------------
__device__ __forceinline__ uint32_t smem_u32(const void* p) {
    uint32_t a;
    asm("{ .reg .u64 t; cvta.to.shared.u64 t, %1; cvt.u32.u64 %0, t; }" : "=r"(a) : "l"(p));
    return a;
}

__device__ __forceinline__ void ldsm_x4(uint32_t& r0, uint32_t& r1, uint32_t& r2, uint32_t& r3,
                                        uint32_t addr) {
    asm volatile("ldmatrix.sync.aligned.m8n8.x4.shared.b16 {%0,%1,%2,%3}, [%4];"
                 : "=r"(r0), "=r"(r1), "=r"(r2), "=r"(r3) : "r"(addr));
}
__device__ __forceinline__ void ldsm_x4_t(uint32_t& r0, uint32_t& r1, uint32_t& r2, uint32_t& r3,
                                          uint32_t addr) {
    asm volatile("ldmatrix.sync.aligned.m8n8.x4.trans.shared.b16 {%0,%1,%2,%3}, [%4];"
                 : "=r"(r0), "=r"(r1), "=r"(r2), "=r"(r3) : "r"(addr));
}

__device__ __forceinline__ void mma16816h(float* c, const uint32_t* a, const uint32_t* b) {
    asm volatile(
        "mma.sync.aligned.m16n8k16.row.col.f32.f16.f16.f32 "
        "{%0,%1,%2,%3}, {%4,%5,%6,%7}, {%8,%9}, {%0,%1,%2,%3};"
        : "+f"(c[0]), "+f"(c[1]), "+f"(c[2]), "+f"(c[3])
        : "r"(a[0]), "r"(a[1]), "r"(a[2]), "r"(a[3]), "r"(b[0]), "r"(b[1]));
}

__device__ __forceinline__ uint32_t pack2h(float x, float y) {
    __half2 t;
    t.x = __float2half_rn(x);
    t.y = __float2half_rn(y);
    return *reinterpret_cast<uint32_t*>(&t);
}

// cp.async (LDGSTS): global -> smem, 16B, L1-bypass (.cg)
#define CPASYNC(saddr, gptr) \
    asm volatile("cp.async.cg.shared.global [%0], [%1], 16;" :: "r"(saddr), "l"(gptr))
#define CPCOMMIT() asm volatile("cp.async.commit_group;" ::: "memory")
#define CPWAIT1() asm volatile("cp.async.wait_group 1;" ::: "memory")
#define CPWAIT0() asm volatile("cp.async.wait_group 0;" ::: "memory")

#define SROWG 72   // GEMM smem row stride (elements; 144B, conflict-free ldmatrix)
#define SROWA 72   // Attention smem row stride (elements)

// fp16 GEMM smem: CTA tile 128x128, K-chunk 64; per stage A + B (128x72), 3 stages
#define GT64 18432             // 128*72*2
#define GSTG (2 * GT64)        // 36864
#define GSM3 (3 * GSTG)        // 110592 (2 CTAs/SM -> 221KB)

// Attention smem: 3 stages, each K + V (single fp16), 64 rows x SROWA.
// Q (128x64) staged in stage-2 region during prologue.
#define ATILE 9216             // 64*72*2
#define ASTG (2 * ATILE)       // 18432
#define ASMEM (3 * ASTG)       // 55296 (2 CTAs/SM -> 110KB)

// ---------------------------------------------------------------------------
// Fused pre-pass: round all three fp32 arrays to fp16 in one launch.
// ---------------------------------------------------------------------------
#define NX4 (Mrows * Cdim / 4)            // 1048576
#define NWA4 (3 * Cdim * Cdim / 4)        // 786432
#define NWP4 (Cdim * Cdim / 4)            // 262144

__global__ void round_all_kernel(const float* __restrict__ x, const float* __restrict__ wa,
                                 const float* __restrict__ wp, __half* __restrict__ dx,
                                 __half* __restrict__ dwa, __half* __restrict__ dwp) {
    int i = blockIdx.x * blockDim.x + threadIdx.x;
    const float4* s;
    uint2* d;
    int j;
    if (i < NX4) { s = (const float4*)x; d = (uint2*)dx; j = i; }
    else if (i < NX4 + NWA4) { s = (const float4*)wa; d = (uint2*)dwa; j = i - NX4; }
    else if (i < NX4 + NWA4 + NWP4) { s = (const float4*)wp; d = (uint2*)dwp; j = i - NX4 - NWA4; }
    else return;
    float4 v = s[j];
    d[j] = make_uint2(pack2h(v.x, v.y), pack2h(v.z, v.w));
}

// ---------------------------------------------------------------------------
// fp16 1-term GEMM (NT): C = A @ B^T. CTA 128x128, warp 64x32, K-chunk 64,
// 3-stage cp.async pipeline, ONE __syncthreads per chunk, 2 CTAs/SM.
// MODE 0: fp32 store. MODE 1: qkv scatter (q*0.125*log2e, k, v fp16 [B,H,T,D]).
// ---------------------------------------------------------------------------
template <int MODE>
__global__ void __launch_bounds__(256, 2) gemm_h1(const __half* __restrict__ Ah,
                                                  const __half* __restrict__ Bh,
                                                  float* __restrict__ Cout,
                                                  int K, int N) {
    extern __shared__ __align__(16) char smem[];
    const uint32_t sb = smem_u32(smem);

    const int tid = threadIdx.x;
    const int lane = tid & 31;
    const int wid = tid >> 5;
    const int wm = wid >> 2;        // 0..1 (64 rows)
    const int wn = wid & 3;         // 0..3 (32 cols)
    const int bm = blockIdx.y * 128;
    const int bn = blockIdx.x * 128;

    const __half* Agh = Ah + (size_t)bm * K;
    const __half* Bgh = Bh + (size_t)bn * K;

    const int nch = K / 64;         // 16

    auto issue = [&](int ch, uint32_t st) {
        const int koff = ch * 64;
#pragma unroll
        for (int p = 0; p < 4; p++) {
            int u = tid + 256 * p;          // 0..1023
            int row = u >> 3;               // 0..127
            int seg = u & 7;                // 8 segs x 16B
            uint32_t so = sb + st + (uint32_t)(row * 144 + seg * 16);
            size_t go = (size_t)row * K + koff + seg * 8;
            CPASYNC(so, Agh + go);
            CPASYNC(so + GT64, Bgh + go);
        }
    };

    float acc[4][4][4];
#pragma unroll
    for (int i = 0; i < 4; i++)
#pragma unroll
        for (int j = 0; j < 4; j++)
#pragma unroll
            for (int r = 0; r < 4; r++) acc[i][j][r] = 0.f;

    const uint32_t aOff = (uint32_t)((wm * 64 + (lane & 15)) * SROWG + (lane >> 4) * 8) * 2;
    const uint32_t bOff = (uint32_t)((wn * 32 + (lane >> 4) * 8 + (lane & 7)) * SROWG +
                                     ((lane >> 3) & 1) * 8) * 2;

    issue(0, 0); CPCOMMIT();
    issue(1, GSTG); CPCOMMIT();

    for (int ch = 0; ch < nch; ch++) {
        if (ch + 1 < nch) { CPWAIT1(); } else { CPWAIT0(); }
        __syncthreads();
        const uint32_t cur = (uint32_t)(ch % 3) * GSTG;
        const uint32_t aB = sb + cur;
        const uint32_t bB = sb + cur + GT64;

#pragma unroll
        for (int kk = 0; kk < 4; kk++) {
            const uint32_t kByte = (uint32_t)(kk * 16 * 2);
            uint32_t bh[4][2];
#pragma unroll
            for (int jp = 0; jp < 2; jp++) {
                uint32_t o = bOff + kByte + (uint32_t)(jp * 16 * SROWG * 2);
                uint32_t t0, t1, t2, t3;
                ldsm_x4(t0, t1, t2, t3, bB + o);
                bh[2 * jp][0] = t0; bh[2 * jp][1] = t1;
                bh[2 * jp + 1][0] = t2; bh[2 * jp + 1][1] = t3;
            }
            uint32_t af[4][4];
#pragma unroll
            for (int i = 0; i < 4; i++)
                ldsm_x4(af[i][0], af[i][1], af[i][2], af[i][3],
                        aB + aOff + kByte + (uint32_t)(i * 16 * SROWG * 2));
#pragma unroll
            for (int i = 0; i < 4; i++)
#pragma unroll
                for (int j = 0; j < 4; j++) mma16816h(acc[i][j], af[i], bh[j]);
        }
        if (ch + 2 < nch) { issue(ch + 2, (uint32_t)((ch + 2) % 3) * GSTG); CPCOMMIT(); }
    }

    const int lr = lane >> 2;
    const int lc = (lane & 3) * 2;

    if (MODE == 0) {
#pragma unroll
        for (int i = 0; i < 4; i++) {
            int rowA = bm + wm * 64 + i * 16 + lr;
#pragma unroll
            for (int j = 0; j < 4; j++) {
                int col = bn + wn * 32 + j * 8 + lc;
                *(float2*)&Cout[(size_t)rowA * N + col] = make_float2(acc[i][j][0], acc[i][j][1]);
                *(float2*)&Cout[(size_t)(rowA + 8) * N + col] = make_float2(acc[i][j][2], acc[i][j][3]);
            }
        }
    } else {
        int col0 = bn + wn * 32;
        int sdx = col0 >> 10;               // 0=q 1=k 2=v
        int rr = col0 & (Cdim - 1);
        int h = rr >> 6;
        int d0 = (rr & (Ddim - 1)) + lc;
        __half* dst = (sdx == 0) ? g_q2 : (sdx == 1) ? g_k2 : g_v2;
        // q pre-scaled by (1/sqrt(D)) * log2(e) so attention can use exp2
        float sc = (sdx == 0) ? 0.125f * 1.4426950408889634f : 1.0f;
#pragma unroll
        for (int i = 0; i < 4; i++) {
            int rowA = bm + wm * 64 + i * 16 + lr;
#pragma unroll
            for (int hh = 0; hh < 2; hh++) {
                int row = rowA + hh * 8;
                int b = row >> 11;
                int t = row & (Tdim - 1);
                size_t off = ((size_t)(b * Hdim + h) * Tdim + t) * Ddim + d0;
#pragma unroll
                for (int j = 0; j < 4; j++) {
                    *(uint32_t*)&dst[off + j * 8] =
                        pack2h(acc[i][j][hh * 2] * sc, acc[i][j][hh * 2 + 1] * sc);
                }
            }
        }
    }
}

// ---------------------------------------------------------------------------
// Tensor-core causal flash attention, 1-term fp16, persistent CTAs,
// cp.async 3-stage K/V pipeline (1 sync per tile), exp2 softmax.
// ---------------------------------------------------------------------------
#define NITEMS (Hdim * Bdim * (Tdim / 128))   // 512

__global__ void __launch_bounds__(256, 2) attn_mma() {
    extern __shared__ __align__(16) char sbuf[];
    const uint32_t sb = smem_u32(sbuf);
    const int tid = threadIdx.x;
    const int lane = tid & 31;
    const int w = tid >> 5;

    for (int it = blockIdx.x; it < NITEMS; it += gridDim.x) {
        const int bh = it & 31;
        const int q0 = (15 - (it >> 5)) * 128;
        const size_t headoff = (size_t)bh * Tdim * Ddim;
        const int ktmax = (q0 + 127) >> 6;

        // cp.async issue of one K/V tile (64 rows x 64 cols fp16 each) into slot
        auto issue_kv = [&](int kt, uint32_t slot) {
            const size_t gbase = headoff + (size_t)(kt * 64) * Ddim;
            const uint32_t st = sb + slot * ASTG;
#pragma unroll
            for (int p = 0; p < 2; p++) {
                int u = tid + 256 * p;          // 0..511
                int row = u >> 3;               // 0..63
                int seg = u & 7;                // 8 segs x 16B
                uint32_t so = st + (uint32_t)(row * 144 + seg * 16);
                size_t go = gbase + (size_t)row * Ddim + seg * 8;
                CPASYNC(so, &g_k2[go]);
                CPASYNC(so + ATILE, &g_v2[go]);
            }
        };

        // protect all slots (incl. Q region) from previous item's readers
        __syncthreads();

        issue_kv(0, 0); CPCOMMIT();
        if (ktmax >= 1) { issue_kv(1, 1); CPCOMMIT(); }

        // stage Q (128x64) into stage-2 region
        {
            const uint32_t qbase = sb + 2 * ASTG;
            const uint4* qg = (const uint4*)(g_q2 + headoff + (size_t)q0 * Ddim);
#pragma unroll
            for (int p = 0; p < 4; p++) {
                int u = p * 256 + tid;
                int row = u >> 3;
                int c8 = (u & 7) * 8;
                *(uint4*)(sbuf + 2 * ASTG + (uint32_t)(row * SROWA + c8) * 2) = qg[u];
            }
            (void)qbase;
        }
        __syncthreads();

        uint32_t qf[4][4];
#pragma unroll
        for (int kk = 0; kk < 4; kk++) {
            uint32_t off = (uint32_t)((16 * w + (lane & 15)) * SROWA + 16 * kk + 8 * (lane >> 4)) * 2;
            ldsm_x4(qf[kk][0], qf[kk][1], qf[kk][2], qf[kk][3], sb + 2 * ASTG + off);
        }

        float oacc[8][4];
#pragma unroll
        for (int j = 0; j < 8; j++)
#pragma unroll
            for (int r = 0; r < 4; r++) oacc[j][r] = 0.f;
        float m1 = -1e30f, m2 = -1e30f, l1 = 0.f, l2 = 0.f;

        const int r1 = q0 + 16 * w + (lane >> 2);
        const int r2 = r1 + 8;

        for (int kt = 0; kt <= ktmax; kt++) {
            const int kbase = kt * 64;
            if (kt + 1 <= ktmax) { CPWAIT1(); } else { CPWAIT0(); }
            __syncthreads();   // tile kt published; also fences q-frag loads (iter 0)
            if (kt + 2 <= ktmax) { issue_kv(kt + 2, (uint32_t)((kt + 2) % 3)); CPCOMMIT(); }

            const uint32_t cur = (uint32_t)(kt % 3) * ASTG;
            const uint32_t oKh = cur;
            const uint32_t oVh = cur + ATILE;

            // ---- S = Q.K^T (S in log2 domain: q pre-scaled by log2e/sqrt(D)) ----
            float sacc[8][4];
#pragma unroll
            for (int j = 0; j < 8; j++)
#pragma unroll
                for (int r = 0; r < 4; r++) sacc[j][r] = 0.f;

#pragma unroll
            for (int kk = 0; kk < 4; kk++) {
                uint32_t bk[8][2];
#pragma unroll
                for (int np = 0; np < 4; np++) {
                    uint32_t off = (uint32_t)((np * 16 + (lane >> 4) * 8 + (lane & 7)) * SROWA +
                                              ((lane >> 3) & 1) * 8 + 16 * kk) * 2;
                    uint32_t t0, t1, t2, t3;
                    ldsm_x4(t0, t1, t2, t3, sb + oKh + off);
                    bk[2 * np][0] = t0; bk[2 * np][1] = t1;
                    bk[2 * np + 1][0] = t2; bk[2 * np + 1][1] = t3;
                }
#pragma unroll
                for (int j = 0; j < 8; j++) mma16816h(sacc[j], qf[kk], bk[j]);
            }

            if (kbase + 63 > q0 + 16 * w) {
                const int c0 = kbase + 2 * (lane & 3);
#pragma unroll
                for (int j = 0; j < 8; j++) {
                    int cj = c0 + 8 * j;
                    if (cj > r1)     sacc[j][0] = -1e30f;
                    if (cj + 1 > r1) sacc[j][1] = -1e30f;
                    if (cj > r2)     sacc[j][2] = -1e30f;
                    if (cj + 1 > r2) sacc[j][3] = -1e30f;
                }
            }

            float t1m = -1e30f, t2m = -1e30f;
#pragma unroll
            for (int j = 0; j < 8; j++) {
                t1m = fmaxf(t1m, fmaxf(sacc[j][0], sacc[j][1]));
                t2m = fmaxf(t2m, fmaxf(sacc[j][2], sacc[j][3]));
            }
            t1m = fmaxf(t1m, __shfl_xor_sync(0xffffffffu, t1m, 1));
            t1m = fmaxf(t1m, __shfl_xor_sync(0xffffffffu, t1m, 2));
            t2m = fmaxf(t2m, __shfl_xor_sync(0xffffffffu, t2m, 1));
            t2m = fmaxf(t2m, __shfl_xor_sync(0xffffffffu, t2m, 2));

            float nm1 = fmaxf(m1, t1m), nm2 = fmaxf(m2, t2m);
            float corr1 = exp2f(m1 - nm1), corr2 = exp2f(m2 - nm2);
            m1 = nm1; m2 = nm2;

            float s1 = 0.f, s2 = 0.f;
#pragma unroll
            for (int j = 0; j < 8; j++) {
                sacc[j][0] = exp2f(sacc[j][0] - m1);
                sacc[j][1] = exp2f(sacc[j][1] - m1);
                sacc[j][2] = exp2f(sacc[j][2] - m2);
                sacc[j][3] = exp2f(sacc[j][3] - m2);
                s1 += sacc[j][0] + sacc[j][1];
                s2 += sacc[j][2] + sacc[j][3];
            }
            s1 += __shfl_xor_sync(0xffffffffu, s1, 1);
            s1 += __shfl_xor_sync(0xffffffffu, s1, 2);
            s2 += __shfl_xor_sync(0xffffffffu, s2, 1);
            s2 += __shfl_xor_sync(0xffffffffu, s2, 2);
            l1 = l1 * corr1 + s1;
            l2 = l2 * corr2 + s2;

            // pack P into fp16 A-fragments
            uint32_t ph[4][4];
#pragma unroll
            for (int kk = 0; kk < 4; kk++) {
                int j0 = 2 * kk, j1 = 2 * kk + 1;
                ph[kk][0] = pack2h(sacc[j0][0], sacc[j0][1]);
                ph[kk][1] = pack2h(sacc[j0][2], sacc[j0][3]);
                ph[kk][2] = pack2h(sacc[j1][0], sacc[j1][1]);
                ph[kk][3] = pack2h(sacc[j1][2], sacc[j1][3]);
            }

#pragma unroll
            for (int j = 0; j < 8; j++) {
                oacc[j][0] *= corr1; oacc[j][1] *= corr1;
                oacc[j][2] *= corr2; oacc[j][3] *= corr2;
            }

            // ---- O += P.V ----
#pragma unroll
            for (int kk = 0; kk < 4; kk++) {
                uint32_t vb[8][2];
#pragma unroll
                for (int np = 0; np < 4; np++) {
                    uint32_t off = (uint32_t)((16 * kk + (lane & 15)) * SROWA +
                                              16 * np + 8 * (lane >> 4)) * 2;
                    uint32_t t0, t1, t2, t3;
                    ldsm_x4_t(t0, t1, t2, t3, sb + oVh + off);
                    vb[2 * np][0] = t0; vb[2 * np][1] = t1;
                    vb[2 * np + 1][0] = t2; vb[2 * np + 1][1] = t3;
                }
#pragma unroll
                for (int j = 0; j < 8; j++) mma16816h(oacc[j], ph[kk], vb[j]);
            }
        }

        // ---- epilogue: y[B,T,H,D] single fp16 ----
        float inv1 = 1.0f / l1, inv2 = 1.0f / l2;
        int b = bh >> 4, h = bh & 15;
        size_t off1 = ((size_t)(b * Tdim + r1) * Hdim + h) * Ddim;
        size_t off2 = ((size_t)(b * Tdim + r2) * Hdim + h) * Ddim;
        int d0 = 2 * (lane & 3);
#pragma unroll
        for (int j = 0; j < 8; j++) {
            *(uint32_t*)&g_y2[off1 + 8 * j + d0] = pack2h(oacc[j][0] * inv1, oacc[j][1] * inv1);
            *(uint32_t*)&g_y2[off2 + 8 * j + d0] = pack2h(oacc[j][2] * inv2, oacc[j][3] * inv2);
        }
    }
}

// ---------------------------------------------------------------------------
extern "C" void kernel_launch(void* const* d_in, const int* in_sizes, int n_in,
                              void* d_out, int out_size) {
    const float* x = (const float*)d_in[0];        // [B,T,C]
    const float* w_attn = (const float*)d_in[1];   // [3C,C]
    const float* w_proj = (const float*)d_in[2];   // [C,C]
    float* out = (float*)d_out;                    // [B,T,C]

    __half *x2, *wa, *wp, *y2;
    cudaGetSymbolAddress((void**)&x2, g_x2);
    cudaGetSymbolAddress((void**)&wa, g_wa);
    cudaGetSymbolAddress((void**)&wp, g_wp);
    cudaGetSymbolAddress((void**)&y2, g_y2);

    cudaFuncSetAttribute(gemm_h1<0>, cudaFuncAttributeMaxDynamicSharedMemorySize, GSM3);
    cudaFuncSetAttribute(gemm_h1<1>, cudaFuncAttributeMaxDynamicSharedMemorySize, GSM3);
    cudaFuncSetAttribute(attn_mma, cudaFuncAttributeMaxDynamicSharedMemorySize, ASMEM);

    // Fused pre-pass: round all inputs to fp16 (one launch)
    const int ntot = NX4 + NWA4 + NWP4;            // 2097152
    round_all_kernel<<<(ntot + 255) / 256, 256>>>(x, w_attn, w_proj, x2, wa, wp);

    // GEMM1: qkv = x @ w_attn^T (fp16 1-term), scatter epilogue
    dim3 g1(3 * Cdim / 128, Mrows / 128);   // (24, 32)
    gemm_h1<1><<<g1, 256, GSM3>>>(x2, wa, nullptr, Cdim, 3 * Cdim);

    // Attention (persistent, cp.async pipeline, 2 CTAs/SM)
    attn_mma<<<296, 256, ASMEM>>>();

    // GEMM2: out = y @ w_proj^T (fp16 1-term)
    dim3 g2(Cdim / 128, Mrows / 128);       // (8, 32)
    gemm_h1<0><<<g2, 256, GSM3>>>(y2, wp, out, Cdim, Cdim);
}